// round 12
// baseline (speedup 1.0000x reference)
#include <cuda_runtime.h>
#include <cuda_bf16.h>
#include <math.h>
#include <stdint.h>

#define B_ 4
#define T_ 1024
#define C_ 1024
#define H_ 16
#define D_ 64

// ---------------- scratch (device globals; no allocations allowed) ----------
__device__ float g_spike[B_ * T_];

// transformed Q',K',V as bf16 hi/lo  [BH][T][64]
__device__ __nv_bfloat16 g_Qhi[(size_t)B_ * H_ * T_ * D_];
__device__ __nv_bfloat16 g_Qlo[(size_t)B_ * H_ * T_ * D_];
__device__ __nv_bfloat16 g_Khi[(size_t)B_ * H_ * T_ * D_];
__device__ __nv_bfloat16 g_Klo[(size_t)B_ * H_ * T_ * D_];
__device__ __nv_bfloat16 g_Vhi[(size_t)B_ * H_ * T_ * D_];
__device__ __nv_bfloat16 g_Vlo[(size_t)B_ * H_ * T_ * D_];

// bf16 hi/lo split operands for tensor-core GEMMs
__device__ __nv_bfloat16 g_xhi[(size_t)B_ * T_ * C_];
__device__ __nv_bfloat16 g_xlo[(size_t)B_ * T_ * C_];
__device__ __nv_bfloat16 g_Wqt_hi[(size_t)3 * C_ * C_];    // W_qkv^T [N,K]
__device__ __nv_bfloat16 g_Wqt_lo[(size_t)3 * C_ * C_];
__device__ __nv_bfloat16 g_Yhi[(size_t)B_ * T_ * C_];      // attn out, bf16 hi/lo
__device__ __nv_bfloat16 g_Ylo[(size_t)B_ * T_ * C_];
__device__ __nv_bfloat16 g_Wot_hi[(size_t)C_ * C_];        // W_out^T [N,K]
__device__ __nv_bfloat16 g_Wot_lo[(size_t)C_ * C_];

// ======================= generic-PTX helpers (no 'a' features) ==============
__device__ __forceinline__ uint32_t smem_u32(const void* p) {
    uint32_t a;
    asm("{ .reg .u64 t; cvta.to.shared.u64 t, %1; cvt.u32.u64 %0, t; }"
        : "=r"(a) : "l"(p));
    return a;
}
#define CP16(saddr, gaddr) \
    asm volatile("cp.async.cg.shared.global [%0], [%1], 16;" \
                 :: "r"(saddr), "l"(gaddr))
#define CP_COMMIT() asm volatile("cp.async.commit_group;" ::: "memory")
#define CP_WAIT1()  asm volatile("cp.async.wait_group 1;" ::: "memory")
#define CP_WAIT0()  asm volatile("cp.async.wait_group 0;" ::: "memory")

#define LDSM_X4(r0, r1, r2, r3, addr) \
    asm volatile("ldmatrix.sync.aligned.m8n8.x4.shared.b16 {%0,%1,%2,%3}, [%4];" \
                 : "=r"(r0), "=r"(r1), "=r"(r2), "=r"(r3) : "r"(addr))

#define LDSM_X4_T(r0, r1, r2, r3, addr) \
    asm volatile("ldmatrix.sync.aligned.m8n8.x4.trans.shared.b16 {%0,%1,%2,%3}, [%4];" \
                 : "=r"(r0), "=r"(r1), "=r"(r2), "=r"(r3) : "r"(addr))

#define MMA_BF16(d, a, b0, b1) \
    asm volatile("mma.sync.aligned.m16n8k16.row.col.f32.bf16.bf16.f32 " \
                 "{%0,%1,%2,%3}, {%4,%5,%6,%7}, {%8,%9}, {%0,%1,%2,%3};" \
                 : "+f"((d)[0]), "+f"((d)[1]), "+f"((d)[2]), "+f"((d)[3]) \
                 : "r"((a)[0]), "r"((a)[1]), "r"((a)[2]), "r"((a)[3]), \
                   "r"(b0), "r"(b1))

__device__ __forceinline__ uint32_t pack_bf16(float a, float b) {
    __nv_bfloat162 h = __floats2bfloat162_rn(a, b);
    return *(uint32_t*)&h;
}

// ---------------- fused x prep: spike gate + bf16 hi/lo split ---------------
// One warp per row: single pass over x computes the surrogate dot product AND
// emits xhi/xlo, deleting a separate 16MB x read + one launch.
__global__ void prep_x_kernel(const float* __restrict__ x,
                              const float* __restrict__ w_sur,
                              const float* __restrict__ b_sur,
                              const float* __restrict__ threshold,
                              __nv_bfloat16* __restrict__ hi,
                              __nv_bfloat16* __restrict__ lo) {
    const int row = blockIdx.x * (blockDim.x >> 5) + (threadIdx.x >> 5);
    const int lane = threadIdx.x & 31;
    const float* xr = x + (size_t)row * C_;
    float s = 0.f;
    #pragma unroll
    for (int i = 0; i < 8; i++) {
        const int e = lane * 4 + i * 128;
        float4 v = *(const float4*)(xr + e);
        float4 w = *(const float4*)(w_sur + e);
        s += v.x * w.x + v.y * w.y + v.z * w.z + v.w * w.w;

        __nv_bfloat16 h0 = __float2bfloat16(v.x);
        __nv_bfloat16 h1 = __float2bfloat16(v.y);
        __nv_bfloat16 h2 = __float2bfloat16(v.z);
        __nv_bfloat16 h3 = __float2bfloat16(v.w);
        __nv_bfloat162* hp = (__nv_bfloat162*)(hi + (size_t)row * C_ + e);
        __nv_bfloat162* lp = (__nv_bfloat162*)(lo + (size_t)row * C_ + e);
        hp[0] = __nv_bfloat162(h0, h1);
        hp[1] = __nv_bfloat162(h2, h3);
        lp[0] = __nv_bfloat162(__float2bfloat16(v.x - __bfloat162float(h0)),
                               __float2bfloat16(v.y - __bfloat162float(h1)));
        lp[1] = __nv_bfloat162(__float2bfloat16(v.z - __bfloat162float(h2)),
                               __float2bfloat16(v.w - __bfloat162float(h3)));
    }
    #pragma unroll
    for (int m = 16; m; m >>= 1) s += __shfl_xor_sync(0xffffffffu, s, m);
    if (lane == 0) {
        float z = s + b_sur[0];
        float imp = 1.f / (1.f + expf(-z));
        g_spike[row] = (imp > threshold[0]) ? 1.f : 0.f;
    }
}

// ---------------- W[K,N] -> W^T[N,K] bf16 hi/lo split -----------------------
__global__ void transpose_split_kernel(const float* __restrict__ W,
                                       __nv_bfloat16* __restrict__ Thi,
                                       __nv_bfloat16* __restrict__ Tlo,
                                       int K, int N) {
    __shared__ float tile[32][33];
    int k0 = blockIdx.y * 32, n0 = blockIdx.x * 32;
    int tx = threadIdx.x, ty = threadIdx.y;    // 32 x 8
    #pragma unroll
    for (int j = 0; j < 32; j += 8)
        tile[ty + j][tx] = W[(size_t)(k0 + ty + j) * N + n0 + tx];
    __syncthreads();
    #pragma unroll
    for (int j = 0; j < 32; j += 8) {
        float v = tile[tx][ty + j];
        __nv_bfloat16 h = __float2bfloat16(v);
        __nv_bfloat16 l = __float2bfloat16(v - __bfloat162float(h));
        Thi[(size_t)(n0 + ty + j) * K + k0 + tx] = h;
        Tlo[(size_t)(n0 + ty + j) * K + k0 + tx] = l;
    }
}

// ---------------- mma.sync bf16x3 GEMM, 4 warps x (64x64) warp tiles --------
// FUSE=false: plain epilogue (bias add, fp32 store to Cmat).
// FUSE=true : QKV epilogue — per-head Lorentz expmap transform + bf16 hi/lo
//             split, written directly to g_{Q,K,V}{hi,lo}.
#define G4_STAGE 32768
#define G4_SMEM (3 * G4_STAGE)
#define G4_TILE 8192

template<bool FUSE>
__global__ __launch_bounds__(128) void gemm4_kernel(
    const __nv_bfloat16* __restrict__ Ahi, const __nv_bfloat16* __restrict__ Alo,
    const __nv_bfloat16* __restrict__ Bhi, const __nv_bfloat16* __restrict__ Blo,
    const float* __restrict__ bias, float* __restrict__ Cmat,
    int M, int N, int K)
{
    extern __shared__ char sm[];
    const uint32_t sbase = smem_u32(sm);

    const int tid  = threadIdx.x;
    const int wid  = tid >> 5;
    const int lane = tid & 31;
    const int m0 = blockIdx.y * 128;
    const int n0 = blockIdx.x * 128;
    const int wm = wid & 1;          // 64-row slab
    const int wn = wid >> 1;         // 64-col slab

    uint32_t so[4];
    const __nv_bfloat16 *pA0[4], *pA1[4], *pB0[4], *pB1[4];
    #pragma unroll
    for (int it = 0; it < 4; it++) {
        const int sub = tid + it * 128;
        const int row = sub >> 2, col = sub & 3;
        so[it] = (uint32_t)row * 64 + (uint32_t)((col ^ ((row >> 1) & 3)) * 16);
        pA0[it] = Ahi + (size_t)(m0 + row) * K + col * 8;
        pA1[it] = Alo + (size_t)(m0 + row) * K + col * 8;
        pB0[it] = Bhi + (size_t)(n0 + row) * K + col * 8;
        pB1[it] = Blo + (size_t)(n0 + row) * K + col * 8;
    }

    float acc[4][8][4];
    #pragma unroll
    for (int i = 0; i < 4; i++)
        #pragma unroll
        for (int j = 0; j < 8; j++)
            #pragma unroll
            for (int c = 0; c < 4; c++) acc[i][j][c] = 0.f;

    const int nch = K >> 5;
    const int lrow = lane & 15;
    const int kc   = lane >> 4;

    #pragma unroll
    for (int s = 0; s < 2; s++) {
        const uint32_t sb = sbase + (uint32_t)s * G4_STAGE;
        const int kb = s << 5;
        #pragma unroll
        for (int it = 0; it < 4; it++) {
            CP16(sb + 0 * G4_TILE + so[it], pA0[it] + kb);
            CP16(sb + 1 * G4_TILE + so[it], pA1[it] + kb);
            CP16(sb + 2 * G4_TILE + so[it], pB0[it] + kb);
            CP16(sb + 3 * G4_TILE + so[it], pB1[it] + kb);
        }
        CP_COMMIT();
    }

    for (int ch = 0; ch < nch; ch++) {
        CP_WAIT1();
        __syncthreads();

        if (ch + 2 < nch) {
            const uint32_t sb = sbase + (uint32_t)((ch + 2) % 3) * G4_STAGE;
            const int kb = (ch + 2) << 5;
            #pragma unroll
            for (int it = 0; it < 4; it++) {
                CP16(sb + 0 * G4_TILE + so[it], pA0[it] + kb);
                CP16(sb + 1 * G4_TILE + so[it], pA1[it] + kb);
                CP16(sb + 2 * G4_TILE + so[it], pB0[it] + kb);
                CP16(sb + 3 * G4_TILE + so[it], pB1[it] + kb);
            }
        }
        CP_COMMIT();

        const uint32_t st = sbase + (uint32_t)(ch % 3) * G4_STAGE;

        #pragma unroll
        for (int kk = 0; kk < 2; kk++) {
            const int chunk = kk * 2 + kc;
            uint32_t ahi[4][4], alo[4][4];
            #pragma unroll
            for (int mi = 0; mi < 4; mi++) {
                const int r = wm * 64 + mi * 16 + lrow;
                const uint32_t off = (uint32_t)r * 64 +
                    (uint32_t)((chunk ^ ((r >> 1) & 3)) * 16);
                LDSM_X4(ahi[mi][0], ahi[mi][1], ahi[mi][2], ahi[mi][3],
                        st + 0 * G4_TILE + off);
                LDSM_X4(alo[mi][0], alo[mi][1], alo[mi][2], alo[mi][3],
                        st + 1 * G4_TILE + off);
            }
            #pragma unroll
            for (int g = 0; g < 4; g++) {
                const int r = wn * 64 + g * 16 + lrow;
                const uint32_t off = (uint32_t)r * 64 +
                    (uint32_t)((chunk ^ ((r >> 1) & 3)) * 16);
                uint32_t bh[4], bl[4];
                LDSM_X4(bh[0], bh[1], bh[2], bh[3], st + 2 * G4_TILE + off);
                LDSM_X4(bl[0], bl[1], bl[2], bl[3], st + 3 * G4_TILE + off);
                #pragma unroll
                for (int mi = 0; mi < 4; mi++) {
                    MMA_BF16(acc[mi][g * 2 + 0], ahi[mi], bh[0], bh[2]);
                    MMA_BF16(acc[mi][g * 2 + 0], ahi[mi], bl[0], bl[2]);
                    MMA_BF16(acc[mi][g * 2 + 0], alo[mi], bh[0], bh[2]);
                    MMA_BF16(acc[mi][g * 2 + 1], ahi[mi], bh[1], bh[3]);
                    MMA_BF16(acc[mi][g * 2 + 1], ahi[mi], bl[1], bl[3]);
                    MMA_BF16(acc[mi][g * 2 + 1], alo[mi], bh[1], bh[3]);
                }
            }
        }
    }

    const int orow = lane >> 2;          // row-in-16 (0..7)
    const int ocol = (lane & 3) * 2;     // col pair base within 8

    if constexpr (!FUSE) {
        #pragma unroll
        for (int mi = 0; mi < 4; mi++) {
            const int r0 = m0 + wm * 64 + mi * 16 + orow;
            #pragma unroll
            for (int ni = 0; ni < 8; ni++) {
                const int c = n0 + wn * 64 + ni * 8 + ocol;
                const float b0 = bias[c], b1 = bias[c + 1];
                float2 v0 = make_float2(acc[mi][ni][0] + b0, acc[mi][ni][1] + b1);
                float2 v1 = make_float2(acc[mi][ni][2] + b0, acc[mi][ni][3] + b1);
                *(float2*)(Cmat + (size_t)r0 * N + c)       = v0;
                *(float2*)(Cmat + (size_t)(r0 + 8) * N + c) = v1;
            }
        }
    } else {
        const int colbase = n0 + wn * 64;          // 64-aligned -> one head
        const int type = colbase >> 10;            // 0=Q, 1=K, 2=V
        const int head = (colbase & 1023) >> 6;
        __nv_bfloat16* ghi = (type == 0) ? g_Qhi : (type == 1) ? g_Khi : g_Vhi;
        __nv_bfloat16* glo = (type == 0) ? g_Qlo : (type == 1) ? g_Klo : g_Vlo;
        const float sgn = (type == 1) ? -1.f : 1.f;

        float bs[8][2];
        #pragma unroll
        for (int ni = 0; ni < 8; ni++) {
            bs[ni][0] = bias[colbase + ni * 8 + ocol];
            bs[ni][1] = bias[colbase + ni * 8 + ocol + 1];
        }

        #pragma unroll
        for (int mi = 0; mi < 4; mi++) {
            #pragma unroll
            for (int hh = 0; hh < 2; hh++) {
                const int r = m0 + wm * 64 + mi * 16 + orow + hh * 8;
                const int batch = r >> 10, t = r & 1023;
                const size_t ob = ((size_t)(batch * H_ + head) * T_ + t) * D_;

                float v[8][2];
                float ss = 0.f;
                #pragma unroll
                for (int ni = 0; ni < 8; ni++) {
                    v[ni][0] = acc[mi][ni][hh * 2 + 0] + bs[ni][0];
                    v[ni][1] = acc[mi][ni][hh * 2 + 1] + bs[ni][1];
                    ss += v[ni][0] * v[ni][0] + v[ni][1] * v[ni][1];
                }

                if (type != 2) {
                    ss += __shfl_xor_sync(0xffffffffu, ss, 1);
                    ss += __shfl_xor_sync(0xffffffffu, ss, 2);
                    float u0 = __shfl_sync(0xffffffffu, v[0][0], lane & ~3u, 32);
                    float mink = ss - 2.f * u0 * u0;
                    float nn = sqrtf(fmaxf(mink, 1e-8f));
                    float e = __expf(nn), ei = 1.f / e;
                    float tme = 0.5f * (e + ei);
                    float coef = sgn * (e - ei) / (2.f * nn);
                    #pragma unroll
                    for (int ni = 0; ni < 8; ni++) {
                        v[ni][0] *= coef;
                        v[ni][1] *= coef;
                    }
                    if ((lane & 3) == 0) v[0][0] = tme;   // d==0 -> time comp
                }

                #pragma unroll
                for (int ni = 0; ni < 8; ni++) {
                    const int d = ni * 8 + ocol;
                    uint32_t hp = pack_bf16(v[ni][0], v[ni][1]);
                    __nv_bfloat162 hv = *(__nv_bfloat162*)&hp;
                    uint32_t lp = pack_bf16(v[ni][0] - __low2float(hv),
                                            v[ni][1] - __high2float(hv));
                    *(uint32_t*)(ghi + ob + d) = hp;
                    *(uint32_t*)(glo + ob + d) = lp;
                }
            }
        }
    }
}

// ---------------- tensor-core flash attention (bf16x3) ----------------------
// CTA: 64 q-rows, 4 warps, 128 threads; j tiles of 64. smem 64KB:
// buf0 @0, buf1 @32K; Q staged at [32K,48K) (aliases buf1), consumed into
// register A-fragments in the prologue before any buf1 prefetch.
#define AT_SMEM 65536
#define SWO(row, ch) ((uint32_t)(row) * 128u + (uint32_t)(((ch) ^ (((row) >> 1) & 3)) * 16))

__global__ __launch_bounds__(128) void attn_kernel() {
    extern __shared__ char sm[];
    const uint32_t sb = smem_u32(sm);
    const int tid = threadIdx.x;
    const int wid = tid >> 5;
    const int lane = tid & 31;
    const int ti = (gridDim.x - 1) - blockIdx.x;   // heavy CTAs first
    const int h  = blockIdx.y;
    const int b  = blockIdx.z;
    const int bh = b * H_ + h;
    const int i0 = ti * 64;
    const size_t gb = (size_t)bh * T_ * D_;

    const int lrow  = lane & 15;
    const int khalf = lane >> 4;

    // ---- prologue: Q -> [32K,48K), K/V tile 0 -> buf0; one group ----
    #pragma unroll
    for (int i = 0; i < 8; i++) {
        const int arr = i >> 2;
        const int sub = tid + (i & 3) * 128;
        const int row = sub >> 3, ch = sub & 7;
        const __nv_bfloat16* g = arr ? g_Qlo : g_Qhi;
        CP16(sb + 32768u + (uint32_t)arr * 8192u + SWO(row, ch),
             g + gb + (size_t)(i0 + row) * D_ + ch * 8);
    }
    #pragma unroll
    for (int i = 0; i < 16; i++) {
        const int arr = i >> 2;
        const int sub = tid + (i & 3) * 128;
        const int row = sub >> 3, ch = sub & 7;
        const __nv_bfloat16* g = (arr == 0) ? g_Khi : (arr == 1) ? g_Klo
                               : (arr == 2) ? g_Vhi : g_Vlo;
        CP16(sb + (uint32_t)arr * 8192u + SWO(row, ch),
             g + gb + (size_t)row * D_ + ch * 8);
    }
    CP_COMMIT();

    float O[8][4];
    #pragma unroll
    for (int i = 0; i < 8; i++)
        #pragma unroll
        for (int c = 0; c < 4; c++) O[i][c] = 0.f;
    float m0 = -1e30f, m1 = -1e30f, l0 = 0.f, l1 = 0.f;

    const int rq = lane >> 2;
    const int cq = (lane & 3) * 2;
    const int grow0 = i0 + wid * 16 + rq;
    const int grow1 = grow0 + 8;

    // Q A-fragments loaded once (hoisted out of the loop)
    uint32_t ahi[4][4], alo[4][4];
    CP_WAIT0();
    __syncthreads();
    #pragma unroll
    for (int kc = 0; kc < 4; kc++) {
        const int r = wid * 16 + lrow;
        const uint32_t off = SWO(r, kc * 2 + khalf);
        LDSM_X4(ahi[kc][0], ahi[kc][1], ahi[kc][2], ahi[kc][3],
                sb + 32768u + off);
        LDSM_X4(alo[kc][0], alo[kc][1], alo[kc][2], alo[kc][3],
                sb + 40960u + off);
    }
    __syncthreads();   // all Q reads done before any buf1 prefetch

    for (int tj = 0; tj <= ti; tj++) {
        if (tj < ti) {         // prefetch tile tj+1 into the other buffer
            const uint32_t dst = sb + (uint32_t)((tj + 1) & 1) * 32768u;
            const size_t src = gb + (size_t)(tj + 1) * 64 * D_;
            #pragma unroll
            for (int i = 0; i < 16; i++) {
                const int arr = i >> 2;
                const int sub = tid + (i & 3) * 128;
                const int row = sub >> 3, ch = sub & 7;
                const __nv_bfloat16* g = (arr == 0) ? g_Khi : (arr == 1) ? g_Klo
                                       : (arr == 2) ? g_Vhi : g_Vlo;
                CP16(dst + (uint32_t)arr * 8192u + SWO(row, ch),
                     g + src + (size_t)row * D_ + ch * 8);
            }
            CP_COMMIT();
        }

        const uint32_t kbuf = sb + (uint32_t)(tj & 1) * 32768u;

        // ---- S = Q' K'^T (bf16x3) ----
        float acc[8][4];
        #pragma unroll
        for (int i = 0; i < 8; i++)
            #pragma unroll
            for (int c = 0; c < 4; c++) acc[i][c] = 0.f;

        #pragma unroll
        for (int kc = 0; kc < 4; kc++) {
            uint32_t bh4[4][4], bl4[4][4];
            #pragma unroll
            for (int g = 0; g < 4; g++) {
                const int r = g * 16 + lrow;
                const uint32_t off = SWO(r, kc * 2 + khalf);
                LDSM_X4(bh4[g][0], bh4[g][1], bh4[g][2], bh4[g][3], kbuf + off);
                LDSM_X4(bl4[g][0], bl4[g][1], bl4[g][2], bl4[g][3],
                        kbuf + 8192u + off);
            }
            #pragma unroll
            for (int ni = 0; ni < 8; ni++) {
                const int g = ni >> 1, o = ni & 1;
                MMA_BF16(acc[ni], ahi[kc], bh4[g][o], bh4[g][2 + o]);
                MMA_BF16(acc[ni], ahi[kc], bl4[g][o], bl4[g][2 + o]);
                MMA_BF16(acc[ni], alo[kc], bh4[g][o], bh4[g][2 + o]);
            }
        }

        // ---- Lorentz transform + causal mask ----
        const int j0 = tj * 64;
        #pragma unroll
        for (int ni = 0; ni < 8; ni++) {
            #pragma unroll
            for (int c = 0; c < 4; c++) {
                const int col = j0 + ni * 8 + cq + (c & 1);
                const int grow = (c < 2) ? grow0 : grow1;
                float x = fmaxf(acc[ni][c], 1.0f + 1e-7f);
                float dd = __logf(x + sqrtf(fmaxf(x * x - 1.f, 0.f)));
                float s = -dd * dd * 0.125f;
                acc[ni][c] = (col > grow) ? -1e30f : s;
            }
        }

        // ---- online softmax ----
        {
            float mx = -1e30f;
            #pragma unroll
            for (int ni = 0; ni < 8; ni++)
                mx = fmaxf(mx, fmaxf(acc[ni][0], acc[ni][1]));
            mx = fmaxf(mx, __shfl_xor_sync(0xffffffffu, mx, 1));
            mx = fmaxf(mx, __shfl_xor_sync(0xffffffffu, mx, 2));
            float mnew = fmaxf(m0, mx);
            float es = __expf(m0 - mnew);
            l0 *= es;
            #pragma unroll
            for (int ni = 0; ni < 8; ni++) { O[ni][0] *= es; O[ni][1] *= es; }
            float rs = 0.f;
            #pragma unroll
            for (int ni = 0; ni < 8; ni++) {
                float p0 = __expf(acc[ni][0] - mnew);
                float p1 = __expf(acc[ni][1] - mnew);
                acc[ni][0] = p0; acc[ni][1] = p1; rs += p0 + p1;
            }
            rs += __shfl_xor_sync(0xffffffffu, rs, 1);
            rs += __shfl_xor_sync(0xffffffffu, rs, 2);
            l0 += rs; m0 = mnew;
        }
        {
            float mx = -1e30f;
            #pragma unroll
            for (int ni = 0; ni < 8; ni++)
                mx = fmaxf(mx, fmaxf(acc[ni][2], acc[ni][3]));
            mx = fmaxf(mx, __shfl_xor_sync(0xffffffffu, mx, 1));
            mx = fmaxf(mx, __shfl_xor_sync(0xffffffffu, mx, 2));
            float mnew = fmaxf(m1, mx);
            float es = __expf(m1 - mnew);
            l1 *= es;
            #pragma unroll
            for (int ni = 0; ni < 8; ni++) { O[ni][2] *= es; O[ni][3] *= es; }
            float rs = 0.f;
            #pragma unroll
            for (int ni = 0; ni < 8; ni++) {
                float p0 = __expf(acc[ni][2] - mnew);
                float p1 = __expf(acc[ni][3] - mnew);
                acc[ni][2] = p0; acc[ni][3] = p1; rs += p0 + p1;
            }
            rs += __shfl_xor_sync(0xffffffffu, rs, 1);
            rs += __shfl_xor_sync(0xffffffffu, rs, 2);
            l1 += rs; m1 = mnew;
        }

        // ---- PV: O += P V (bf16x3, P packed in registers) ----
        const uint32_t vbuf = kbuf + 16384u;
        #pragma unroll
        for (int kc = 0; kc < 4; kc++) {
            uint32_t ph[4], pl[4];
            #pragma unroll
            for (int q = 0; q < 4; q++) {
                const int ni = 2 * kc + (q >> 1);
                const int c0 = (q & 1) * 2;
                float a = acc[ni][c0], bb = acc[ni][c0 + 1];
                uint32_t hp = pack_bf16(a, bb);
                __nv_bfloat162 hv = *(__nv_bfloat162*)&hp;
                const int idx = (q & 1) + (q >> 1) * 2;
                ph[idx] = hp;
                pl[idx] = pack_bf16(a - __low2float(hv), bb - __high2float(hv));
            }
            #pragma unroll
            for (int g = 0; g < 4; g++) {
                const int r = kc * 16 + ((lane >> 3) & 1) * 8 + (lane & 7);
                const uint32_t off = SWO(r, g * 2 + khalf);
                uint32_t vh[4], vl[4];
                LDSM_X4_T(vh[0], vh[1], vh[2], vh[3], vbuf + off);
                LDSM_X4_T(vl[0], vl[1], vl[2], vl[3], vbuf + 8192u + off);
                MMA_BF16(O[g * 2],     ph, vh[0], vh[1]);
                MMA_BF16(O[g * 2],     ph, vl[0], vl[1]);
                MMA_BF16(O[g * 2],     pl, vh[0], vh[1]);
                MMA_BF16(O[g * 2 + 1], ph, vh[2], vh[3]);
                MMA_BF16(O[g * 2 + 1], ph, vl[2], vl[3]);
                MMA_BF16(O[g * 2 + 1], pl, vh[2], vh[3]);
            }
        }

        if (tj < ti) {         // tile tj+1 landed; barrier also fences reuse
            CP_WAIT0();
            __syncthreads();
        }
    }

    // ---- epilogue: write Yhi/Ylo bf16 directly ----
    const float inv0 = g_spike[b * T_ + grow0] / l0;
    const float inv1 = g_spike[b * T_ + grow1] / l1;
    const size_t y0 = ((size_t)(b * T_ + grow0)) * C_ + h * D_;
    const size_t y1 = ((size_t)(b * T_ + grow1)) * C_ + h * D_;
    #pragma unroll
    for (int ni = 0; ni < 8; ni++) {
        const int d = ni * 8 + cq;
        float a0 = O[ni][0] * inv0, a1 = O[ni][1] * inv0;
        float b0 = O[ni][2] * inv1, b1 = O[ni][3] * inv1;
        uint32_t h0 = pack_bf16(a0, a1);
        __nv_bfloat162 hv0 = *(__nv_bfloat162*)&h0;
        uint32_t l0p = pack_bf16(a0 - __low2float(hv0), a1 - __high2float(hv0));
        uint32_t h1 = pack_bf16(b0, b1);
        __nv_bfloat162 hv1 = *(__nv_bfloat162*)&h1;
        uint32_t l1p = pack_bf16(b0 - __low2float(hv1), b1 - __high2float(hv1));
        *(uint32_t*)(g_Yhi + y0 + d) = h0;
        *(uint32_t*)(g_Ylo + y0 + d) = l0p;
        *(uint32_t*)(g_Yhi + y1 + d) = h1;
        *(uint32_t*)(g_Ylo + y1 + d) = l1p;
    }
}

// ---------------- launch -----------------------------------------------------
extern "C" void kernel_launch(void* const* d_in, const int* in_sizes, int n_in,
                              void* d_out, int out_size) {
    const float* x      = (const float*)d_in[0];
    const float* W_qkv  = (const float*)d_in[1];
    const float* b_qkv  = (const float*)d_in[2];
    const float* W_out  = (const float*)d_in[3];
    const float* b_out  = (const float*)d_in[4];
    const float* w_sur  = (const float*)d_in[5];
    const float* b_sur  = (const float*)d_in[6];
    const float* thresh = (const float*)d_in[7];
    float* out = (float*)d_out;

    __nv_bfloat16 *p_xhi, *p_xlo, *p_Wqt_hi, *p_Wqt_lo;
    __nv_bfloat16 *p_Yhi, *p_Ylo, *p_Wot_hi, *p_Wot_lo;
    cudaGetSymbolAddress((void**)&p_xhi, g_xhi);
    cudaGetSymbolAddress((void**)&p_xlo, g_xlo);
    cudaGetSymbolAddress((void**)&p_Wqt_hi, g_Wqt_hi);
    cudaGetSymbolAddress((void**)&p_Wqt_lo, g_Wqt_lo);
    cudaGetSymbolAddress((void**)&p_Yhi, g_Yhi);
    cudaGetSymbolAddress((void**)&p_Ylo, g_Ylo);
    cudaGetSymbolAddress((void**)&p_Wot_hi, g_Wot_hi);
    cudaGetSymbolAddress((void**)&p_Wot_lo, g_Wot_lo);

    cudaFuncSetAttribute(attn_kernel,
                         cudaFuncAttributeMaxDynamicSharedMemorySize, AT_SMEM);
    cudaFuncSetAttribute(gemm4_kernel<true>,
                         cudaFuncAttributeMaxDynamicSharedMemorySize, G4_SMEM);
    cudaFuncSetAttribute(gemm4_kernel<false>,
                         cudaFuncAttributeMaxDynamicSharedMemorySize, G4_SMEM);

    const int M = B_ * T_;   // 4096

    // 1. fused x prep: spike gate + bf16 hi/lo split (single x read)
    prep_x_kernel<<<M / 8, 256>>>(x, w_sur, b_sur, thresh, p_xhi, p_xlo);

    // 2. weight prep for QKV GEMM
    transpose_split_kernel<<<dim3(3 * C_ / 32, C_ / 32), dim3(32, 8)>>>(
        W_qkv, p_Wqt_hi, p_Wqt_lo, C_, 3 * C_);

    // 3. QKV GEMM with fused Lorentz transform epilogue -> g_{Q,K,V}{hi,lo}
    gemm4_kernel<true><<<dim3(3 * C_ / 128, M / 128), 128, G4_SMEM>>>(
        p_xhi, p_xlo, p_Wqt_hi, p_Wqt_lo, b_qkv, nullptr, M, 3 * C_, C_);

    // 4. tensor-core flash attention
    attn_kernel<<<dim3(T_ / 64, H_, B_), 128, AT_SMEM>>>();

    // 5. out projection
    transpose_split_kernel<<<dim3(C_ / 32, C_ / 32), dim3(32, 8)>>>(
        W_out, p_Wot_hi, p_Wot_lo, C_, C_);
    gemm4_kernel<false><<<dim3(C_ / 128, M / 128), 128, G4_SMEM>>>(
        p_Yhi, p_Ylo, p_Wot_hi, p_Wot_lo, b_out, out, M, C_, C_);
}

// round 13
// speedup vs baseline: 1.0268x; 1.0268x over previous
#include <cuda_runtime.h>
#include <cuda_bf16.h>
#include <math.h>
#include <stdint.h>

#define B_ 4
#define T_ 1024
#define C_ 1024
#define H_ 16
#define D_ 64

// ---------------- scratch (device globals; no allocations allowed) ----------
__device__ float g_spike[B_ * T_];

// transformed Q',K',V as bf16 hi/lo  [BH][T][64]
__device__ __nv_bfloat16 g_Qhi[(size_t)B_ * H_ * T_ * D_];
__device__ __nv_bfloat16 g_Qlo[(size_t)B_ * H_ * T_ * D_];
__device__ __nv_bfloat16 g_Khi[(size_t)B_ * H_ * T_ * D_];
__device__ __nv_bfloat16 g_Klo[(size_t)B_ * H_ * T_ * D_];
__device__ __nv_bfloat16 g_Vhi[(size_t)B_ * H_ * T_ * D_];
__device__ __nv_bfloat16 g_Vlo[(size_t)B_ * H_ * T_ * D_];

// bf16 hi/lo split operands for tensor-core GEMMs
__device__ __nv_bfloat16 g_xhi[(size_t)B_ * T_ * C_];
__device__ __nv_bfloat16 g_xlo[(size_t)B_ * T_ * C_];
__device__ __nv_bfloat16 g_Wqt_hi[(size_t)3 * C_ * C_];    // W_qkv^T [N,K]
__device__ __nv_bfloat16 g_Wqt_lo[(size_t)3 * C_ * C_];
__device__ __nv_bfloat16 g_Yhi[(size_t)B_ * T_ * C_];      // attn out, bf16 hi/lo
__device__ __nv_bfloat16 g_Ylo[(size_t)B_ * T_ * C_];
__device__ __nv_bfloat16 g_Wot_hi[(size_t)C_ * C_];        // W_out^T [N,K]
__device__ __nv_bfloat16 g_Wot_lo[(size_t)C_ * C_];

// ======================= generic-PTX helpers (no 'a' features) ==============
__device__ __forceinline__ uint32_t smem_u32(const void* p) {
    uint32_t a;
    asm("{ .reg .u64 t; cvta.to.shared.u64 t, %1; cvt.u32.u64 %0, t; }"
        : "=r"(a) : "l"(p));
    return a;
}
#define CP16(saddr, gaddr) \
    asm volatile("cp.async.cg.shared.global [%0], [%1], 16;" \
                 :: "r"(saddr), "l"(gaddr))
#define CP_COMMIT() asm volatile("cp.async.commit_group;" ::: "memory")
#define CP_WAIT1()  asm volatile("cp.async.wait_group 1;" ::: "memory")
#define CP_WAIT0()  asm volatile("cp.async.wait_group 0;" ::: "memory")

#define LDSM_X4(r0, r1, r2, r3, addr) \
    asm volatile("ldmatrix.sync.aligned.m8n8.x4.shared.b16 {%0,%1,%2,%3}, [%4];" \
                 : "=r"(r0), "=r"(r1), "=r"(r2), "=r"(r3) : "r"(addr))

#define LDSM_X4_T(r0, r1, r2, r3, addr) \
    asm volatile("ldmatrix.sync.aligned.m8n8.x4.trans.shared.b16 {%0,%1,%2,%3}, [%4];" \
                 : "=r"(r0), "=r"(r1), "=r"(r2), "=r"(r3) : "r"(addr))

#define MMA_BF16(d, a, b0, b1) \
    asm volatile("mma.sync.aligned.m16n8k16.row.col.f32.bf16.bf16.f32 " \
                 "{%0,%1,%2,%3}, {%4,%5,%6,%7}, {%8,%9}, {%0,%1,%2,%3};" \
                 : "+f"((d)[0]), "+f"((d)[1]), "+f"((d)[2]), "+f"((d)[3]) \
                 : "r"((a)[0]), "r"((a)[1]), "r"((a)[2]), "r"((a)[3]), \
                   "r"(b0), "r"(b1))

__device__ __forceinline__ uint32_t pack_bf16(float a, float b) {
    __nv_bfloat162 h = __floats2bfloat162_rn(a, b);
    return *(uint32_t*)&h;
}

// ---------------- fused x prep: spike gate + bf16 hi/lo split ---------------
__global__ void prep_x_kernel(const float* __restrict__ x,
                              const float* __restrict__ w_sur,
                              const float* __restrict__ b_sur,
                              const float* __restrict__ threshold,
                              __nv_bfloat16* __restrict__ hi,
                              __nv_bfloat16* __restrict__ lo) {
    const int row = blockIdx.x * (blockDim.x >> 5) + (threadIdx.x >> 5);
    const int lane = threadIdx.x & 31;
    const float* xr = x + (size_t)row * C_;
    float s = 0.f;
    #pragma unroll
    for (int i = 0; i < 8; i++) {
        const int e = lane * 4 + i * 128;
        float4 v = *(const float4*)(xr + e);
        float4 w = *(const float4*)(w_sur + e);
        s += v.x * w.x + v.y * w.y + v.z * w.z + v.w * w.w;

        __nv_bfloat16 h0 = __float2bfloat16(v.x);
        __nv_bfloat16 h1 = __float2bfloat16(v.y);
        __nv_bfloat16 h2 = __float2bfloat16(v.z);
        __nv_bfloat16 h3 = __float2bfloat16(v.w);
        __nv_bfloat162* hp = (__nv_bfloat162*)(hi + (size_t)row * C_ + e);
        __nv_bfloat162* lp = (__nv_bfloat162*)(lo + (size_t)row * C_ + e);
        hp[0] = __nv_bfloat162(h0, h1);
        hp[1] = __nv_bfloat162(h2, h3);
        lp[0] = __nv_bfloat162(__float2bfloat16(v.x - __bfloat162float(h0)),
                               __float2bfloat16(v.y - __bfloat162float(h1)));
        lp[1] = __nv_bfloat162(__float2bfloat16(v.z - __bfloat162float(h2)),
                               __float2bfloat16(v.w - __bfloat162float(h3)));
    }
    #pragma unroll
    for (int m = 16; m; m >>= 1) s += __shfl_xor_sync(0xffffffffu, s, m);
    if (lane == 0) {
        float z = s + b_sur[0];
        float imp = 1.f / (1.f + expf(-z));
        g_spike[row] = (imp > threshold[0]) ? 1.f : 0.f;
    }
}

// ---------------- W[K,N] -> W^T[N,K] bf16 hi/lo split -----------------------
__global__ void transpose_split_kernel(const float* __restrict__ W,
                                       __nv_bfloat16* __restrict__ Thi,
                                       __nv_bfloat16* __restrict__ Tlo,
                                       int K, int N) {
    __shared__ float tile[32][33];
    int k0 = blockIdx.y * 32, n0 = blockIdx.x * 32;
    int tx = threadIdx.x, ty = threadIdx.y;    // 32 x 8
    #pragma unroll
    for (int j = 0; j < 32; j += 8)
        tile[ty + j][tx] = W[(size_t)(k0 + ty + j) * N + n0 + tx];
    __syncthreads();
    #pragma unroll
    for (int j = 0; j < 32; j += 8) {
        float v = tile[tx][ty + j];
        __nv_bfloat16 h = __float2bfloat16(v);
        __nv_bfloat16 l = __float2bfloat16(v - __bfloat162float(h));
        Thi[(size_t)(n0 + ty + j) * K + k0 + tx] = h;
        Tlo[(size_t)(n0 + ty + j) * K + k0 + tx] = l;
    }
}

// ---------------- mma.sync bf16x3 GEMM, 4 warps x (64x64) warp tiles --------
#define G4_STAGE 32768
#define G4_SMEM (3 * G4_STAGE)
#define G4_TILE 8192

template<bool FUSE>
__global__ __launch_bounds__(128) void gemm4_kernel(
    const __nv_bfloat16* __restrict__ Ahi, const __nv_bfloat16* __restrict__ Alo,
    const __nv_bfloat16* __restrict__ Bhi, const __nv_bfloat16* __restrict__ Blo,
    const float* __restrict__ bias, float* __restrict__ Cmat,
    int M, int N, int K)
{
    extern __shared__ char sm[];
    const uint32_t sbase = smem_u32(sm);

    const int tid  = threadIdx.x;
    const int wid  = tid >> 5;
    const int lane = tid & 31;
    const int m0 = blockIdx.y * 128;
    const int n0 = blockIdx.x * 128;
    const int wm = wid & 1;          // 64-row slab
    const int wn = wid >> 1;         // 64-col slab

    uint32_t so[4];
    const __nv_bfloat16 *pA0[4], *pA1[4], *pB0[4], *pB1[4];
    #pragma unroll
    for (int it = 0; it < 4; it++) {
        const int sub = tid + it * 128;
        const int row = sub >> 2, col = sub & 3;
        so[it] = (uint32_t)row * 64 + (uint32_t)((col ^ ((row >> 1) & 3)) * 16);
        pA0[it] = Ahi + (size_t)(m0 + row) * K + col * 8;
        pA1[it] = Alo + (size_t)(m0 + row) * K + col * 8;
        pB0[it] = Bhi + (size_t)(n0 + row) * K + col * 8;
        pB1[it] = Blo + (size_t)(n0 + row) * K + col * 8;
    }

    float acc[4][8][4];
    #pragma unroll
    for (int i = 0; i < 4; i++)
        #pragma unroll
        for (int j = 0; j < 8; j++)
            #pragma unroll
            for (int c = 0; c < 4; c++) acc[i][j][c] = 0.f;

    const int nch = K >> 5;
    const int lrow = lane & 15;
    const int kc   = lane >> 4;

    #pragma unroll
    for (int s = 0; s < 2; s++) {
        const uint32_t sb = sbase + (uint32_t)s * G4_STAGE;
        const int kb = s << 5;
        #pragma unroll
        for (int it = 0; it < 4; it++) {
            CP16(sb + 0 * G4_TILE + so[it], pA0[it] + kb);
            CP16(sb + 1 * G4_TILE + so[it], pA1[it] + kb);
            CP16(sb + 2 * G4_TILE + so[it], pB0[it] + kb);
            CP16(sb + 3 * G4_TILE + so[it], pB1[it] + kb);
        }
        CP_COMMIT();
    }

    for (int ch = 0; ch < nch; ch++) {
        CP_WAIT1();
        __syncthreads();

        if (ch + 2 < nch) {
            const uint32_t sb = sbase + (uint32_t)((ch + 2) % 3) * G4_STAGE;
            const int kb = (ch + 2) << 5;
            #pragma unroll
            for (int it = 0; it < 4; it++) {
                CP16(sb + 0 * G4_TILE + so[it], pA0[it] + kb);
                CP16(sb + 1 * G4_TILE + so[it], pA1[it] + kb);
                CP16(sb + 2 * G4_TILE + so[it], pB0[it] + kb);
                CP16(sb + 3 * G4_TILE + so[it], pB1[it] + kb);
            }
        }
        CP_COMMIT();

        const uint32_t st = sbase + (uint32_t)(ch % 3) * G4_STAGE;

        #pragma unroll
        for (int kk = 0; kk < 2; kk++) {
            const int chunk = kk * 2 + kc;
            uint32_t ahi[4][4], alo[4][4];
            #pragma unroll
            for (int mi = 0; mi < 4; mi++) {
                const int r = wm * 64 + mi * 16 + lrow;
                const uint32_t off = (uint32_t)r * 64 +
                    (uint32_t)((chunk ^ ((r >> 1) & 3)) * 16);
                LDSM_X4(ahi[mi][0], ahi[mi][1], ahi[mi][2], ahi[mi][3],
                        st + 0 * G4_TILE + off);
                LDSM_X4(alo[mi][0], alo[mi][1], alo[mi][2], alo[mi][3],
                        st + 1 * G4_TILE + off);
            }
            #pragma unroll
            for (int g = 0; g < 4; g++) {
                const int r = wn * 64 + g * 16 + lrow;
                const uint32_t off = (uint32_t)r * 64 +
                    (uint32_t)((chunk ^ ((r >> 1) & 3)) * 16);
                uint32_t bh[4], bl[4];
                LDSM_X4(bh[0], bh[1], bh[2], bh[3], st + 2 * G4_TILE + off);
                LDSM_X4(bl[0], bl[1], bl[2], bl[3], st + 3 * G4_TILE + off);
                #pragma unroll
                for (int mi = 0; mi < 4; mi++) {
                    MMA_BF16(acc[mi][g * 2 + 0], ahi[mi], bh[0], bh[2]);
                    MMA_BF16(acc[mi][g * 2 + 0], ahi[mi], bl[0], bl[2]);
                    MMA_BF16(acc[mi][g * 2 + 0], alo[mi], bh[0], bh[2]);
                    MMA_BF16(acc[mi][g * 2 + 1], ahi[mi], bh[1], bh[3]);
                    MMA_BF16(acc[mi][g * 2 + 1], ahi[mi], bl[1], bl[3]);
                    MMA_BF16(acc[mi][g * 2 + 1], alo[mi], bh[1], bh[3]);
                }
            }
        }
    }

    const int orow = lane >> 2;          // row-in-16 (0..7)
    const int ocol = (lane & 3) * 2;     // col pair base within 8

    if constexpr (!FUSE) {
        #pragma unroll
        for (int mi = 0; mi < 4; mi++) {
            const int r0 = m0 + wm * 64 + mi * 16 + orow;
            #pragma unroll
            for (int ni = 0; ni < 8; ni++) {
                const int c = n0 + wn * 64 + ni * 8 + ocol;
                const float b0 = bias[c], b1 = bias[c + 1];
                float2 v0 = make_float2(acc[mi][ni][0] + b0, acc[mi][ni][1] + b1);
                float2 v1 = make_float2(acc[mi][ni][2] + b0, acc[mi][ni][3] + b1);
                *(float2*)(Cmat + (size_t)r0 * N + c)       = v0;
                *(float2*)(Cmat + (size_t)(r0 + 8) * N + c) = v1;
            }
        }
    } else {
        const int colbase = n0 + wn * 64;          // 64-aligned -> one head
        const int type = colbase >> 10;            // 0=Q, 1=K, 2=V
        const int head = (colbase & 1023) >> 6;
        __nv_bfloat16* ghi = (type == 0) ? g_Qhi : (type == 1) ? g_Khi : g_Vhi;
        __nv_bfloat16* glo = (type == 0) ? g_Qlo : (type == 1) ? g_Klo : g_Vlo;
        const float sgn = (type == 1) ? -1.f : 1.f;

        float bs[8][2];
        #pragma unroll
        for (int ni = 0; ni < 8; ni++) {
            bs[ni][0] = bias[colbase + ni * 8 + ocol];
            bs[ni][1] = bias[colbase + ni * 8 + ocol + 1];
        }

        #pragma unroll
        for (int mi = 0; mi < 4; mi++) {
            #pragma unroll
            for (int hh = 0; hh < 2; hh++) {
                const int r = m0 + wm * 64 + mi * 16 + orow + hh * 8;
                const int batch = r >> 10, t = r & 1023;
                const size_t ob = ((size_t)(batch * H_ + head) * T_ + t) * D_;

                float v[8][2];
                float ss = 0.f;
                #pragma unroll
                for (int ni = 0; ni < 8; ni++) {
                    v[ni][0] = acc[mi][ni][hh * 2 + 0] + bs[ni][0];
                    v[ni][1] = acc[mi][ni][hh * 2 + 1] + bs[ni][1];
                    ss += v[ni][0] * v[ni][0] + v[ni][1] * v[ni][1];
                }

                if (type != 2) {
                    ss += __shfl_xor_sync(0xffffffffu, ss, 1);
                    ss += __shfl_xor_sync(0xffffffffu, ss, 2);
                    float u0 = __shfl_sync(0xffffffffu, v[0][0], lane & ~3u, 32);
                    float mink = ss - 2.f * u0 * u0;
                    float nn = sqrtf(fmaxf(mink, 1e-8f));
                    float e = __expf(nn), ei = 1.f / e;
                    float tme = 0.5f * (e + ei);
                    float coef = sgn * (e - ei) / (2.f * nn);
                    #pragma unroll
                    for (int ni = 0; ni < 8; ni++) {
                        v[ni][0] *= coef;
                        v[ni][1] *= coef;
                    }
                    if ((lane & 3) == 0) v[0][0] = tme;   // d==0 -> time comp
                }

                #pragma unroll
                for (int ni = 0; ni < 8; ni++) {
                    const int d = ni * 8 + ocol;
                    uint32_t hp = pack_bf16(v[ni][0], v[ni][1]);
                    __nv_bfloat162 hv = *(__nv_bfloat162*)&hp;
                    uint32_t lp = pack_bf16(v[ni][0] - __low2float(hv),
                                            v[ni][1] - __high2float(hv));
                    *(uint32_t*)(ghi + ob + d) = hp;
                    *(uint32_t*)(glo + ob + d) = lp;
                }
            }
        }
    }
}

// ---------------- tensor-core flash attention (bf16x3, R11 shape) -----------
// CTA: 64 q-rows, 4 warps (16 rows each), 128 threads; j tiles of 64.
// smem 64KB: buf0 @0, buf1 @32K (each: Khi+0 Klo+8K Vhi+16K Vlo+24K).
// Q staged at [32K,48K) (aliases buf1 Khi/Klo) and consumed into register
// A-fragments before the first prefetch overwrites buf1.
#define AT_SMEM 65536
#define SWO(row, ch) ((uint32_t)(row) * 128u + (uint32_t)(((ch) ^ (((row) >> 1) & 3)) * 16))

__global__ __launch_bounds__(128) void attn_kernel() {
    extern __shared__ char sm[];
    const uint32_t sb = smem_u32(sm);
    const int tid = threadIdx.x;
    const int wid = tid >> 5;
    const int lane = tid & 31;
    const int ti = (gridDim.x - 1) - blockIdx.x;   // heavy CTAs first
    const int h  = blockIdx.y;
    const int b  = blockIdx.z;
    const int bh = b * H_ + h;
    const int i0 = ti * 64;
    const size_t gb = (size_t)bh * T_ * D_;

    const int lrow  = lane & 15;
    const int khalf = lane >> 4;

    // ---- prologue: Q -> [32K,48K), K/V tile 0 -> buf0 [0,32K) ----
    #pragma unroll
    for (int i = 0; i < 8; i++) {
        const int arr = i >> 2;
        const int sub = tid + (i & 3) * 128;
        const int row = sub >> 3, ch = sub & 7;
        const __nv_bfloat16* g = arr ? g_Qlo : g_Qhi;
        CP16(sb + 32768u + (uint32_t)arr * 8192u + SWO(row, ch),
             g + gb + (size_t)(i0 + row) * D_ + ch * 8);
    }
    #pragma unroll
    for (int i = 0; i < 16; i++) {
        const int arr = i >> 2;
        const int sub = tid + (i & 3) * 128;
        const int row = sub >> 3, ch = sub & 7;
        const __nv_bfloat16* g = (arr == 0) ? g_Khi : (arr == 1) ? g_Klo
                               : (arr == 2) ? g_Vhi : g_Vlo;
        CP16(sb + (uint32_t)arr * 8192u + SWO(row, ch),
             g + gb + (size_t)row * D_ + ch * 8);
    }
    CP_COMMIT();

    float O[8][4];
    #pragma unroll
    for (int i = 0; i < 8; i++)
        #pragma unroll
        for (int c = 0; c < 4; c++) O[i][c] = 0.f;
    float m0 = -1e30f, m1 = -1e30f, l0 = 0.f, l1 = 0.f;
    uint32_t ahi[4][4], alo[4][4];

    const int rq = lane >> 2;
    const int cq = (lane & 3) * 2;
    const int grow0 = i0 + wid * 16 + rq;
    const int grow1 = grow0 + 8;

    for (int tj = 0; tj <= ti; tj++) {
        CP_WAIT0();            // tile tj (and, for tj==0, Q) landed
        __syncthreads();

        if (tj == 0) {
            // Q A-frags from the staging region, cached for all tiles
            #pragma unroll
            for (int kc = 0; kc < 4; kc++) {
                const int r = wid * 16 + lrow;
                const uint32_t off = SWO(r, kc * 2 + khalf);
                LDSM_X4(ahi[kc][0], ahi[kc][1], ahi[kc][2], ahi[kc][3],
                        sb + 32768u + off);
                LDSM_X4(alo[kc][0], alo[kc][1], alo[kc][2], alo[kc][3],
                        sb + 40960u + off);
            }
            __syncthreads();   // Q reads done before buf1 prefetch overwrites
        }

        if (tj < ti) {         // prefetch tile tj+1 into the other buffer
            const uint32_t dst = sb + (uint32_t)((tj + 1) & 1) * 32768u;
            const size_t src = gb + (size_t)(tj + 1) * 64 * D_;
            #pragma unroll
            for (int i = 0; i < 16; i++) {
                const int arr = i >> 2;
                const int sub = tid + (i & 3) * 128;
                const int row = sub >> 3, ch = sub & 7;
                const __nv_bfloat16* g = (arr == 0) ? g_Khi : (arr == 1) ? g_Klo
                                       : (arr == 2) ? g_Vhi : g_Vlo;
                CP16(dst + (uint32_t)arr * 8192u + SWO(row, ch),
                     g + src + (size_t)row * D_ + ch * 8);
            }
            CP_COMMIT();
        }

        const uint32_t kbuf = sb + (uint32_t)(tj & 1) * 32768u;

        // ---- S = Q' K'^T (bf16x3) ----
        float acc[8][4];
        #pragma unroll
        for (int i = 0; i < 8; i++)
            #pragma unroll
            for (int c = 0; c < 4; c++) acc[i][c] = 0.f;

        #pragma unroll
        for (int kc = 0; kc < 4; kc++) {
            uint32_t bh4[4][4], bl4[4][4];
            #pragma unroll
            for (int g = 0; g < 4; g++) {
                const int r = g * 16 + lrow;
                const uint32_t off = SWO(r, kc * 2 + khalf);
                LDSM_X4(bh4[g][0], bh4[g][1], bh4[g][2], bh4[g][3], kbuf + off);
                LDSM_X4(bl4[g][0], bl4[g][1], bl4[g][2], bl4[g][3],
                        kbuf + 8192u + off);
            }
            #pragma unroll
            for (int ni = 0; ni < 8; ni++) {
                const int g = ni >> 1, o = ni & 1;
                MMA_BF16(acc[ni], ahi[kc], bh4[g][o], bh4[g][2 + o]);
                MMA_BF16(acc[ni], ahi[kc], bl4[g][o], bl4[g][2 + o]);
                MMA_BF16(acc[ni], alo[kc], bh4[g][o], bh4[g][2 + o]);
            }
        }

        // ---- Lorentz transform + causal mask ----
        const int j0 = tj * 64;
        #pragma unroll
        for (int ni = 0; ni < 8; ni++) {
            #pragma unroll
            for (int c = 0; c < 4; c++) {
                const int col = j0 + ni * 8 + cq + (c & 1);
                const int grow = (c < 2) ? grow0 : grow1;
                float x = fmaxf(acc[ni][c], 1.0f + 1e-7f);
                float dd = __logf(x + sqrtf(fmaxf(x * x - 1.f, 0.f)));
                float s = -dd * dd * 0.125f;
                acc[ni][c] = (col > grow) ? -1e30f : s;
            }
        }

        // ---- online softmax (rows grow0 / grow1, quad = 4 lanes) ----
        {
            float mx = -1e30f;
            #pragma unroll
            for (int ni = 0; ni < 8; ni++)
                mx = fmaxf(mx, fmaxf(acc[ni][0], acc[ni][1]));
            mx = fmaxf(mx, __shfl_xor_sync(0xffffffffu, mx, 1));
            mx = fmaxf(mx, __shfl_xor_sync(0xffffffffu, mx, 2));
            float mnew = fmaxf(m0, mx);
            float es = __expf(m0 - mnew);
            l0 *= es;
            #pragma unroll
            for (int ni = 0; ni < 8; ni++) { O[ni][0] *= es; O[ni][1] *= es; }
            float rs = 0.f;
            #pragma unroll
            for (int ni = 0; ni < 8; ni++) {
                float p0 = __expf(acc[ni][0] - mnew);
                float p1 = __expf(acc[ni][1] - mnew);
                acc[ni][0] = p0; acc[ni][1] = p1; rs += p0 + p1;
            }
            rs += __shfl_xor_sync(0xffffffffu, rs, 1);
            rs += __shfl_xor_sync(0xffffffffu, rs, 2);
            l0 += rs; m0 = mnew;
        }
        {
            float mx = -1e30f;
            #pragma unroll
            for (int ni = 0; ni < 8; ni++)
                mx = fmaxf(mx, fmaxf(acc[ni][2], acc[ni][3]));
            mx = fmaxf(mx, __shfl_xor_sync(0xffffffffu, mx, 1));
            mx = fmaxf(mx, __shfl_xor_sync(0xffffffffu, mx, 2));
            float mnew = fmaxf(m1, mx);
            float es = __expf(m1 - mnew);
            l1 *= es;
            #pragma unroll
            for (int ni = 0; ni < 8; ni++) { O[ni][2] *= es; O[ni][3] *= es; }
            float rs = 0.f;
            #pragma unroll
            for (int ni = 0; ni < 8; ni++) {
                float p0 = __expf(acc[ni][2] - mnew);
                float p1 = __expf(acc[ni][3] - mnew);
                acc[ni][2] = p0; acc[ni][3] = p1; rs += p0 + p1;
            }
            rs += __shfl_xor_sync(0xffffffffu, rs, 1);
            rs += __shfl_xor_sync(0xffffffffu, rs, 2);
            l1 += rs; m1 = mnew;
        }

        // ---- PV: O += P V (bf16x3, P packed in registers) ----
        const uint32_t vbuf = kbuf + 16384u;
        #pragma unroll
        for (int kc = 0; kc < 4; kc++) {
            uint32_t ph[4], pl[4];
            #pragma unroll
            for (int q = 0; q < 4; q++) {
                const int ni = 2 * kc + (q >> 1);
                const int c0 = (q & 1) * 2;
                float a = acc[ni][c0], bb = acc[ni][c0 + 1];
                uint32_t hp = pack_bf16(a, bb);
                __nv_bfloat162 hv = *(__nv_bfloat162*)&hp;
                const int idx = (q & 1) + (q >> 1) * 2;
                ph[idx] = hp;
                pl[idx] = pack_bf16(a - __low2float(hv), bb - __high2float(hv));
            }
            #pragma unroll
            for (int g = 0; g < 4; g++) {
                const int r = kc * 16 + ((lane >> 3) & 1) * 8 + (lane & 7);
                const uint32_t off = SWO(r, g * 2 + khalf);
                uint32_t vh[4], vl[4];
                LDSM_X4_T(vh[0], vh[1], vh[2], vh[3], vbuf + off);
                LDSM_X4_T(vl[0], vl[1], vl[2], vl[3], vbuf + 8192u + off);
                MMA_BF16(O[g * 2],     ph, vh[0], vh[1]);
                MMA_BF16(O[g * 2],     ph, vl[0], vl[1]);
                MMA_BF16(O[g * 2],     pl, vh[0], vh[1]);
                MMA_BF16(O[g * 2 + 1], ph, vh[2], vh[3]);
                MMA_BF16(O[g * 2 + 1], ph, vl[2], vl[3]);
                MMA_BF16(O[g * 2 + 1], pl, vh[2], vh[3]);
            }
        }
        // no trailing sync: next iteration's top-of-loop barrier protects reuse
    }

    // ---- epilogue: write Yhi/Ylo bf16 directly ----
    const float inv0 = g_spike[b * T_ + grow0] / l0;
    const float inv1 = g_spike[b * T_ + grow1] / l1;
    const size_t y0 = ((size_t)(b * T_ + grow0)) * C_ + h * D_;
    const size_t y1 = ((size_t)(b * T_ + grow1)) * C_ + h * D_;
    #pragma unroll
    for (int ni = 0; ni < 8; ni++) {
        const int d = ni * 8 + cq;
        float a0 = O[ni][0] * inv0, a1 = O[ni][1] * inv0;
        float b0 = O[ni][2] * inv1, b1 = O[ni][3] * inv1;
        uint32_t h0 = pack_bf16(a0, a1);
        __nv_bfloat162 hv0 = *(__nv_bfloat162*)&h0;
        uint32_t l0p = pack_bf16(a0 - __low2float(hv0), a1 - __high2float(hv0));
        uint32_t h1 = pack_bf16(b0, b1);
        __nv_bfloat162 hv1 = *(__nv_bfloat162*)&h1;
        uint32_t l1p = pack_bf16(b0 - __low2float(hv1), b1 - __high2float(hv1));
        *(uint32_t*)(g_Yhi + y0 + d) = h0;
        *(uint32_t*)(g_Ylo + y0 + d) = l0p;
        *(uint32_t*)(g_Yhi + y1 + d) = h1;
        *(uint32_t*)(g_Ylo + y1 + d) = l1p;
    }
}

// ---------------- launch -----------------------------------------------------
extern "C" void kernel_launch(void* const* d_in, const int* in_sizes, int n_in,
                              void* d_out, int out_size) {
    const float* x      = (const float*)d_in[0];
    const float* W_qkv  = (const float*)d_in[1];
    const float* b_qkv  = (const float*)d_in[2];
    const float* W_out  = (const float*)d_in[3];
    const float* b_out  = (const float*)d_in[4];
    const float* w_sur  = (const float*)d_in[5];
    const float* b_sur  = (const float*)d_in[6];
    const float* thresh = (const float*)d_in[7];
    float* out = (float*)d_out;

    __nv_bfloat16 *p_xhi, *p_xlo, *p_Wqt_hi, *p_Wqt_lo;
    __nv_bfloat16 *p_Yhi, *p_Ylo, *p_Wot_hi, *p_Wot_lo;
    cudaGetSymbolAddress((void**)&p_xhi, g_xhi);
    cudaGetSymbolAddress((void**)&p_xlo, g_xlo);
    cudaGetSymbolAddress((void**)&p_Wqt_hi, g_Wqt_hi);
    cudaGetSymbolAddress((void**)&p_Wqt_lo, g_Wqt_lo);
    cudaGetSymbolAddress((void**)&p_Yhi, g_Yhi);
    cudaGetSymbolAddress((void**)&p_Ylo, g_Ylo);
    cudaGetSymbolAddress((void**)&p_Wot_hi, g_Wot_hi);
    cudaGetSymbolAddress((void**)&p_Wot_lo, g_Wot_lo);

    cudaFuncSetAttribute(attn_kernel,
                         cudaFuncAttributeMaxDynamicSharedMemorySize, AT_SMEM);
    cudaFuncSetAttribute(gemm4_kernel<true>,
                         cudaFuncAttributeMaxDynamicSharedMemorySize, G4_SMEM);
    cudaFuncSetAttribute(gemm4_kernel<false>,
                         cudaFuncAttributeMaxDynamicSharedMemorySize, G4_SMEM);

    const int M = B_ * T_;   // 4096

    // 1. fused x prep: spike gate + bf16 hi/lo split (single x read)
    prep_x_kernel<<<M / 8, 256>>>(x, w_sur, b_sur, thresh, p_xhi, p_xlo);

    // 2. weight prep for QKV GEMM
    transpose_split_kernel<<<dim3(3 * C_ / 32, C_ / 32), dim3(32, 8)>>>(
        W_qkv, p_Wqt_hi, p_Wqt_lo, C_, 3 * C_);

    // 3. QKV GEMM with fused Lorentz transform epilogue -> g_{Q,K,V}{hi,lo}
    gemm4_kernel<true><<<dim3(3 * C_ / 128, M / 128), 128, G4_SMEM>>>(
        p_xhi, p_xlo, p_Wqt_hi, p_Wqt_lo, b_qkv, nullptr, M, 3 * C_, C_);

    // 4. tensor-core flash attention (R11 shape)
    attn_kernel<<<dim3(T_ / 64, H_, B_), 128, AT_SMEM>>>();

    // 5. out projection
    transpose_split_kernel<<<dim3(C_ / 32, C_ / 32), dim3(32, 8)>>>(
        W_out, p_Wot_hi, p_Wot_lo, C_, C_);
    gemm4_kernel<false><<<dim3(C_ / 128, M / 128), 128, G4_SMEM>>>(
        p_Yhi, p_Ylo, p_Wot_hi, p_Wot_lo, b_out, out, M, C_, C_);
}

// round 14
// speedup vs baseline: 1.0907x; 1.0622x over previous
#include <cuda_runtime.h>
#include <cuda_bf16.h>
#include <math.h>
#include <stdint.h>

#define B_ 4
#define T_ 1024
#define C_ 1024
#define H_ 16
#define D_ 64

// ---------------- scratch (device globals; no allocations allowed) ----------
__device__ float g_spike[B_ * T_];

// transformed Q',K',V as bf16 hi/lo  [BH][T][64]
__device__ __nv_bfloat16 g_Qhi[(size_t)B_ * H_ * T_ * D_];
__device__ __nv_bfloat16 g_Qlo[(size_t)B_ * H_ * T_ * D_];
__device__ __nv_bfloat16 g_Khi[(size_t)B_ * H_ * T_ * D_];
__device__ __nv_bfloat16 g_Klo[(size_t)B_ * H_ * T_ * D_];
__device__ __nv_bfloat16 g_Vhi[(size_t)B_ * H_ * T_ * D_];
__device__ __nv_bfloat16 g_Vlo[(size_t)B_ * H_ * T_ * D_];

// bf16 hi/lo split operands for tensor-core GEMMs
__device__ __nv_bfloat16 g_xhi[(size_t)B_ * T_ * C_];
__device__ __nv_bfloat16 g_xlo[(size_t)B_ * T_ * C_];
__device__ __nv_bfloat16 g_Wqt_hi[(size_t)3 * C_ * C_];    // W_qkv^T [N,K]
__device__ __nv_bfloat16 g_Wqt_lo[(size_t)3 * C_ * C_];
__device__ __nv_bfloat16 g_Yhi[(size_t)B_ * T_ * C_];      // attn out, bf16 hi/lo
__device__ __nv_bfloat16 g_Ylo[(size_t)B_ * T_ * C_];
__device__ __nv_bfloat16 g_Wot_hi[(size_t)C_ * C_];        // W_out^T [N,K]
__device__ __nv_bfloat16 g_Wot_lo[(size_t)C_ * C_];

// ======================= generic-PTX helpers (no 'a' features) ==============
__device__ __forceinline__ uint32_t smem_u32(const void* p) {
    uint32_t a;
    asm("{ .reg .u64 t; cvta.to.shared.u64 t, %1; cvt.u32.u64 %0, t; }"
        : "=r"(a) : "l"(p));
    return a;
}
__device__ __forceinline__ float sqrt_approx(float x) {
    float r;
    asm("sqrt.approx.f32 %0, %1;" : "=f"(r) : "f"(x));
    return r;
}
#define CP16(saddr, gaddr) \
    asm volatile("cp.async.cg.shared.global [%0], [%1], 16;" \
                 :: "r"(saddr), "l"(gaddr))
#define CP_COMMIT() asm volatile("cp.async.commit_group;" ::: "memory")
#define CP_WAIT1()  asm volatile("cp.async.wait_group 1;" ::: "memory")
#define CP_WAIT0()  asm volatile("cp.async.wait_group 0;" ::: "memory")

#define LDSM_X4(r0, r1, r2, r3, addr) \
    asm volatile("ldmatrix.sync.aligned.m8n8.x4.shared.b16 {%0,%1,%2,%3}, [%4];" \
                 : "=r"(r0), "=r"(r1), "=r"(r2), "=r"(r3) : "r"(addr))

#define LDSM_X4_T(r0, r1, r2, r3, addr) \
    asm volatile("ldmatrix.sync.aligned.m8n8.x4.trans.shared.b16 {%0,%1,%2,%3}, [%4];" \
                 : "=r"(r0), "=r"(r1), "=r"(r2), "=r"(r3) : "r"(addr))

#define MMA_BF16(d, a, b0, b1) \
    asm volatile("mma.sync.aligned.m16n8k16.row.col.f32.bf16.bf16.f32 " \
                 "{%0,%1,%2,%3}, {%4,%5,%6,%7}, {%8,%9}, {%0,%1,%2,%3};" \
                 : "+f"((d)[0]), "+f"((d)[1]), "+f"((d)[2]), "+f"((d)[3]) \
                 : "r"((a)[0]), "r"((a)[1]), "r"((a)[2]), "r"((a)[3]), \
                   "r"(b0), "r"(b1))

__device__ __forceinline__ uint32_t pack_bf16(float a, float b) {
    __nv_bfloat162 h = __floats2bfloat162_rn(a, b);
    return *(uint32_t*)&h;
}

// ---------------- fused prep: spike+x split | W_qkv^T split | W_out^T split -
__device__ __forceinline__ void transpose_tile(
    const float* __restrict__ W, __nv_bfloat16* __restrict__ Thi,
    __nv_bfloat16* __restrict__ Tlo, int K, int N, int k0, int n0,
    int tx, int ty, float (*tile)[33])
{
    #pragma unroll
    for (int j = 0; j < 32; j += 8)
        tile[ty + j][tx] = W[(size_t)(k0 + ty + j) * N + n0 + tx];
    __syncthreads();
    #pragma unroll
    for (int j = 0; j < 32; j += 8) {
        float v = tile[tx][ty + j];
        __nv_bfloat16 h = __float2bfloat16(v);
        __nv_bfloat16 l = __float2bfloat16(v - __bfloat162float(h));
        Thi[(size_t)(n0 + ty + j) * K + k0 + tx] = h;
        Tlo[(size_t)(n0 + ty + j) * K + k0 + tx] = l;
    }
}

// grid: [0,512) x-prep | [512,3584) W_qkv tiles (96x32) | [3584,4608) W_out (32x32)
__global__ void prep_all_kernel(const float* __restrict__ x,
                                const float* __restrict__ W_qkv,
                                const float* __restrict__ W_out,
                                const float* __restrict__ w_sur,
                                const float* __restrict__ b_sur,
                                const float* __restrict__ threshold,
                                __nv_bfloat16* __restrict__ xhi,
                                __nv_bfloat16* __restrict__ xlo,
                                __nv_bfloat16* __restrict__ Wqt_hi,
                                __nv_bfloat16* __restrict__ Wqt_lo,
                                __nv_bfloat16* __restrict__ Wot_hi,
                                __nv_bfloat16* __restrict__ Wot_lo) {
    __shared__ float tile[32][33];
    const int bid = blockIdx.x;
    const int tid = threadIdx.x;

    if (bid < 512) {
        // ---- x prep: one warp per row; spike dot + bf16 hi/lo split ----
        const int row = bid * 8 + (tid >> 5);
        const int lane = tid & 31;
        const float* xr = x + (size_t)row * C_;
        float s = 0.f;
        #pragma unroll
        for (int i = 0; i < 8; i++) {
            const int e = lane * 4 + i * 128;
            float4 v = *(const float4*)(xr + e);
            float4 w = *(const float4*)(w_sur + e);
            s += v.x * w.x + v.y * w.y + v.z * w.z + v.w * w.w;

            __nv_bfloat16 h0 = __float2bfloat16(v.x);
            __nv_bfloat16 h1 = __float2bfloat16(v.y);
            __nv_bfloat16 h2 = __float2bfloat16(v.z);
            __nv_bfloat16 h3 = __float2bfloat16(v.w);
            __nv_bfloat162* hp = (__nv_bfloat162*)(xhi + (size_t)row * C_ + e);
            __nv_bfloat162* lp = (__nv_bfloat162*)(xlo + (size_t)row * C_ + e);
            hp[0] = __nv_bfloat162(h0, h1);
            hp[1] = __nv_bfloat162(h2, h3);
            lp[0] = __nv_bfloat162(__float2bfloat16(v.x - __bfloat162float(h0)),
                                   __float2bfloat16(v.y - __bfloat162float(h1)));
            lp[1] = __nv_bfloat162(__float2bfloat16(v.z - __bfloat162float(h2)),
                                   __float2bfloat16(v.w - __bfloat162float(h3)));
        }
        #pragma unroll
        for (int m = 16; m; m >>= 1) s += __shfl_xor_sync(0xffffffffu, s, m);
        if (lane == 0) {
            float z = s + b_sur[0];
            float imp = 1.f / (1.f + expf(-z));
            g_spike[row] = (imp > threshold[0]) ? 1.f : 0.f;
        }
    } else if (bid < 3584) {
        const int t = bid - 512;                 // W_qkv: N=3072 (96 tiles), K=1024
        transpose_tile(W_qkv, Wqt_hi, Wqt_lo, C_, 3 * C_,
                       (t / 96) * 32, (t % 96) * 32, tid & 31, tid >> 5, tile);
    } else {
        const int t = bid - 3584;                // W_out: N=1024 (32), K=1024
        transpose_tile(W_out, Wot_hi, Wot_lo, C_, C_,
                       (t / 32) * 32, (t % 32) * 32, tid & 31, tid >> 5, tile);
    }
}

// ---------------- mma.sync bf16x3 GEMM, 4 warps x (64x64) warp tiles --------
#define G4_STAGE 32768
#define G4_SMEM (3 * G4_STAGE)
#define G4_TILE 8192

template<bool FUSE>
__global__ __launch_bounds__(128) void gemm4_kernel(
    const __nv_bfloat16* __restrict__ Ahi, const __nv_bfloat16* __restrict__ Alo,
    const __nv_bfloat16* __restrict__ Bhi, const __nv_bfloat16* __restrict__ Blo,
    const float* __restrict__ bias, float* __restrict__ Cmat,
    int M, int N, int K)
{
    extern __shared__ char sm[];
    const uint32_t sbase = smem_u32(sm);

    const int tid  = threadIdx.x;
    const int wid  = tid >> 5;
    const int lane = tid & 31;
    const int m0 = blockIdx.y * 128;
    const int n0 = blockIdx.x * 128;
    const int wm = wid & 1;          // 64-row slab
    const int wn = wid >> 1;         // 64-col slab

    uint32_t so[4];
    const __nv_bfloat16 *pA0[4], *pA1[4], *pB0[4], *pB1[4];
    #pragma unroll
    for (int it = 0; it < 4; it++) {
        const int sub = tid + it * 128;
        const int row = sub >> 2, col = sub & 3;
        so[it] = (uint32_t)row * 64 + (uint32_t)((col ^ ((row >> 1) & 3)) * 16);
        pA0[it] = Ahi + (size_t)(m0 + row) * K + col * 8;
        pA1[it] = Alo + (size_t)(m0 + row) * K + col * 8;
        pB0[it] = Bhi + (size_t)(n0 + row) * K + col * 8;
        pB1[it] = Blo + (size_t)(n0 + row) * K + col * 8;
    }

    float acc[4][8][4];
    #pragma unroll
    for (int i = 0; i < 4; i++)
        #pragma unroll
        for (int j = 0; j < 8; j++)
            #pragma unroll
            for (int c = 0; c < 4; c++) acc[i][j][c] = 0.f;

    const int nch = K >> 5;
    const int lrow = lane & 15;
    const int kc   = lane >> 4;

    #pragma unroll
    for (int s = 0; s < 2; s++) {
        const uint32_t sb = sbase + (uint32_t)s * G4_STAGE;
        const int kb = s << 5;
        #pragma unroll
        for (int it = 0; it < 4; it++) {
            CP16(sb + 0 * G4_TILE + so[it], pA0[it] + kb);
            CP16(sb + 1 * G4_TILE + so[it], pA1[it] + kb);
            CP16(sb + 2 * G4_TILE + so[it], pB0[it] + kb);
            CP16(sb + 3 * G4_TILE + so[it], pB1[it] + kb);
        }
        CP_COMMIT();
    }

    for (int ch = 0; ch < nch; ch++) {
        CP_WAIT1();
        __syncthreads();

        if (ch + 2 < nch) {
            const uint32_t sb = sbase + (uint32_t)((ch + 2) % 3) * G4_STAGE;
            const int kb = (ch + 2) << 5;
            #pragma unroll
            for (int it = 0; it < 4; it++) {
                CP16(sb + 0 * G4_TILE + so[it], pA0[it] + kb);
                CP16(sb + 1 * G4_TILE + so[it], pA1[it] + kb);
                CP16(sb + 2 * G4_TILE + so[it], pB0[it] + kb);
                CP16(sb + 3 * G4_TILE + so[it], pB1[it] + kb);
            }
        }
        CP_COMMIT();

        const uint32_t st = sbase + (uint32_t)(ch % 3) * G4_STAGE;

        #pragma unroll
        for (int kk = 0; kk < 2; kk++) {
            const int chunk = kk * 2 + kc;
            uint32_t ahi[4][4], alo[4][4];
            #pragma unroll
            for (int mi = 0; mi < 4; mi++) {
                const int r = wm * 64 + mi * 16 + lrow;
                const uint32_t off = (uint32_t)r * 64 +
                    (uint32_t)((chunk ^ ((r >> 1) & 3)) * 16);
                LDSM_X4(ahi[mi][0], ahi[mi][1], ahi[mi][2], ahi[mi][3],
                        st + 0 * G4_TILE + off);
                LDSM_X4(alo[mi][0], alo[mi][1], alo[mi][2], alo[mi][3],
                        st + 1 * G4_TILE + off);
            }
            #pragma unroll
            for (int g = 0; g < 4; g++) {
                const int r = wn * 64 + g * 16 + lrow;
                const uint32_t off = (uint32_t)r * 64 +
                    (uint32_t)((chunk ^ ((r >> 1) & 3)) * 16);
                uint32_t bh[4], bl[4];
                LDSM_X4(bh[0], bh[1], bh[2], bh[3], st + 2 * G4_TILE + off);
                LDSM_X4(bl[0], bl[1], bl[2], bl[3], st + 3 * G4_TILE + off);
                #pragma unroll
                for (int mi = 0; mi < 4; mi++) {
                    MMA_BF16(acc[mi][g * 2 + 0], ahi[mi], bh[0], bh[2]);
                    MMA_BF16(acc[mi][g * 2 + 0], ahi[mi], bl[0], bl[2]);
                    MMA_BF16(acc[mi][g * 2 + 0], alo[mi], bh[0], bh[2]);
                    MMA_BF16(acc[mi][g * 2 + 1], ahi[mi], bh[1], bh[3]);
                    MMA_BF16(acc[mi][g * 2 + 1], ahi[mi], bl[1], bl[3]);
                    MMA_BF16(acc[mi][g * 2 + 1], alo[mi], bh[1], bh[3]);
                }
            }
        }
    }

    const int orow = lane >> 2;          // row-in-16 (0..7)
    const int ocol = (lane & 3) * 2;     // col pair base within 8

    if constexpr (!FUSE) {
        #pragma unroll
        for (int mi = 0; mi < 4; mi++) {
            const int r0 = m0 + wm * 64 + mi * 16 + orow;
            #pragma unroll
            for (int ni = 0; ni < 8; ni++) {
                const int c = n0 + wn * 64 + ni * 8 + ocol;
                const float b0 = bias[c], b1 = bias[c + 1];
                float2 v0 = make_float2(acc[mi][ni][0] + b0, acc[mi][ni][1] + b1);
                float2 v1 = make_float2(acc[mi][ni][2] + b0, acc[mi][ni][3] + b1);
                *(float2*)(Cmat + (size_t)r0 * N + c)       = v0;
                *(float2*)(Cmat + (size_t)(r0 + 8) * N + c) = v1;
            }
        }
    } else {
        const int colbase = n0 + wn * 64;          // 64-aligned -> one head
        const int type = colbase >> 10;            // 0=Q, 1=K, 2=V
        const int head = (colbase & 1023) >> 6;
        __nv_bfloat16* ghi = (type == 0) ? g_Qhi : (type == 1) ? g_Khi : g_Vhi;
        __nv_bfloat16* glo = (type == 0) ? g_Qlo : (type == 1) ? g_Klo : g_Vlo;
        const float sgn = (type == 1) ? -1.f : 1.f;

        float bs[8][2];
        #pragma unroll
        for (int ni = 0; ni < 8; ni++) {
            bs[ni][0] = bias[colbase + ni * 8 + ocol];
            bs[ni][1] = bias[colbase + ni * 8 + ocol + 1];
        }

        #pragma unroll
        for (int mi = 0; mi < 4; mi++) {
            #pragma unroll
            for (int hh = 0; hh < 2; hh++) {
                const int r = m0 + wm * 64 + mi * 16 + orow + hh * 8;
                const int batch = r >> 10, t = r & 1023;
                const size_t ob = ((size_t)(batch * H_ + head) * T_ + t) * D_;

                float v[8][2];
                float ss = 0.f;
                #pragma unroll
                for (int ni = 0; ni < 8; ni++) {
                    v[ni][0] = acc[mi][ni][hh * 2 + 0] + bs[ni][0];
                    v[ni][1] = acc[mi][ni][hh * 2 + 1] + bs[ni][1];
                    ss += v[ni][0] * v[ni][0] + v[ni][1] * v[ni][1];
                }

                if (type != 2) {
                    ss += __shfl_xor_sync(0xffffffffu, ss, 1);
                    ss += __shfl_xor_sync(0xffffffffu, ss, 2);
                    float u0 = __shfl_sync(0xffffffffu, v[0][0], lane & ~3u, 32);
                    float mink = ss - 2.f * u0 * u0;
                    float nn = sqrtf(fmaxf(mink, 1e-8f));
                    float e = __expf(nn), ei = 1.f / e;
                    float tme = 0.5f * (e + ei);
                    float coef = sgn * (e - ei) / (2.f * nn);
                    #pragma unroll
                    for (int ni = 0; ni < 8; ni++) {
                        v[ni][0] *= coef;
                        v[ni][1] *= coef;
                    }
                    if ((lane & 3) == 0) v[0][0] = tme;   // d==0 -> time comp
                }

                #pragma unroll
                for (int ni = 0; ni < 8; ni++) {
                    const int d = ni * 8 + ocol;
                    uint32_t hp = pack_bf16(v[ni][0], v[ni][1]);
                    __nv_bfloat162 hv = *(__nv_bfloat162*)&hp;
                    uint32_t lp = pack_bf16(v[ni][0] - __low2float(hv),
                                            v[ni][1] - __high2float(hv));
                    *(uint32_t*)(ghi + ob + d) = hp;
                    *(uint32_t*)(glo + ob + d) = lp;
                }
            }
        }
    }
}

// ---------------- tensor-core flash attention (bf16x3, R11 shape) -----------
#define AT_SMEM 65536
#define SWO(row, ch) ((uint32_t)(row) * 128u + (uint32_t)(((ch) ^ (((row) >> 1) & 3)) * 16))

__global__ __launch_bounds__(128) void attn_kernel() {
    extern __shared__ char sm[];
    const uint32_t sb = smem_u32(sm);
    const int tid = threadIdx.x;
    const int wid = tid >> 5;
    const int lane = tid & 31;
    const int ti = (gridDim.x - 1) - blockIdx.x;   // heavy CTAs first
    const int h  = blockIdx.y;
    const int b  = blockIdx.z;
    const int bh = b * H_ + h;
    const int i0 = ti * 64;
    const size_t gb = (size_t)bh * T_ * D_;

    const int lrow  = lane & 15;
    const int khalf = lane >> 4;

    // ---- prologue: Q -> [32K,48K), K/V tile 0 -> buf0 [0,32K) ----
    #pragma unroll
    for (int i = 0; i < 8; i++) {
        const int arr = i >> 2;
        const int sub = tid + (i & 3) * 128;
        const int row = sub >> 3, ch = sub & 7;
        const __nv_bfloat16* g = arr ? g_Qlo : g_Qhi;
        CP16(sb + 32768u + (uint32_t)arr * 8192u + SWO(row, ch),
             g + gb + (size_t)(i0 + row) * D_ + ch * 8);
    }
    #pragma unroll
    for (int i = 0; i < 16; i++) {
        const int arr = i >> 2;
        const int sub = tid + (i & 3) * 128;
        const int row = sub >> 3, ch = sub & 7;
        const __nv_bfloat16* g = (arr == 0) ? g_Khi : (arr == 1) ? g_Klo
                               : (arr == 2) ? g_Vhi : g_Vlo;
        CP16(sb + (uint32_t)arr * 8192u + SWO(row, ch),
             g + gb + (size_t)row * D_ + ch * 8);
    }
    CP_COMMIT();

    float O[8][4];
    #pragma unroll
    for (int i = 0; i < 8; i++)
        #pragma unroll
        for (int c = 0; c < 4; c++) O[i][c] = 0.f;
    float m0 = -1e30f, m1 = -1e30f, l0 = 0.f, l1 = 0.f;
    uint32_t ahi[4][4], alo[4][4];

    const int rq = lane >> 2;
    const int cq = (lane & 3) * 2;
    const int grow0 = i0 + wid * 16 + rq;
    const int grow1 = grow0 + 8;

    for (int tj = 0; tj <= ti; tj++) {
        CP_WAIT0();            // tile tj (and, for tj==0, Q) landed
        __syncthreads();

        if (tj == 0) {
            #pragma unroll
            for (int kc = 0; kc < 4; kc++) {
                const int r = wid * 16 + lrow;
                const uint32_t off = SWO(r, kc * 2 + khalf);
                LDSM_X4(ahi[kc][0], ahi[kc][1], ahi[kc][2], ahi[kc][3],
                        sb + 32768u + off);
                LDSM_X4(alo[kc][0], alo[kc][1], alo[kc][2], alo[kc][3],
                        sb + 40960u + off);
            }
            __syncthreads();   // Q reads done before buf1 prefetch overwrites
        }

        if (tj < ti) {         // prefetch tile tj+1 into the other buffer
            const uint32_t dst = sb + (uint32_t)((tj + 1) & 1) * 32768u;
            const size_t src = gb + (size_t)(tj + 1) * 64 * D_;
            #pragma unroll
            for (int i = 0; i < 16; i++) {
                const int arr = i >> 2;
                const int sub = tid + (i & 3) * 128;
                const int row = sub >> 3, ch = sub & 7;
                const __nv_bfloat16* g = (arr == 0) ? g_Khi : (arr == 1) ? g_Klo
                                       : (arr == 2) ? g_Vhi : g_Vlo;
                CP16(dst + (uint32_t)arr * 8192u + SWO(row, ch),
                     g + src + (size_t)row * D_ + ch * 8);
            }
            CP_COMMIT();
        }

        const uint32_t kbuf = sb + (uint32_t)(tj & 1) * 32768u;

        // ---- S = Q' K'^T (bf16x3) ----
        float acc[8][4];
        #pragma unroll
        for (int i = 0; i < 8; i++)
            #pragma unroll
            for (int c = 0; c < 4; c++) acc[i][c] = 0.f;

        #pragma unroll
        for (int kc = 0; kc < 4; kc++) {
            uint32_t bh4[4][4], bl4[4][4];
            #pragma unroll
            for (int g = 0; g < 4; g++) {
                const int r = g * 16 + lrow;
                const uint32_t off = SWO(r, kc * 2 + khalf);
                LDSM_X4(bh4[g][0], bh4[g][1], bh4[g][2], bh4[g][3], kbuf + off);
                LDSM_X4(bl4[g][0], bl4[g][1], bl4[g][2], bl4[g][3],
                        kbuf + 8192u + off);
            }
            #pragma unroll
            for (int ni = 0; ni < 8; ni++) {
                const int g = ni >> 1, o = ni & 1;
                MMA_BF16(acc[ni], ahi[kc], bh4[g][o], bh4[g][2 + o]);
                MMA_BF16(acc[ni], ahi[kc], bl4[g][o], bl4[g][2 + o]);
                MMA_BF16(acc[ni], alo[kc], bh4[g][o], bh4[g][2 + o]);
            }
        }

        // ---- Lorentz transform (approx sqrt) + causal mask ----
        const int j0 = tj * 64;
        #pragma unroll
        for (int ni = 0; ni < 8; ni++) {
            #pragma unroll
            for (int c = 0; c < 4; c++) {
                const int col = j0 + ni * 8 + cq + (c & 1);
                const int grow = (c < 2) ? grow0 : grow1;
                float x = fmaxf(acc[ni][c], 1.0f + 1e-7f);
                float dd = __logf(x + sqrt_approx(fmaxf(x * x - 1.f, 0.f)));
                float s = -dd * dd * 0.125f;
                acc[ni][c] = (col > grow) ? -1e30f : s;
            }
        }

        // ---- online softmax (rows grow0 / grow1, quad = 4 lanes) ----
        {
            float mx = -1e30f;
            #pragma unroll
            for (int ni = 0; ni < 8; ni++)
                mx = fmaxf(mx, fmaxf(acc[ni][0], acc[ni][1]));
            mx = fmaxf(mx, __shfl_xor_sync(0xffffffffu, mx, 1));
            mx = fmaxf(mx, __shfl_xor_sync(0xffffffffu, mx, 2));
            float mnew = fmaxf(m0, mx);
            float es = __expf(m0 - mnew);
            l0 *= es;
            #pragma unroll
            for (int ni = 0; ni < 8; ni++) { O[ni][0] *= es; O[ni][1] *= es; }
            float rs = 0.f;
            #pragma unroll
            for (int ni = 0; ni < 8; ni++) {
                float p0 = __expf(acc[ni][0] - mnew);
                float p1 = __expf(acc[ni][1] - mnew);
                acc[ni][0] = p0; acc[ni][1] = p1; rs += p0 + p1;
            }
            rs += __shfl_xor_sync(0xffffffffu, rs, 1);
            rs += __shfl_xor_sync(0xffffffffu, rs, 2);
            l0 += rs; m0 = mnew;
        }
        {
            float mx = -1e30f;
            #pragma unroll
            for (int ni = 0; ni < 8; ni++)
                mx = fmaxf(mx, fmaxf(acc[ni][2], acc[ni][3]));
            mx = fmaxf(mx, __shfl_xor_sync(0xffffffffu, mx, 1));
            mx = fmaxf(mx, __shfl_xor_sync(0xffffffffu, mx, 2));
            float mnew = fmaxf(m1, mx);
            float es = __expf(m1 - mnew);
            l1 *= es;
            #pragma unroll
            for (int ni = 0; ni < 8; ni++) { O[ni][2] *= es; O[ni][3] *= es; }
            float rs = 0.f;
            #pragma unroll
            for (int ni = 0; ni < 8; ni++) {
                float p0 = __expf(acc[ni][2] - mnew);
                float p1 = __expf(acc[ni][3] - mnew);
                acc[ni][2] = p0; acc[ni][3] = p1; rs += p0 + p1;
            }
            rs += __shfl_xor_sync(0xffffffffu, rs, 1);
            rs += __shfl_xor_sync(0xffffffffu, rs, 2);
            l1 += rs; m1 = mnew;
        }

        // ---- PV: O += P V (bf16x3, P packed in registers) ----
        const uint32_t vbuf = kbuf + 16384u;
        #pragma unroll
        for (int kc = 0; kc < 4; kc++) {
            uint32_t ph[4], pl[4];
            #pragma unroll
            for (int q = 0; q < 4; q++) {
                const int ni = 2 * kc + (q >> 1);
                const int c0 = (q & 1) * 2;
                float a = acc[ni][c0], bb = acc[ni][c0 + 1];
                uint32_t hp = pack_bf16(a, bb);
                __nv_bfloat162 hv = *(__nv_bfloat162*)&hp;
                const int idx = (q & 1) + (q >> 1) * 2;
                ph[idx] = hp;
                pl[idx] = pack_bf16(a - __low2float(hv), bb - __high2float(hv));
            }
            #pragma unroll
            for (int g = 0; g < 4; g++) {
                const int r = kc * 16 + ((lane >> 3) & 1) * 8 + (lane & 7);
                const uint32_t off = SWO(r, g * 2 + khalf);
                uint32_t vh[4], vl[4];
                LDSM_X4_T(vh[0], vh[1], vh[2], vh[3], vbuf + off);
                LDSM_X4_T(vl[0], vl[1], vl[2], vl[3], vbuf + 8192u + off);
                MMA_BF16(O[g * 2],     ph, vh[0], vh[1]);
                MMA_BF16(O[g * 2],     ph, vl[0], vl[1]);
                MMA_BF16(O[g * 2],     pl, vh[0], vh[1]);
                MMA_BF16(O[g * 2 + 1], ph, vh[2], vh[3]);
                MMA_BF16(O[g * 2 + 1], ph, vl[2], vl[3]);
                MMA_BF16(O[g * 2 + 1], pl, vh[2], vh[3]);
            }
        }
        // no trailing sync: next iteration's top-of-loop barrier protects reuse
    }

    // ---- epilogue: write Yhi/Ylo bf16 directly ----
    const float inv0 = g_spike[b * T_ + grow0] / l0;
    const float inv1 = g_spike[b * T_ + grow1] / l1;
    const size_t y0 = ((size_t)(b * T_ + grow0)) * C_ + h * D_;
    const size_t y1 = ((size_t)(b * T_ + grow1)) * C_ + h * D_;
    #pragma unroll
    for (int ni = 0; ni < 8; ni++) {
        const int d = ni * 8 + cq;
        float a0 = O[ni][0] * inv0, a1 = O[ni][1] * inv0;
        float b0 = O[ni][2] * inv1, b1 = O[ni][3] * inv1;
        uint32_t h0 = pack_bf16(a0, a1);
        __nv_bfloat162 hv0 = *(__nv_bfloat162*)&h0;
        uint32_t l0p = pack_bf16(a0 - __low2float(hv0), a1 - __high2float(hv0));
        uint32_t h1 = pack_bf16(b0, b1);
        __nv_bfloat162 hv1 = *(__nv_bfloat162*)&h1;
        uint32_t l1p = pack_bf16(b0 - __low2float(hv1), b1 - __high2float(hv1));
        *(uint32_t*)(g_Yhi + y0 + d) = h0;
        *(uint32_t*)(g_Ylo + y0 + d) = l0p;
        *(uint32_t*)(g_Yhi + y1 + d) = h1;
        *(uint32_t*)(g_Ylo + y1 + d) = l1p;
    }
}

// ---------------- launch -----------------------------------------------------
extern "C" void kernel_launch(void* const* d_in, const int* in_sizes, int n_in,
                              void* d_out, int out_size) {
    const float* x      = (const float*)d_in[0];
    const float* W_qkv  = (const float*)d_in[1];
    const float* b_qkv  = (const float*)d_in[2];
    const float* W_out  = (const float*)d_in[3];
    const float* b_out  = (const float*)d_in[4];
    const float* w_sur  = (const float*)d_in[5];
    const float* b_sur  = (const float*)d_in[6];
    const float* thresh = (const float*)d_in[7];
    float* out = (float*)d_out;

    __nv_bfloat16 *p_xhi, *p_xlo, *p_Wqt_hi, *p_Wqt_lo;
    __nv_bfloat16 *p_Yhi, *p_Ylo, *p_Wot_hi, *p_Wot_lo;
    cudaGetSymbolAddress((void**)&p_xhi, g_xhi);
    cudaGetSymbolAddress((void**)&p_xlo, g_xlo);
    cudaGetSymbolAddress((void**)&p_Wqt_hi, g_Wqt_hi);
    cudaGetSymbolAddress((void**)&p_Wqt_lo, g_Wqt_lo);
    cudaGetSymbolAddress((void**)&p_Yhi, g_Yhi);
    cudaGetSymbolAddress((void**)&p_Ylo, g_Ylo);
    cudaGetSymbolAddress((void**)&p_Wot_hi, g_Wot_hi);
    cudaGetSymbolAddress((void**)&p_Wot_lo, g_Wot_lo);

    cudaFuncSetAttribute(attn_kernel,
                         cudaFuncAttributeMaxDynamicSharedMemorySize, AT_SMEM);
    cudaFuncSetAttribute(gemm4_kernel<true>,
                         cudaFuncAttributeMaxDynamicSharedMemorySize, G4_SMEM);
    cudaFuncSetAttribute(gemm4_kernel<false>,
                         cudaFuncAttributeMaxDynamicSharedMemorySize, G4_SMEM);

    const int M = B_ * T_;   // 4096

    // 1. fused prep: x spike+split | W_qkv^T split | W_out^T split (one launch)
    prep_all_kernel<<<4608, 256>>>(x, W_qkv, W_out, w_sur, b_sur, thresh,
                                   p_xhi, p_xlo, p_Wqt_hi, p_Wqt_lo,
                                   p_Wot_hi, p_Wot_lo);

    // 2. QKV GEMM with fused Lorentz transform epilogue -> g_{Q,K,V}{hi,lo}
    gemm4_kernel<true><<<dim3(3 * C_ / 128, M / 128), 128, G4_SMEM>>>(
        p_xhi, p_xlo, p_Wqt_hi, p_Wqt_lo, b_qkv, nullptr, M, 3 * C_, C_);

    // 3. tensor-core flash attention
    attn_kernel<<<dim3(T_ / 64, H_, B_), 128, AT_SMEM>>>();

    // 4. out projection
    gemm4_kernel<false><<<dim3(C_ / 128, M / 128), 128, G4_SMEM>>>(
        p_Yhi, p_Ylo, p_Wot_hi, p_Wot_lo, b_out, out, M, C_, C_);
}

// round 15
// speedup vs baseline: 1.1421x; 1.0471x over previous
#include <cuda_runtime.h>
#include <cuda_bf16.h>
#include <math.h>
#include <stdint.h>

#define B_ 4
#define T_ 1024
#define C_ 1024
#define H_ 16
#define D_ 64

// ---------------- scratch (device globals; no allocations allowed) ----------
__device__ float g_spike[B_ * T_];
__device__ int   g_idx[B_][T_];     // compacted spiking token indices per batch
__device__ int   g_cnt[B_];

// transformed Q',K',V as bf16 hi/lo  [BH][T][64]
__device__ __nv_bfloat16 g_Qhi[(size_t)B_ * H_ * T_ * D_];
__device__ __nv_bfloat16 g_Qlo[(size_t)B_ * H_ * T_ * D_];
__device__ __nv_bfloat16 g_Khi[(size_t)B_ * H_ * T_ * D_];
__device__ __nv_bfloat16 g_Klo[(size_t)B_ * H_ * T_ * D_];
__device__ __nv_bfloat16 g_Vhi[(size_t)B_ * H_ * T_ * D_];
__device__ __nv_bfloat16 g_Vlo[(size_t)B_ * H_ * T_ * D_];

// bf16 hi/lo split operands for tensor-core GEMMs
__device__ __nv_bfloat16 g_xhi[(size_t)B_ * T_ * C_];
__device__ __nv_bfloat16 g_xlo[(size_t)B_ * T_ * C_];
__device__ __nv_bfloat16 g_Wqt_hi[(size_t)3 * C_ * C_];    // W_qkv^T [N,K]
__device__ __nv_bfloat16 g_Wqt_lo[(size_t)3 * C_ * C_];
__device__ __nv_bfloat16 g_Yhi[(size_t)B_ * T_ * C_];      // attn out, bf16 hi/lo
__device__ __nv_bfloat16 g_Ylo[(size_t)B_ * T_ * C_];
__device__ __nv_bfloat16 g_Wot_hi[(size_t)C_ * C_];        // W_out^T [N,K]
__device__ __nv_bfloat16 g_Wot_lo[(size_t)C_ * C_];

// ======================= generic-PTX helpers (no 'a' features) ==============
__device__ __forceinline__ uint32_t smem_u32(const void* p) {
    uint32_t a;
    asm("{ .reg .u64 t; cvta.to.shared.u64 t, %1; cvt.u32.u64 %0, t; }"
        : "=r"(a) : "l"(p));
    return a;
}
__device__ __forceinline__ float sqrt_approx(float x) {
    float r;
    asm("sqrt.approx.f32 %0, %1;" : "=f"(r) : "f"(x));
    return r;
}
#define CP16(saddr, gaddr) \
    asm volatile("cp.async.cg.shared.global [%0], [%1], 16;" \
                 :: "r"(saddr), "l"(gaddr))
#define CP_COMMIT() asm volatile("cp.async.commit_group;" ::: "memory")
#define CP_WAIT1()  asm volatile("cp.async.wait_group 1;" ::: "memory")
#define CP_WAIT0()  asm volatile("cp.async.wait_group 0;" ::: "memory")

#define LDSM_X4(r0, r1, r2, r3, addr) \
    asm volatile("ldmatrix.sync.aligned.m8n8.x4.shared.b16 {%0,%1,%2,%3}, [%4];" \
                 : "=r"(r0), "=r"(r1), "=r"(r2), "=r"(r3) : "r"(addr))

#define LDSM_X4_T(r0, r1, r2, r3, addr) \
    asm volatile("ldmatrix.sync.aligned.m8n8.x4.trans.shared.b16 {%0,%1,%2,%3}, [%4];" \
                 : "=r"(r0), "=r"(r1), "=r"(r2), "=r"(r3) : "r"(addr))

#define MMA_BF16(d, a, b0, b1) \
    asm volatile("mma.sync.aligned.m16n8k16.row.col.f32.bf16.bf16.f32 " \
                 "{%0,%1,%2,%3}, {%4,%5,%6,%7}, {%8,%9}, {%0,%1,%2,%3};" \
                 : "+f"((d)[0]), "+f"((d)[1]), "+f"((d)[2]), "+f"((d)[3]) \
                 : "r"((a)[0]), "r"((a)[1]), "r"((a)[2]), "r"((a)[3]), \
                   "r"(b0), "r"(b1))

__device__ __forceinline__ uint32_t pack_bf16(float a, float b) {
    __nv_bfloat162 h = __floats2bfloat162_rn(a, b);
    return *(uint32_t*)&h;
}

// ---------------- fused prep: x | W_qkv^T | W_out^T | Y zero-fill -----------
__device__ __forceinline__ void transpose_tile(
    const float* __restrict__ W, __nv_bfloat16* __restrict__ Thi,
    __nv_bfloat16* __restrict__ Tlo, int K, int N, int k0, int n0,
    int tx, int ty, float (*tile)[33])
{
    #pragma unroll
    for (int j = 0; j < 32; j += 8)
        tile[ty + j][tx] = W[(size_t)(k0 + ty + j) * N + n0 + tx];
    __syncthreads();
    #pragma unroll
    for (int j = 0; j < 32; j += 8) {
        float v = tile[tx][ty + j];
        __nv_bfloat16 h = __float2bfloat16(v);
        __nv_bfloat16 l = __float2bfloat16(v - __bfloat162float(h));
        Thi[(size_t)(n0 + ty + j) * K + k0 + tx] = h;
        Tlo[(size_t)(n0 + ty + j) * K + k0 + tx] = l;
    }
}

// grid: [0,512) x-prep | [512,3584) W_qkv | [3584,4608) W_out | [4608,5120) Y zero
__global__ void prep_all_kernel(const float* __restrict__ x,
                                const float* __restrict__ W_qkv,
                                const float* __restrict__ W_out,
                                const float* __restrict__ w_sur,
                                const float* __restrict__ b_sur,
                                const float* __restrict__ threshold,
                                __nv_bfloat16* __restrict__ xhi,
                                __nv_bfloat16* __restrict__ xlo,
                                __nv_bfloat16* __restrict__ Wqt_hi,
                                __nv_bfloat16* __restrict__ Wqt_lo,
                                __nv_bfloat16* __restrict__ Wot_hi,
                                __nv_bfloat16* __restrict__ Wot_lo) {
    __shared__ float tile[32][33];
    const int bid = blockIdx.x;
    const int tid = threadIdx.x;

    if (bid < 512) {
        // ---- x prep: one warp per row; spike dot + bf16 hi/lo split ----
        const int row = bid * 8 + (tid >> 5);
        const int lane = tid & 31;
        const float* xr = x + (size_t)row * C_;
        float s = 0.f;
        #pragma unroll
        for (int i = 0; i < 8; i++) {
            const int e = lane * 4 + i * 128;
            float4 v = *(const float4*)(xr + e);
            float4 w = *(const float4*)(w_sur + e);
            s += v.x * w.x + v.y * w.y + v.z * w.z + v.w * w.w;

            __nv_bfloat16 h0 = __float2bfloat16(v.x);
            __nv_bfloat16 h1 = __float2bfloat16(v.y);
            __nv_bfloat16 h2 = __float2bfloat16(v.z);
            __nv_bfloat16 h3 = __float2bfloat16(v.w);
            __nv_bfloat162* hp = (__nv_bfloat162*)(xhi + (size_t)row * C_ + e);
            __nv_bfloat162* lp = (__nv_bfloat162*)(xlo + (size_t)row * C_ + e);
            hp[0] = __nv_bfloat162(h0, h1);
            hp[1] = __nv_bfloat162(h2, h3);
            lp[0] = __nv_bfloat162(__float2bfloat16(v.x - __bfloat162float(h0)),
                                   __float2bfloat16(v.y - __bfloat162float(h1)));
            lp[1] = __nv_bfloat162(__float2bfloat16(v.z - __bfloat162float(h2)),
                                   __float2bfloat16(v.w - __bfloat162float(h3)));
        }
        #pragma unroll
        for (int m = 16; m; m >>= 1) s += __shfl_xor_sync(0xffffffffu, s, m);
        if (lane == 0) {
            float z = s + b_sur[0];
            float imp = 1.f / (1.f + expf(-z));
            g_spike[row] = (imp > threshold[0]) ? 1.f : 0.f;
        }
    } else if (bid < 3584) {
        const int t = bid - 512;                 // W_qkv: N=3072 (96 tiles), K=1024
        transpose_tile(W_qkv, Wqt_hi, Wqt_lo, C_, 3 * C_,
                       (t / 96) * 32, (t % 96) * 32, tid & 31, tid >> 5, tile);
    } else if (bid < 4608) {
        const int t = bid - 3584;                // W_out: N=1024 (32), K=1024
        transpose_tile(W_out, Wot_hi, Wot_lo, C_, C_,
                       (t / 32) * 32, (t % 32) * 32, tid & 31, tid >> 5, tile);
    } else {
        // ---- Y zero-fill: one warp per row (non-spiking rows stay 0) ----
        const int row = (bid - 4608) * 8 + (tid >> 5);
        const int lane = tid & 31;
        uint4 z = make_uint4(0, 0, 0, 0);
        uint4* yh = (uint4*)(g_Yhi + (size_t)row * C_);
        uint4* yl = (uint4*)(g_Ylo + (size_t)row * C_);
        #pragma unroll
        for (int i = 0; i < 4; i++) {
            yh[lane + i * 32] = z;
            yl[lane + i * 32] = z;
        }
    }
}

// ---------------- spike compaction: one warp per batch ----------------------
__global__ void compact_kernel() {
    const int b = threadIdx.x >> 5;
    const int lane = threadIdx.x & 31;
    int base = 0;
    for (int c = 0; c < 32; c++) {
        const int t = c * 32 + lane;
        const bool sp = g_spike[b * T_ + t] > 0.5f;
        const unsigned m = __ballot_sync(0xffffffffu, sp);
        const int pos = base + __popc(m & ((1u << lane) - 1u));
        if (sp) g_idx[b][pos] = t;
        base += __popc(m);
    }
    if (lane == 0) g_cnt[b] = base;
}

// ---------------- mma.sync bf16x3 GEMM, 4 warps x (64x64) warp tiles --------
#define G4_STAGE 32768
#define G4_SMEM (3 * G4_STAGE)
#define G4_TILE 8192

template<bool FUSE>
__global__ __launch_bounds__(128) void gemm4_kernel(
    const __nv_bfloat16* __restrict__ Ahi, const __nv_bfloat16* __restrict__ Alo,
    const __nv_bfloat16* __restrict__ Bhi, const __nv_bfloat16* __restrict__ Blo,
    const float* __restrict__ bias, float* __restrict__ Cmat,
    int M, int N, int K)
{
    extern __shared__ char sm[];
    const uint32_t sbase = smem_u32(sm);

    const int tid  = threadIdx.x;
    const int wid  = tid >> 5;
    const int lane = tid & 31;
    const int m0 = blockIdx.y * 128;
    const int n0 = blockIdx.x * 128;
    const int wm = wid & 1;          // 64-row slab
    const int wn = wid >> 1;         // 64-col slab

    uint32_t so[4];
    const __nv_bfloat16 *pA0[4], *pA1[4], *pB0[4], *pB1[4];
    #pragma unroll
    for (int it = 0; it < 4; it++) {
        const int sub = tid + it * 128;
        const int row = sub >> 2, col = sub & 3;
        so[it] = (uint32_t)row * 64 + (uint32_t)((col ^ ((row >> 1) & 3)) * 16);
        pA0[it] = Ahi + (size_t)(m0 + row) * K + col * 8;
        pA1[it] = Alo + (size_t)(m0 + row) * K + col * 8;
        pB0[it] = Bhi + (size_t)(n0 + row) * K + col * 8;
        pB1[it] = Blo + (size_t)(n0 + row) * K + col * 8;
    }

    float acc[4][8][4];
    #pragma unroll
    for (int i = 0; i < 4; i++)
        #pragma unroll
        for (int j = 0; j < 8; j++)
            #pragma unroll
            for (int c = 0; c < 4; c++) acc[i][j][c] = 0.f;

    const int nch = K >> 5;
    const int lrow = lane & 15;
    const int kc   = lane >> 4;

    #pragma unroll
    for (int s = 0; s < 2; s++) {
        const uint32_t sb = sbase + (uint32_t)s * G4_STAGE;
        const int kb = s << 5;
        #pragma unroll
        for (int it = 0; it < 4; it++) {
            CP16(sb + 0 * G4_TILE + so[it], pA0[it] + kb);
            CP16(sb + 1 * G4_TILE + so[it], pA1[it] + kb);
            CP16(sb + 2 * G4_TILE + so[it], pB0[it] + kb);
            CP16(sb + 3 * G4_TILE + so[it], pB1[it] + kb);
        }
        CP_COMMIT();
    }

    for (int ch = 0; ch < nch; ch++) {
        CP_WAIT1();
        __syncthreads();

        if (ch + 2 < nch) {
            const uint32_t sb = sbase + (uint32_t)((ch + 2) % 3) * G4_STAGE;
            const int kb = (ch + 2) << 5;
            #pragma unroll
            for (int it = 0; it < 4; it++) {
                CP16(sb + 0 * G4_TILE + so[it], pA0[it] + kb);
                CP16(sb + 1 * G4_TILE + so[it], pA1[it] + kb);
                CP16(sb + 2 * G4_TILE + so[it], pB0[it] + kb);
                CP16(sb + 3 * G4_TILE + so[it], pB1[it] + kb);
            }
        }
        CP_COMMIT();

        const uint32_t st = sbase + (uint32_t)(ch % 3) * G4_STAGE;

        #pragma unroll
        for (int kk = 0; kk < 2; kk++) {
            const int chunk = kk * 2 + kc;
            uint32_t ahi[4][4], alo[4][4];
            #pragma unroll
            for (int mi = 0; mi < 4; mi++) {
                const int r = wm * 64 + mi * 16 + lrow;
                const uint32_t off = (uint32_t)r * 64 +
                    (uint32_t)((chunk ^ ((r >> 1) & 3)) * 16);
                LDSM_X4(ahi[mi][0], ahi[mi][1], ahi[mi][2], ahi[mi][3],
                        st + 0 * G4_TILE + off);
                LDSM_X4(alo[mi][0], alo[mi][1], alo[mi][2], alo[mi][3],
                        st + 1 * G4_TILE + off);
            }
            #pragma unroll
            for (int g = 0; g < 4; g++) {
                const int r = wn * 64 + g * 16 + lrow;
                const uint32_t off = (uint32_t)r * 64 +
                    (uint32_t)((chunk ^ ((r >> 1) & 3)) * 16);
                uint32_t bh[4], bl[4];
                LDSM_X4(bh[0], bh[1], bh[2], bh[3], st + 2 * G4_TILE + off);
                LDSM_X4(bl[0], bl[1], bl[2], bl[3], st + 3 * G4_TILE + off);
                #pragma unroll
                for (int mi = 0; mi < 4; mi++) {
                    MMA_BF16(acc[mi][g * 2 + 0], ahi[mi], bh[0], bh[2]);
                    MMA_BF16(acc[mi][g * 2 + 0], ahi[mi], bl[0], bl[2]);
                    MMA_BF16(acc[mi][g * 2 + 0], alo[mi], bh[0], bh[2]);
                    MMA_BF16(acc[mi][g * 2 + 1], ahi[mi], bh[1], bh[3]);
                    MMA_BF16(acc[mi][g * 2 + 1], ahi[mi], bl[1], bl[3]);
                    MMA_BF16(acc[mi][g * 2 + 1], alo[mi], bh[1], bh[3]);
                }
            }
        }
    }

    const int orow = lane >> 2;          // row-in-16 (0..7)
    const int ocol = (lane & 3) * 2;     // col pair base within 8

    if constexpr (!FUSE) {
        #pragma unroll
        for (int mi = 0; mi < 4; mi++) {
            const int r0 = m0 + wm * 64 + mi * 16 + orow;
            #pragma unroll
            for (int ni = 0; ni < 8; ni++) {
                const int c = n0 + wn * 64 + ni * 8 + ocol;
                const float b0 = bias[c], b1 = bias[c + 1];
                float2 v0 = make_float2(acc[mi][ni][0] + b0, acc[mi][ni][1] + b1);
                float2 v1 = make_float2(acc[mi][ni][2] + b0, acc[mi][ni][3] + b1);
                *(float2*)(Cmat + (size_t)r0 * N + c)       = v0;
                *(float2*)(Cmat + (size_t)(r0 + 8) * N + c) = v1;
            }
        }
    } else {
        const int colbase = n0 + wn * 64;          // 64-aligned -> one head
        const int type = colbase >> 10;            // 0=Q, 1=K, 2=V
        const int head = (colbase & 1023) >> 6;
        __nv_bfloat16* ghi = (type == 0) ? g_Qhi : (type == 1) ? g_Khi : g_Vhi;
        __nv_bfloat16* glo = (type == 0) ? g_Qlo : (type == 1) ? g_Klo : g_Vlo;
        const float sgn = (type == 1) ? -1.f : 1.f;

        float bs[8][2];
        #pragma unroll
        for (int ni = 0; ni < 8; ni++) {
            bs[ni][0] = bias[colbase + ni * 8 + ocol];
            bs[ni][1] = bias[colbase + ni * 8 + ocol + 1];
        }

        #pragma unroll
        for (int mi = 0; mi < 4; mi++) {
            #pragma unroll
            for (int hh = 0; hh < 2; hh++) {
                const int r = m0 + wm * 64 + mi * 16 + orow + hh * 8;
                const int batch = r >> 10, t = r & 1023;
                const size_t ob = ((size_t)(batch * H_ + head) * T_ + t) * D_;

                float v[8][2];
                float ss = 0.f;
                #pragma unroll
                for (int ni = 0; ni < 8; ni++) {
                    v[ni][0] = acc[mi][ni][hh * 2 + 0] + bs[ni][0];
                    v[ni][1] = acc[mi][ni][hh * 2 + 1] + bs[ni][1];
                    ss += v[ni][0] * v[ni][0] + v[ni][1] * v[ni][1];
                }

                if (type != 2) {
                    ss += __shfl_xor_sync(0xffffffffu, ss, 1);
                    ss += __shfl_xor_sync(0xffffffffu, ss, 2);
                    float u0 = __shfl_sync(0xffffffffu, v[0][0], lane & ~3u, 32);
                    float mink = ss - 2.f * u0 * u0;
                    float nn = sqrtf(fmaxf(mink, 1e-8f));
                    float e = __expf(nn), ei = 1.f / e;
                    float tme = 0.5f * (e + ei);
                    float coef = sgn * (e - ei) / (2.f * nn);
                    #pragma unroll
                    for (int ni = 0; ni < 8; ni++) {
                        v[ni][0] *= coef;
                        v[ni][1] *= coef;
                    }
                    if ((lane & 3) == 0) v[0][0] = tme;   // d==0 -> time comp
                }

                #pragma unroll
                for (int ni = 0; ni < 8; ni++) {
                    const int d = ni * 8 + ocol;
                    uint32_t hp = pack_bf16(v[ni][0], v[ni][1]);
                    __nv_bfloat162 hv = *(__nv_bfloat162*)&hp;
                    uint32_t lp = pack_bf16(v[ni][0] - __low2float(hv),
                                            v[ni][1] - __high2float(hv));
                    *(uint32_t*)(ghi + ob + d) = hp;
                    *(uint32_t*)(glo + ob + d) = lp;
                }
            }
        }
    }
}

// ---------------- tensor-core flash attention (bf16x3, spike-compacted) -----
// Only spiking q-rows (g_idx[b], count g_cnt[b]) are processed; non-spiking
// Y rows stay zero (prep zero-fill). Core loop identical to the R14 kernel.
#define AT_SMEM 65536
#define SWO(row, ch) ((uint32_t)(row) * 128u + (uint32_t)(((ch) ^ (((row) >> 1) & 3)) * 16))

__global__ __launch_bounds__(128) void attn_kernel() {
    const int b  = blockIdx.z;
    const int cnt = g_cnt[b];
    const int ntiles = (cnt + 63) >> 6;
    if ((int)blockIdx.x >= ntiles) return;
    const int ti = ntiles - 1 - (int)blockIdx.x;   // heavy CTAs first
    const int i0 = ti * 64;

    extern __shared__ char sm[];
    const uint32_t sb = smem_u32(sm);
    const int tid = threadIdx.x;
    const int wid = tid >> 5;
    const int lane = tid & 31;
    const int h  = blockIdx.y;
    const int bh = b * H_ + h;
    const size_t gb = (size_t)bh * T_ * D_;
    const int* idx = g_idx[b];
    const int cm1 = cnt - 1;

    const int lrow  = lane & 15;
    const int khalf = lane >> 4;

    // ---- prologue: gathered Q -> [32K,48K), K/V tile 0 -> buf0 [0,32K) ----
    #pragma unroll
    for (int i = 0; i < 8; i++) {
        const int arr = i >> 2;
        const int sub = tid + (i & 3) * 128;
        const int row = sub >> 3, ch = sub & 7;
        const int tq = idx[min(i0 + row, cm1)];
        const __nv_bfloat16* g = arr ? g_Qlo : g_Qhi;
        CP16(sb + 32768u + (uint32_t)arr * 8192u + SWO(row, ch),
             g + gb + (size_t)tq * D_ + ch * 8);
    }
    #pragma unroll
    for (int i = 0; i < 16; i++) {
        const int arr = i >> 2;
        const int sub = tid + (i & 3) * 128;
        const int row = sub >> 3, ch = sub & 7;
        const __nv_bfloat16* g = (arr == 0) ? g_Khi : (arr == 1) ? g_Klo
                               : (arr == 2) ? g_Vhi : g_Vlo;
        CP16(sb + (uint32_t)arr * 8192u + SWO(row, ch),
             g + gb + (size_t)row * D_ + ch * 8);
    }
    CP_COMMIT();

    float O[8][4];
    #pragma unroll
    for (int i = 0; i < 8; i++)
        #pragma unroll
        for (int c = 0; c < 4; c++) O[i][c] = 0.f;
    float m0 = -1e30f, m1 = -1e30f, l0 = 0.f, l1 = 0.f;
    uint32_t ahi[4][4], alo[4][4];

    const int rq = lane >> 2;
    const int cq = (lane & 3) * 2;
    const int lr0 = i0 + wid * 16 + rq;        // compacted positions
    const int lr1 = lr0 + 8;
    const int grow0 = idx[min(lr0, cm1)];      // actual token indices
    const int grow1 = idx[min(lr1, cm1)];
    const bool v0 = (lr0 <= cm1);
    const bool v1 = (lr1 <= cm1);

    const int tjmax = idx[min(i0 + 63, cm1)] >> 6;   // rows sorted ascending

    for (int tj = 0; tj <= tjmax; tj++) {
        CP_WAIT0();            // tile tj (and, for tj==0, Q) landed
        __syncthreads();

        if (tj == 0) {
            #pragma unroll
            for (int kc = 0; kc < 4; kc++) {
                const int r = wid * 16 + lrow;
                const uint32_t off = SWO(r, kc * 2 + khalf);
                LDSM_X4(ahi[kc][0], ahi[kc][1], ahi[kc][2], ahi[kc][3],
                        sb + 32768u + off);
                LDSM_X4(alo[kc][0], alo[kc][1], alo[kc][2], alo[kc][3],
                        sb + 40960u + off);
            }
            __syncthreads();   // Q reads done before buf1 prefetch overwrites
        }

        if (tj < tjmax) {      // prefetch tile tj+1 into the other buffer
            const uint32_t dst = sb + (uint32_t)((tj + 1) & 1) * 32768u;
            const size_t src = gb + (size_t)(tj + 1) * 64 * D_;
            #pragma unroll
            for (int i = 0; i < 16; i++) {
                const int arr = i >> 2;
                const int sub = tid + (i & 3) * 128;
                const int row = sub >> 3, ch = sub & 7;
                const __nv_bfloat16* g = (arr == 0) ? g_Khi : (arr == 1) ? g_Klo
                                       : (arr == 2) ? g_Vhi : g_Vlo;
                CP16(dst + (uint32_t)arr * 8192u + SWO(row, ch),
                     g + src + (size_t)row * D_ + ch * 8);
            }
            CP_COMMIT();
        }

        const uint32_t kbuf = sb + (uint32_t)(tj & 1) * 32768u;

        // ---- S = Q' K'^T (bf16x3) ----
        float acc[8][4];
        #pragma unroll
        for (int i = 0; i < 8; i++)
            #pragma unroll
            for (int c = 0; c < 4; c++) acc[i][c] = 0.f;

        #pragma unroll
        for (int kc = 0; kc < 4; kc++) {
            uint32_t bh4[4][4], bl4[4][4];
            #pragma unroll
            for (int g = 0; g < 4; g++) {
                const int r = g * 16 + lrow;
                const uint32_t off = SWO(r, kc * 2 + khalf);
                LDSM_X4(bh4[g][0], bh4[g][1], bh4[g][2], bh4[g][3], kbuf + off);
                LDSM_X4(bl4[g][0], bl4[g][1], bl4[g][2], bl4[g][3],
                        kbuf + 8192u + off);
            }
            #pragma unroll
            for (int ni = 0; ni < 8; ni++) {
                const int g = ni >> 1, o = ni & 1;
                MMA_BF16(acc[ni], ahi[kc], bh4[g][o], bh4[g][2 + o]);
                MMA_BF16(acc[ni], ahi[kc], bl4[g][o], bl4[g][2 + o]);
                MMA_BF16(acc[ni], alo[kc], bh4[g][o], bh4[g][2 + o]);
            }
        }

        // ---- Lorentz transform (approx sqrt) + causal mask ----
        const int j0 = tj * 64;
        #pragma unroll
        for (int ni = 0; ni < 8; ni++) {
            #pragma unroll
            for (int c = 0; c < 4; c++) {
                const int col = j0 + ni * 8 + cq + (c & 1);
                const int grow = (c < 2) ? grow0 : grow1;
                float x = fmaxf(acc[ni][c], 1.0f + 1e-7f);
                float dd = __logf(x + sqrt_approx(fmaxf(x * x - 1.f, 0.f)));
                float s = -dd * dd * 0.125f;
                acc[ni][c] = (col > grow) ? -1e30f : s;
            }
        }

        // ---- online softmax (rows grow0 / grow1, quad = 4 lanes) ----
        {
            float mx = -1e30f;
            #pragma unroll
            for (int ni = 0; ni < 8; ni++)
                mx = fmaxf(mx, fmaxf(acc[ni][0], acc[ni][1]));
            mx = fmaxf(mx, __shfl_xor_sync(0xffffffffu, mx, 1));
            mx = fmaxf(mx, __shfl_xor_sync(0xffffffffu, mx, 2));
            float mnew = fmaxf(m0, mx);
            float es = __expf(m0 - mnew);
            l0 *= es;
            #pragma unroll
            for (int ni = 0; ni < 8; ni++) { O[ni][0] *= es; O[ni][1] *= es; }
            float rs = 0.f;
            #pragma unroll
            for (int ni = 0; ni < 8; ni++) {
                float p0 = __expf(acc[ni][0] - mnew);
                float p1 = __expf(acc[ni][1] - mnew);
                acc[ni][0] = p0; acc[ni][1] = p1; rs += p0 + p1;
            }
            rs += __shfl_xor_sync(0xffffffffu, rs, 1);
            rs += __shfl_xor_sync(0xffffffffu, rs, 2);
            l0 += rs; m0 = mnew;
        }
        {
            float mx = -1e30f;
            #pragma unroll
            for (int ni = 0; ni < 8; ni++)
                mx = fmaxf(mx, fmaxf(acc[ni][2], acc[ni][3]));
            mx = fmaxf(mx, __shfl_xor_sync(0xffffffffu, mx, 1));
            mx = fmaxf(mx, __shfl_xor_sync(0xffffffffu, mx, 2));
            float mnew = fmaxf(m1, mx);
            float es = __expf(m1 - mnew);
            l1 *= es;
            #pragma unroll
            for (int ni = 0; ni < 8; ni++) { O[ni][2] *= es; O[ni][3] *= es; }
            float rs = 0.f;
            #pragma unroll
            for (int ni = 0; ni < 8; ni++) {
                float p0 = __expf(acc[ni][2] - mnew);
                float p1 = __expf(acc[ni][3] - mnew);
                acc[ni][2] = p0; acc[ni][3] = p1; rs += p0 + p1;
            }
            rs += __shfl_xor_sync(0xffffffffu, rs, 1);
            rs += __shfl_xor_sync(0xffffffffu, rs, 2);
            l1 += rs; m1 = mnew;
        }

        // ---- PV: O += P V (bf16x3, P packed in registers) ----
        const uint32_t vbuf = kbuf + 16384u;
        #pragma unroll
        for (int kc = 0; kc < 4; kc++) {
            uint32_t ph[4], pl[4];
            #pragma unroll
            for (int q = 0; q < 4; q++) {
                const int ni = 2 * kc + (q >> 1);
                const int c0 = (q & 1) * 2;
                float a = acc[ni][c0], bb = acc[ni][c0 + 1];
                uint32_t hp = pack_bf16(a, bb);
                __nv_bfloat162 hv = *(__nv_bfloat162*)&hp;
                const int idx2 = (q & 1) + (q >> 1) * 2;
                ph[idx2] = hp;
                pl[idx2] = pack_bf16(a - __low2float(hv), bb - __high2float(hv));
            }
            #pragma unroll
            for (int g = 0; g < 4; g++) {
                const int r = kc * 16 + ((lane >> 3) & 1) * 8 + (lane & 7);
                const uint32_t off = SWO(r, g * 2 + khalf);
                uint32_t vh[4], vl[4];
                LDSM_X4_T(vh[0], vh[1], vh[2], vh[3], vbuf + off);
                LDSM_X4_T(vl[0], vl[1], vl[2], vl[3], vbuf + 8192u + off);
                MMA_BF16(O[g * 2],     ph, vh[0], vh[1]);
                MMA_BF16(O[g * 2],     ph, vl[0], vl[1]);
                MMA_BF16(O[g * 2],     pl, vh[0], vh[1]);
                MMA_BF16(O[g * 2 + 1], ph, vh[2], vh[3]);
                MMA_BF16(O[g * 2 + 1], ph, vl[2], vl[3]);
                MMA_BF16(O[g * 2 + 1], pl, vh[2], vh[3]);
            }
        }
        // no trailing sync: next iteration's top-of-loop barrier protects reuse
    }

    // ---- epilogue: write Yhi/Ylo bf16 (spiking rows only; spike==1) ----
    const float inv0 = 1.f / l0;
    const float inv1 = 1.f / l1;
    const size_t y0 = ((size_t)(b * T_ + grow0)) * C_ + h * D_;
    const size_t y1 = ((size_t)(b * T_ + grow1)) * C_ + h * D_;
    #pragma unroll
    for (int ni = 0; ni < 8; ni++) {
        const int d = ni * 8 + cq;
        if (v0) {
            float a0 = O[ni][0] * inv0, a1 = O[ni][1] * inv0;
            uint32_t h0 = pack_bf16(a0, a1);
            __nv_bfloat162 hv0 = *(__nv_bfloat162*)&h0;
            uint32_t l0p = pack_bf16(a0 - __low2float(hv0), a1 - __high2float(hv0));
            *(uint32_t*)(g_Yhi + y0 + d) = h0;
            *(uint32_t*)(g_Ylo + y0 + d) = l0p;
        }
        if (v1) {
            float b0 = O[ni][2] * inv1, b1 = O[ni][3] * inv1;
            uint32_t h1 = pack_bf16(b0, b1);
            __nv_bfloat162 hv1 = *(__nv_bfloat162*)&h1;
            uint32_t l1p = pack_bf16(b0 - __low2float(hv1), b1 - __high2float(hv1));
            *(uint32_t*)(g_Yhi + y1 + d) = h1;
            *(uint32_t*)(g_Ylo + y1 + d) = l1p;
        }
    }
}

// ---------------- launch -----------------------------------------------------
extern "C" void kernel_launch(void* const* d_in, const int* in_sizes, int n_in,
                              void* d_out, int out_size) {
    const float* x      = (const float*)d_in[0];
    const float* W_qkv  = (const float*)d_in[1];
    const float* b_qkv  = (const float*)d_in[2];
    const float* W_out  = (const float*)d_in[3];
    const float* b_out  = (const float*)d_in[4];
    const float* w_sur  = (const float*)d_in[5];
    const float* b_sur  = (const float*)d_in[6];
    const float* thresh = (const float*)d_in[7];
    float* out = (float*)d_out;

    __nv_bfloat16 *p_xhi, *p_xlo, *p_Wqt_hi, *p_Wqt_lo;
    __nv_bfloat16 *p_Yhi, *p_Ylo, *p_Wot_hi, *p_Wot_lo;
    cudaGetSymbolAddress((void**)&p_xhi, g_xhi);
    cudaGetSymbolAddress((void**)&p_xlo, g_xlo);
    cudaGetSymbolAddress((void**)&p_Wqt_hi, g_Wqt_hi);
    cudaGetSymbolAddress((void**)&p_Wqt_lo, g_Wqt_lo);
    cudaGetSymbolAddress((void**)&p_Yhi, g_Yhi);
    cudaGetSymbolAddress((void**)&p_Ylo, g_Ylo);
    cudaGetSymbolAddress((void**)&p_Wot_hi, g_Wot_hi);
    cudaGetSymbolAddress((void**)&p_Wot_lo, g_Wot_lo);

    cudaFuncSetAttribute(attn_kernel,
                         cudaFuncAttributeMaxDynamicSharedMemorySize, AT_SMEM);
    cudaFuncSetAttribute(gemm4_kernel<true>,
                         cudaFuncAttributeMaxDynamicSharedMemorySize, G4_SMEM);
    cudaFuncSetAttribute(gemm4_kernel<false>,
                         cudaFuncAttributeMaxDynamicSharedMemorySize, G4_SMEM);

    const int M = B_ * T_;   // 4096

    // 1. fused prep: x spike+split | W^T splits | Y zero-fill (one launch)
    prep_all_kernel<<<5120, 256>>>(x, W_qkv, W_out, w_sur, b_sur, thresh,
                                   p_xhi, p_xlo, p_Wqt_hi, p_Wqt_lo,
                                   p_Wot_hi, p_Wot_lo);

    // 2. spike compaction (1 warp per batch)
    compact_kernel<<<1, 128>>>();

    // 3. QKV GEMM with fused Lorentz transform epilogue -> g_{Q,K,V}{hi,lo}
    gemm4_kernel<true><<<dim3(3 * C_ / 128, M / 128), 128, G4_SMEM>>>(
        p_xhi, p_xlo, p_Wqt_hi, p_Wqt_lo, b_qkv, nullptr, M, 3 * C_, C_);

    // 4. spike-compacted tensor-core flash attention
    attn_kernel<<<dim3(T_ / 64, H_, B_), 128, AT_SMEM>>>();

    // 5. out projection (zero Y rows -> exact bias rows)
    gemm4_kernel<false><<<dim3(C_ / 128, M / 128), 128, G4_SMEM>>>(
        p_Yhi, p_Ylo, p_Wot_hi, p_Wot_lo, b_out, out, M, C_, C_);
}

// round 16
// speedup vs baseline: 1.2279x; 1.0751x over previous
#include <cuda_runtime.h>
#include <cuda_bf16.h>
#include <math.h>
#include <stdint.h>

#define B_ 4
#define T_ 1024
#define C_ 1024
#define H_ 16
#define D_ 64

// ---------------- scratch (device globals; no allocations allowed) ----------
__device__ float g_spike[B_ * T_];
__device__ int   g_idx[B_][T_];     // compacted spiking token indices per batch
__device__ int   g_cnt[B_];
__device__ int   g_gidx[B_ * T_];   // global compacted spiking rows (b*T+t)
__device__ int   g_total;

// transformed Q',K',V as bf16 hi/lo  [BH][T][64]
__device__ __nv_bfloat16 g_Qhi[(size_t)B_ * H_ * T_ * D_];
__device__ __nv_bfloat16 g_Qlo[(size_t)B_ * H_ * T_ * D_];
__device__ __nv_bfloat16 g_Khi[(size_t)B_ * H_ * T_ * D_];
__device__ __nv_bfloat16 g_Klo[(size_t)B_ * H_ * T_ * D_];
__device__ __nv_bfloat16 g_Vhi[(size_t)B_ * H_ * T_ * D_];
__device__ __nv_bfloat16 g_Vlo[(size_t)B_ * H_ * T_ * D_];

// bf16 hi/lo split operands for tensor-core GEMMs
__device__ __nv_bfloat16 g_xhi[(size_t)B_ * T_ * C_];
__device__ __nv_bfloat16 g_xlo[(size_t)B_ * T_ * C_];
__device__ __nv_bfloat16 g_Wqt_hi[(size_t)3 * C_ * C_];    // W_qkv^T [N,K]
__device__ __nv_bfloat16 g_Wqt_lo[(size_t)3 * C_ * C_];
__device__ __nv_bfloat16 g_Yhi[(size_t)B_ * T_ * C_];      // attn out, bf16 hi/lo
__device__ __nv_bfloat16 g_Ylo[(size_t)B_ * T_ * C_];
__device__ __nv_bfloat16 g_Wot_hi[(size_t)C_ * C_];        // W_out^T [N,K]
__device__ __nv_bfloat16 g_Wot_lo[(size_t)C_ * C_];

// ======================= generic-PTX helpers (no 'a' features) ==============
__device__ __forceinline__ uint32_t smem_u32(const void* p) {
    uint32_t a;
    asm("{ .reg .u64 t; cvta.to.shared.u64 t, %1; cvt.u32.u64 %0, t; }"
        : "=r"(a) : "l"(p));
    return a;
}
__device__ __forceinline__ float sqrt_approx(float x) {
    float r;
    asm("sqrt.approx.f32 %0, %1;" : "=f"(r) : "f"(x));
    return r;
}
#define CP16(saddr, gaddr) \
    asm volatile("cp.async.cg.shared.global [%0], [%1], 16;" \
                 :: "r"(saddr), "l"(gaddr))
#define CP_COMMIT() asm volatile("cp.async.commit_group;" ::: "memory")
#define CP_WAIT1()  asm volatile("cp.async.wait_group 1;" ::: "memory")
#define CP_WAIT0()  asm volatile("cp.async.wait_group 0;" ::: "memory")

#define LDSM_X4(r0, r1, r2, r3, addr) \
    asm volatile("ldmatrix.sync.aligned.m8n8.x4.shared.b16 {%0,%1,%2,%3}, [%4];" \
                 : "=r"(r0), "=r"(r1), "=r"(r2), "=r"(r3) : "r"(addr))

#define LDSM_X4_T(r0, r1, r2, r3, addr) \
    asm volatile("ldmatrix.sync.aligned.m8n8.x4.trans.shared.b16 {%0,%1,%2,%3}, [%4];" \
                 : "=r"(r0), "=r"(r1), "=r"(r2), "=r"(r3) : "r"(addr))

#define MMA_BF16(d, a, b0, b1) \
    asm volatile("mma.sync.aligned.m16n8k16.row.col.f32.bf16.bf16.f32 " \
                 "{%0,%1,%2,%3}, {%4,%5,%6,%7}, {%8,%9}, {%0,%1,%2,%3};" \
                 : "+f"((d)[0]), "+f"((d)[1]), "+f"((d)[2]), "+f"((d)[3]) \
                 : "r"((a)[0]), "r"((a)[1]), "r"((a)[2]), "r"((a)[3]), \
                   "r"(b0), "r"(b1))

__device__ __forceinline__ uint32_t pack_bf16(float a, float b) {
    __nv_bfloat162 h = __floats2bfloat162_rn(a, b);
    return *(uint32_t*)&h;
}

// ---------------- fused prep: x | W_qkv^T | W_out^T | out bias-fill ---------
__device__ __forceinline__ void transpose_tile(
    const float* __restrict__ W, __nv_bfloat16* __restrict__ Thi,
    __nv_bfloat16* __restrict__ Tlo, int K, int N, int k0, int n0,
    int tx, int ty, float (*tile)[33])
{
    #pragma unroll
    for (int j = 0; j < 32; j += 8)
        tile[ty + j][tx] = W[(size_t)(k0 + ty + j) * N + n0 + tx];
    __syncthreads();
    #pragma unroll
    for (int j = 0; j < 32; j += 8) {
        float v = tile[tx][ty + j];
        __nv_bfloat16 h = __float2bfloat16(v);
        __nv_bfloat16 l = __float2bfloat16(v - __bfloat162float(h));
        Thi[(size_t)(n0 + ty + j) * K + k0 + tx] = h;
        Tlo[(size_t)(n0 + ty + j) * K + k0 + tx] = l;
    }
}

// grid: [0,512) x-prep | [512,3584) W_qkv | [3584,4608) W_out | [4608,5120) out=b
__global__ void prep_all_kernel(const float* __restrict__ x,
                                const float* __restrict__ W_qkv,
                                const float* __restrict__ W_out,
                                const float* __restrict__ w_sur,
                                const float* __restrict__ b_sur,
                                const float* __restrict__ threshold,
                                const float* __restrict__ b_out,
                                float* __restrict__ out,
                                __nv_bfloat16* __restrict__ xhi,
                                __nv_bfloat16* __restrict__ xlo,
                                __nv_bfloat16* __restrict__ Wqt_hi,
                                __nv_bfloat16* __restrict__ Wqt_lo,
                                __nv_bfloat16* __restrict__ Wot_hi,
                                __nv_bfloat16* __restrict__ Wot_lo) {
    __shared__ float tile[32][33];
    const int bid = blockIdx.x;
    const int tid = threadIdx.x;

    if (bid < 512) {
        // ---- x prep: one warp per row; spike dot + bf16 hi/lo split ----
        const int row = bid * 8 + (tid >> 5);
        const int lane = tid & 31;
        const float* xr = x + (size_t)row * C_;
        float s = 0.f;
        #pragma unroll
        for (int i = 0; i < 8; i++) {
            const int e = lane * 4 + i * 128;
            float4 v = *(const float4*)(xr + e);
            float4 w = *(const float4*)(w_sur + e);
            s += v.x * w.x + v.y * w.y + v.z * w.z + v.w * w.w;

            __nv_bfloat16 h0 = __float2bfloat16(v.x);
            __nv_bfloat16 h1 = __float2bfloat16(v.y);
            __nv_bfloat16 h2 = __float2bfloat16(v.z);
            __nv_bfloat16 h3 = __float2bfloat16(v.w);
            __nv_bfloat162* hp = (__nv_bfloat162*)(xhi + (size_t)row * C_ + e);
            __nv_bfloat162* lp = (__nv_bfloat162*)(xlo + (size_t)row * C_ + e);
            hp[0] = __nv_bfloat162(h0, h1);
            hp[1] = __nv_bfloat162(h2, h3);
            lp[0] = __nv_bfloat162(__float2bfloat16(v.x - __bfloat162float(h0)),
                                   __float2bfloat16(v.y - __bfloat162float(h1)));
            lp[1] = __nv_bfloat162(__float2bfloat16(v.z - __bfloat162float(h2)),
                                   __float2bfloat16(v.w - __bfloat162float(h3)));
        }
        #pragma unroll
        for (int m = 16; m; m >>= 1) s += __shfl_xor_sync(0xffffffffu, s, m);
        if (lane == 0) {
            float z = s + b_sur[0];
            float imp = 1.f / (1.f + expf(-z));
            g_spike[row] = (imp > threshold[0]) ? 1.f : 0.f;
        }
    } else if (bid < 3584) {
        const int t = bid - 512;                 // W_qkv: N=3072 (96 tiles), K=1024
        transpose_tile(W_qkv, Wqt_hi, Wqt_lo, C_, 3 * C_,
                       (t / 96) * 32, (t % 96) * 32, tid & 31, tid >> 5, tile);
    } else if (bid < 4608) {
        const int t = bid - 3584;                // W_out: N=1024 (32), K=1024
        transpose_tile(W_out, Wot_hi, Wot_lo, C_, C_,
                       (t / 32) * 32, (t % 32) * 32, tid & 31, tid >> 5, tile);
    } else {
        // ---- out bias-fill: every row = b_out (spiking rows overwritten) ----
        const int row = (bid - 4608) * 8 + (tid >> 5);
        const int lane = tid & 31;
        float* orow = out + (size_t)row * C_;
        #pragma unroll
        for (int i = 0; i < 8; i++) {
            const int e = lane * 4 + i * 128;
            *(float4*)(orow + e) = *(const float4*)(b_out + e);
        }
    }
}

// ---------------- spike compaction: per-batch lists + global list -----------
__global__ void compact_kernel() {
    __shared__ int cnts[B_];
    const int b = threadIdx.x >> 5;
    const int lane = threadIdx.x & 31;
    int base = 0;
    for (int c = 0; c < 32; c++) {
        const int t = c * 32 + lane;
        const bool sp = g_spike[b * T_ + t] > 0.5f;
        const unsigned m = __ballot_sync(0xffffffffu, sp);
        const int pos = base + __popc(m & ((1u << lane) - 1u));
        if (sp) g_idx[b][pos] = t;
        base += __popc(m);
    }
    if (lane == 0) { g_cnt[b] = base; cnts[b] = base; }
    __syncthreads();
    int off = 0;
    #pragma unroll
    for (int i = 0; i < B_; i++) if (i < b) off += cnts[i];
    for (int i = lane; i < cnts[b]; i += 32)
        g_gidx[off + i] = b * T_ + g_idx[b][i];
    if (b == B_ - 1 && lane == 0) g_total = off + cnts[b];
}

// ---------------- mma.sync bf16x3 GEMM, 4 warps x (64x64) warp tiles --------
// GATHER=false, FUSE=true : QKV GEMM + Lorentz epilogue (dense M).
// GATHER=true             : out-proj on spiking rows only (A gathered via
//                           g_gidx; stores guarded; early-exit past g_total).
#define G4_STAGE 32768
#define G4_SMEM (3 * G4_STAGE)
#define G4_TILE 8192

template<bool FUSE, bool GATHER>
__global__ __launch_bounds__(128) void gemm4_kernel(
    const __nv_bfloat16* __restrict__ Ahi, const __nv_bfloat16* __restrict__ Alo,
    const __nv_bfloat16* __restrict__ Bhi, const __nv_bfloat16* __restrict__ Blo,
    const float* __restrict__ bias, float* __restrict__ Cmat,
    int M, int N, int K)
{
    const int m0 = blockIdx.y * 128;
    int total = 0, tm1 = 0;
    if constexpr (GATHER) {
        total = g_total;
        if (m0 >= total) return;
        tm1 = total - 1;
    }

    extern __shared__ char sm[];
    const uint32_t sbase = smem_u32(sm);

    const int tid  = threadIdx.x;
    const int wid  = tid >> 5;
    const int lane = tid & 31;
    const int n0 = blockIdx.x * 128;
    const int wm = wid & 1;          // 64-row slab
    const int wn = wid >> 1;         // 64-col slab

    uint32_t so[4];
    const __nv_bfloat16 *pA0[4], *pA1[4], *pB0[4], *pB1[4];
    #pragma unroll
    for (int it = 0; it < 4; it++) {
        const int sub = tid + it * 128;
        const int row = sub >> 2, col = sub & 3;
        so[it] = (uint32_t)row * 64 + (uint32_t)((col ^ ((row >> 1) & 3)) * 16);
        const int ar = GATHER ? g_gidx[min(m0 + row, tm1)] : (m0 + row);
        pA0[it] = Ahi + (size_t)ar * K + col * 8;
        pA1[it] = Alo + (size_t)ar * K + col * 8;
        pB0[it] = Bhi + (size_t)(n0 + row) * K + col * 8;
        pB1[it] = Blo + (size_t)(n0 + row) * K + col * 8;
    }

    float acc[4][8][4];
    #pragma unroll
    for (int i = 0; i < 4; i++)
        #pragma unroll
        for (int j = 0; j < 8; j++)
            #pragma unroll
            for (int c = 0; c < 4; c++) acc[i][j][c] = 0.f;

    const int nch = K >> 5;
    const int lrow = lane & 15;
    const int kc   = lane >> 4;

    #pragma unroll
    for (int s = 0; s < 2; s++) {
        const uint32_t sb = sbase + (uint32_t)s * G4_STAGE;
        const int kb = s << 5;
        #pragma unroll
        for (int it = 0; it < 4; it++) {
            CP16(sb + 0 * G4_TILE + so[it], pA0[it] + kb);
            CP16(sb + 1 * G4_TILE + so[it], pA1[it] + kb);
            CP16(sb + 2 * G4_TILE + so[it], pB0[it] + kb);
            CP16(sb + 3 * G4_TILE + so[it], pB1[it] + kb);
        }
        CP_COMMIT();
    }

    for (int ch = 0; ch < nch; ch++) {
        CP_WAIT1();
        __syncthreads();

        if (ch + 2 < nch) {
            const uint32_t sb = sbase + (uint32_t)((ch + 2) % 3) * G4_STAGE;
            const int kb = (ch + 2) << 5;
            #pragma unroll
            for (int it = 0; it < 4; it++) {
                CP16(sb + 0 * G4_TILE + so[it], pA0[it] + kb);
                CP16(sb + 1 * G4_TILE + so[it], pA1[it] + kb);
                CP16(sb + 2 * G4_TILE + so[it], pB0[it] + kb);
                CP16(sb + 3 * G4_TILE + so[it], pB1[it] + kb);
            }
        }
        CP_COMMIT();

        const uint32_t st = sbase + (uint32_t)(ch % 3) * G4_STAGE;

        #pragma unroll
        for (int kk = 0; kk < 2; kk++) {
            const int chunk = kk * 2 + kc;
            uint32_t ahi[4][4], alo[4][4];
            #pragma unroll
            for (int mi = 0; mi < 4; mi++) {
                const int r = wm * 64 + mi * 16 + lrow;
                const uint32_t off = (uint32_t)r * 64 +
                    (uint32_t)((chunk ^ ((r >> 1) & 3)) * 16);
                LDSM_X4(ahi[mi][0], ahi[mi][1], ahi[mi][2], ahi[mi][3],
                        st + 0 * G4_TILE + off);
                LDSM_X4(alo[mi][0], alo[mi][1], alo[mi][2], alo[mi][3],
                        st + 1 * G4_TILE + off);
            }
            #pragma unroll
            for (int g = 0; g < 4; g++) {
                const int r = wn * 64 + g * 16 + lrow;
                const uint32_t off = (uint32_t)r * 64 +
                    (uint32_t)((chunk ^ ((r >> 1) & 3)) * 16);
                uint32_t bh[4], bl[4];
                LDSM_X4(bh[0], bh[1], bh[2], bh[3], st + 2 * G4_TILE + off);
                LDSM_X4(bl[0], bl[1], bl[2], bl[3], st + 3 * G4_TILE + off);
                #pragma unroll
                for (int mi = 0; mi < 4; mi++) {
                    MMA_BF16(acc[mi][g * 2 + 0], ahi[mi], bh[0], bh[2]);
                    MMA_BF16(acc[mi][g * 2 + 0], ahi[mi], bl[0], bl[2]);
                    MMA_BF16(acc[mi][g * 2 + 0], alo[mi], bh[0], bh[2]);
                    MMA_BF16(acc[mi][g * 2 + 1], ahi[mi], bh[1], bh[3]);
                    MMA_BF16(acc[mi][g * 2 + 1], ahi[mi], bl[1], bl[3]);
                    MMA_BF16(acc[mi][g * 2 + 1], alo[mi], bh[1], bh[3]);
                }
            }
        }
    }

    const int orow = lane >> 2;          // row-in-16 (0..7)
    const int ocol = (lane & 3) * 2;     // col pair base within 8

    if constexpr (GATHER) {
        #pragma unroll
        for (int mi = 0; mi < 4; mi++) {
            #pragma unroll
            for (int hh = 0; hh < 2; hh++) {
                const int rl = m0 + wm * 64 + mi * 16 + orow + hh * 8;
                if (rl >= total) continue;
                const int r0 = g_gidx[rl];
                #pragma unroll
                for (int ni = 0; ni < 8; ni++) {
                    const int c = n0 + wn * 64 + ni * 8 + ocol;
                    float2 v = make_float2(acc[mi][ni][hh * 2 + 0] + bias[c],
                                           acc[mi][ni][hh * 2 + 1] + bias[c + 1]);
                    *(float2*)(Cmat + (size_t)r0 * N + c) = v;
                }
            }
        }
    } else if constexpr (!FUSE) {
        #pragma unroll
        for (int mi = 0; mi < 4; mi++) {
            const int r0 = m0 + wm * 64 + mi * 16 + orow;
            #pragma unroll
            for (int ni = 0; ni < 8; ni++) {
                const int c = n0 + wn * 64 + ni * 8 + ocol;
                const float b0 = bias[c], b1 = bias[c + 1];
                float2 v0 = make_float2(acc[mi][ni][0] + b0, acc[mi][ni][1] + b1);
                float2 v1 = make_float2(acc[mi][ni][2] + b0, acc[mi][ni][3] + b1);
                *(float2*)(Cmat + (size_t)r0 * N + c)       = v0;
                *(float2*)(Cmat + (size_t)(r0 + 8) * N + c) = v1;
            }
        }
    } else {
        const int colbase = n0 + wn * 64;          // 64-aligned -> one head
        const int type = colbase >> 10;            // 0=Q, 1=K, 2=V
        const int head = (colbase & 1023) >> 6;
        __nv_bfloat16* ghi = (type == 0) ? g_Qhi : (type == 1) ? g_Khi : g_Vhi;
        __nv_bfloat16* glo = (type == 0) ? g_Qlo : (type == 1) ? g_Klo : g_Vlo;
        const float sgn = (type == 1) ? -1.f : 1.f;

        float bs[8][2];
        #pragma unroll
        for (int ni = 0; ni < 8; ni++) {
            bs[ni][0] = bias[colbase + ni * 8 + ocol];
            bs[ni][1] = bias[colbase + ni * 8 + ocol + 1];
        }

        #pragma unroll
        for (int mi = 0; mi < 4; mi++) {
            #pragma unroll
            for (int hh = 0; hh < 2; hh++) {
                const int r = m0 + wm * 64 + mi * 16 + orow + hh * 8;
                const int batch = r >> 10, t = r & 1023;
                const size_t ob = ((size_t)(batch * H_ + head) * T_ + t) * D_;

                float v[8][2];
                float ss = 0.f;
                #pragma unroll
                for (int ni = 0; ni < 8; ni++) {
                    v[ni][0] = acc[mi][ni][hh * 2 + 0] + bs[ni][0];
                    v[ni][1] = acc[mi][ni][hh * 2 + 1] + bs[ni][1];
                    ss += v[ni][0] * v[ni][0] + v[ni][1] * v[ni][1];
                }

                if (type != 2) {
                    ss += __shfl_xor_sync(0xffffffffu, ss, 1);
                    ss += __shfl_xor_sync(0xffffffffu, ss, 2);
                    float u0 = __shfl_sync(0xffffffffu, v[0][0], lane & ~3u, 32);
                    float mink = ss - 2.f * u0 * u0;
                    float nn = sqrtf(fmaxf(mink, 1e-8f));
                    float e = __expf(nn), ei = 1.f / e;
                    float tme = 0.5f * (e + ei);
                    float coef = sgn * (e - ei) / (2.f * nn);
                    #pragma unroll
                    for (int ni = 0; ni < 8; ni++) {
                        v[ni][0] *= coef;
                        v[ni][1] *= coef;
                    }
                    if ((lane & 3) == 0) v[0][0] = tme;   // d==0 -> time comp
                }

                #pragma unroll
                for (int ni = 0; ni < 8; ni++) {
                    const int d = ni * 8 + ocol;
                    uint32_t hp = pack_bf16(v[ni][0], v[ni][1]);
                    __nv_bfloat162 hv = *(__nv_bfloat162*)&hp;
                    uint32_t lp = pack_bf16(v[ni][0] - __low2float(hv),
                                            v[ni][1] - __high2float(hv));
                    *(uint32_t*)(ghi + ob + d) = hp;
                    *(uint32_t*)(glo + ob + d) = lp;
                }
            }
        }
    }
}

// ---------------- tensor-core flash attention (bf16x3, spike-compacted) -----
#define AT_SMEM 65536
#define SWO(row, ch) ((uint32_t)(row) * 128u + (uint32_t)(((ch) ^ (((row) >> 1) & 3)) * 16))

__global__ __launch_bounds__(128) void attn_kernel() {
    const int b  = blockIdx.z;
    const int cnt = g_cnt[b];
    const int ntiles = (cnt + 63) >> 6;
    if ((int)blockIdx.x >= ntiles) return;
    const int ti = ntiles - 1 - (int)blockIdx.x;   // heavy CTAs first
    const int i0 = ti * 64;

    extern __shared__ char sm[];
    const uint32_t sb = smem_u32(sm);
    const int tid = threadIdx.x;
    const int wid = tid >> 5;
    const int lane = tid & 31;
    const int h  = blockIdx.y;
    const int bh = b * H_ + h;
    const size_t gb = (size_t)bh * T_ * D_;
    const int* idx = g_idx[b];
    const int cm1 = cnt - 1;

    const int lrow  = lane & 15;
    const int khalf = lane >> 4;

    // ---- prologue: gathered Q -> [32K,48K), K/V tile 0 -> buf0 [0,32K) ----
    #pragma unroll
    for (int i = 0; i < 8; i++) {
        const int arr = i >> 2;
        const int sub = tid + (i & 3) * 128;
        const int row = sub >> 3, ch = sub & 7;
        const int tq = idx[min(i0 + row, cm1)];
        const __nv_bfloat16* g = arr ? g_Qlo : g_Qhi;
        CP16(sb + 32768u + (uint32_t)arr * 8192u + SWO(row, ch),
             g + gb + (size_t)tq * D_ + ch * 8);
    }
    #pragma unroll
    for (int i = 0; i < 16; i++) {
        const int arr = i >> 2;
        const int sub = tid + (i & 3) * 128;
        const int row = sub >> 3, ch = sub & 7;
        const __nv_bfloat16* g = (arr == 0) ? g_Khi : (arr == 1) ? g_Klo
                               : (arr == 2) ? g_Vhi : g_Vlo;
        CP16(sb + (uint32_t)arr * 8192u + SWO(row, ch),
             g + gb + (size_t)row * D_ + ch * 8);
    }
    CP_COMMIT();

    float O[8][4];
    #pragma unroll
    for (int i = 0; i < 8; i++)
        #pragma unroll
        for (int c = 0; c < 4; c++) O[i][c] = 0.f;
    float m0 = -1e30f, m1 = -1e30f, l0 = 0.f, l1 = 0.f;
    uint32_t ahi[4][4], alo[4][4];

    const int rq = lane >> 2;
    const int cq = (lane & 3) * 2;
    const int lr0 = i0 + wid * 16 + rq;
    const int lr1 = lr0 + 8;
    const int grow0 = idx[min(lr0, cm1)];
    const int grow1 = idx[min(lr1, cm1)];
    const bool v0 = (lr0 <= cm1);
    const bool v1 = (lr1 <= cm1);

    const int tjmax = idx[min(i0 + 63, cm1)] >> 6;

    for (int tj = 0; tj <= tjmax; tj++) {
        CP_WAIT0();
        __syncthreads();

        if (tj == 0) {
            #pragma unroll
            for (int kc = 0; kc < 4; kc++) {
                const int r = wid * 16 + lrow;
                const uint32_t off = SWO(r, kc * 2 + khalf);
                LDSM_X4(ahi[kc][0], ahi[kc][1], ahi[kc][2], ahi[kc][3],
                        sb + 32768u + off);
                LDSM_X4(alo[kc][0], alo[kc][1], alo[kc][2], alo[kc][3],
                        sb + 40960u + off);
            }
            __syncthreads();
        }

        if (tj < tjmax) {
            const uint32_t dst = sb + (uint32_t)((tj + 1) & 1) * 32768u;
            const size_t src = gb + (size_t)(tj + 1) * 64 * D_;
            #pragma unroll
            for (int i = 0; i < 16; i++) {
                const int arr = i >> 2;
                const int sub = tid + (i & 3) * 128;
                const int row = sub >> 3, ch = sub & 7;
                const __nv_bfloat16* g = (arr == 0) ? g_Khi : (arr == 1) ? g_Klo
                                       : (arr == 2) ? g_Vhi : g_Vlo;
                CP16(dst + (uint32_t)arr * 8192u + SWO(row, ch),
                     g + src + (size_t)row * D_ + ch * 8);
            }
            CP_COMMIT();
        }

        const uint32_t kbuf = sb + (uint32_t)(tj & 1) * 32768u;

        float acc[8][4];
        #pragma unroll
        for (int i = 0; i < 8; i++)
            #pragma unroll
            for (int c = 0; c < 4; c++) acc[i][c] = 0.f;

        #pragma unroll
        for (int kc = 0; kc < 4; kc++) {
            uint32_t bh4[4][4], bl4[4][4];
            #pragma unroll
            for (int g = 0; g < 4; g++) {
                const int r = g * 16 + lrow;
                const uint32_t off = SWO(r, kc * 2 + khalf);
                LDSM_X4(bh4[g][0], bh4[g][1], bh4[g][2], bh4[g][3], kbuf + off);
                LDSM_X4(bl4[g][0], bl4[g][1], bl4[g][2], bl4[g][3],
                        kbuf + 8192u + off);
            }
            #pragma unroll
            for (int ni = 0; ni < 8; ni++) {
                const int g = ni >> 1, o = ni & 1;
                MMA_BF16(acc[ni], ahi[kc], bh4[g][o], bh4[g][2 + o]);
                MMA_BF16(acc[ni], ahi[kc], bl4[g][o], bl4[g][2 + o]);
                MMA_BF16(acc[ni], alo[kc], bh4[g][o], bh4[g][2 + o]);
            }
        }

        const int j0 = tj * 64;
        #pragma unroll
        for (int ni = 0; ni < 8; ni++) {
            #pragma unroll
            for (int c = 0; c < 4; c++) {
                const int col = j0 + ni * 8 + cq + (c & 1);
                const int grow = (c < 2) ? grow0 : grow1;
                float x = fmaxf(acc[ni][c], 1.0f + 1e-7f);
                float dd = __logf(x + sqrt_approx(fmaxf(x * x - 1.f, 0.f)));
                float s = -dd * dd * 0.125f;
                acc[ni][c] = (col > grow) ? -1e30f : s;
            }
        }

        {
            float mx = -1e30f;
            #pragma unroll
            for (int ni = 0; ni < 8; ni++)
                mx = fmaxf(mx, fmaxf(acc[ni][0], acc[ni][1]));
            mx = fmaxf(mx, __shfl_xor_sync(0xffffffffu, mx, 1));
            mx = fmaxf(mx, __shfl_xor_sync(0xffffffffu, mx, 2));
            float mnew = fmaxf(m0, mx);
            float es = __expf(m0 - mnew);
            l0 *= es;
            #pragma unroll
            for (int ni = 0; ni < 8; ni++) { O[ni][0] *= es; O[ni][1] *= es; }
            float rs = 0.f;
            #pragma unroll
            for (int ni = 0; ni < 8; ni++) {
                float p0 = __expf(acc[ni][0] - mnew);
                float p1 = __expf(acc[ni][1] - mnew);
                acc[ni][0] = p0; acc[ni][1] = p1; rs += p0 + p1;
            }
            rs += __shfl_xor_sync(0xffffffffu, rs, 1);
            rs += __shfl_xor_sync(0xffffffffu, rs, 2);
            l0 += rs; m0 = mnew;
        }
        {
            float mx = -1e30f;
            #pragma unroll
            for (int ni = 0; ni < 8; ni++)
                mx = fmaxf(mx, fmaxf(acc[ni][2], acc[ni][3]));
            mx = fmaxf(mx, __shfl_xor_sync(0xffffffffu, mx, 1));
            mx = fmaxf(mx, __shfl_xor_sync(0xffffffffu, mx, 2));
            float mnew = fmaxf(m1, mx);
            float es = __expf(m1 - mnew);
            l1 *= es;
            #pragma unroll
            for (int ni = 0; ni < 8; ni++) { O[ni][2] *= es; O[ni][3] *= es; }
            float rs = 0.f;
            #pragma unroll
            for (int ni = 0; ni < 8; ni++) {
                float p0 = __expf(acc[ni][2] - mnew);
                float p1 = __expf(acc[ni][3] - mnew);
                acc[ni][2] = p0; acc[ni][3] = p1; rs += p0 + p1;
            }
            rs += __shfl_xor_sync(0xffffffffu, rs, 1);
            rs += __shfl_xor_sync(0xffffffffu, rs, 2);
            l1 += rs; m1 = mnew;
        }

        const uint32_t vbuf = kbuf + 16384u;
        #pragma unroll
        for (int kc = 0; kc < 4; kc++) {
            uint32_t ph[4], pl[4];
            #pragma unroll
            for (int q = 0; q < 4; q++) {
                const int ni = 2 * kc + (q >> 1);
                const int c0 = (q & 1) * 2;
                float a = acc[ni][c0], bb = acc[ni][c0 + 1];
                uint32_t hp = pack_bf16(a, bb);
                __nv_bfloat162 hv = *(__nv_bfloat162*)&hp;
                const int idx2 = (q & 1) + (q >> 1) * 2;
                ph[idx2] = hp;
                pl[idx2] = pack_bf16(a - __low2float(hv), bb - __high2float(hv));
            }
            #pragma unroll
            for (int g = 0; g < 4; g++) {
                const int r = kc * 16 + ((lane >> 3) & 1) * 8 + (lane & 7);
                const uint32_t off = SWO(r, g * 2 + khalf);
                uint32_t vh[4], vl[4];
                LDSM_X4_T(vh[0], vh[1], vh[2], vh[3], vbuf + off);
                LDSM_X4_T(vl[0], vl[1], vl[2], vl[3], vbuf + 8192u + off);
                MMA_BF16(O[g * 2],     ph, vh[0], vh[1]);
                MMA_BF16(O[g * 2],     ph, vl[0], vl[1]);
                MMA_BF16(O[g * 2],     pl, vh[0], vh[1]);
                MMA_BF16(O[g * 2 + 1], ph, vh[2], vh[3]);
                MMA_BF16(O[g * 2 + 1], ph, vl[2], vl[3]);
                MMA_BF16(O[g * 2 + 1], pl, vh[2], vh[3]);
            }
        }
    }

    // ---- epilogue: write Yhi/Ylo bf16 (spiking rows only; spike==1) ----
    const float inv0 = 1.f / l0;
    const float inv1 = 1.f / l1;
    const size_t y0 = ((size_t)(b * T_ + grow0)) * C_ + h * D_;
    const size_t y1 = ((size_t)(b * T_ + grow1)) * C_ + h * D_;
    #pragma unroll
    for (int ni = 0; ni < 8; ni++) {
        const int d = ni * 8 + cq;
        if (v0) {
            float a0 = O[ni][0] * inv0, a1 = O[ni][1] * inv0;
            uint32_t h0 = pack_bf16(a0, a1);
            __nv_bfloat162 hv0 = *(__nv_bfloat162*)&h0;
            uint32_t l0p = pack_bf16(a0 - __low2float(hv0), a1 - __high2float(hv0));
            *(uint32_t*)(g_Yhi + y0 + d) = h0;
            *(uint32_t*)(g_Ylo + y0 + d) = l0p;
        }
        if (v1) {
            float b0 = O[ni][2] * inv1, b1 = O[ni][3] * inv1;
            uint32_t h1 = pack_bf16(b0, b1);
            __nv_bfloat162 hv1 = *(__nv_bfloat162*)&h1;
            uint32_t l1p = pack_bf16(b0 - __low2float(hv1), b1 - __high2float(hv1));
            *(uint32_t*)(g_Yhi + y1 + d) = h1;
            *(uint32_t*)(g_Ylo + y1 + d) = l1p;
        }
    }
}

// ---------------- launch -----------------------------------------------------
extern "C" void kernel_launch(void* const* d_in, const int* in_sizes, int n_in,
                              void* d_out, int out_size) {
    const float* x      = (const float*)d_in[0];
    const float* W_qkv  = (const float*)d_in[1];
    const float* b_qkv  = (const float*)d_in[2];
    const float* W_out  = (const float*)d_in[3];
    const float* b_out  = (const float*)d_in[4];
    const float* w_sur  = (const float*)d_in[5];
    const float* b_sur  = (const float*)d_in[6];
    const float* thresh = (const float*)d_in[7];
    float* out = (float*)d_out;

    __nv_bfloat16 *p_xhi, *p_xlo, *p_Wqt_hi, *p_Wqt_lo;
    __nv_bfloat16 *p_Yhi, *p_Ylo, *p_Wot_hi, *p_Wot_lo;
    cudaGetSymbolAddress((void**)&p_xhi, g_xhi);
    cudaGetSymbolAddress((void**)&p_xlo, g_xlo);
    cudaGetSymbolAddress((void**)&p_Wqt_hi, g_Wqt_hi);
    cudaGetSymbolAddress((void**)&p_Wqt_lo, g_Wqt_lo);
    cudaGetSymbolAddress((void**)&p_Yhi, g_Yhi);
    cudaGetSymbolAddress((void**)&p_Ylo, g_Ylo);
    cudaGetSymbolAddress((void**)&p_Wot_hi, g_Wot_hi);
    cudaGetSymbolAddress((void**)&p_Wot_lo, g_Wot_lo);

    cudaFuncSetAttribute(attn_kernel,
                         cudaFuncAttributeMaxDynamicSharedMemorySize, AT_SMEM);
    cudaFuncSetAttribute(gemm4_kernel<true, false>,
                         cudaFuncAttributeMaxDynamicSharedMemorySize, G4_SMEM);
    cudaFuncSetAttribute(gemm4_kernel<false, true>,
                         cudaFuncAttributeMaxDynamicSharedMemorySize, G4_SMEM);

    const int M = B_ * T_;   // 4096

    // 1. fused prep: x spike+split | W^T splits | out = bias (one launch)
    prep_all_kernel<<<5120, 256>>>(x, W_qkv, W_out, w_sur, b_sur, thresh,
                                   b_out, out,
                                   p_xhi, p_xlo, p_Wqt_hi, p_Wqt_lo,
                                   p_Wot_hi, p_Wot_lo);

    // 2. spike compaction (per-batch lists + global list)
    compact_kernel<<<1, 128>>>();

    // 3. QKV GEMM with fused Lorentz transform epilogue -> g_{Q,K,V}{hi,lo}
    gemm4_kernel<true, false><<<dim3(3 * C_ / 128, M / 128), 128, G4_SMEM>>>(
        p_xhi, p_xlo, p_Wqt_hi, p_Wqt_lo, b_qkv, nullptr, M, 3 * C_, C_);

    // 4. spike-compacted tensor-core flash attention
    attn_kernel<<<dim3(T_ / 64, H_, B_), 128, AT_SMEM>>>();

    // 5. out projection on spiking rows only (others = bias from prep)
    gemm4_kernel<false, true><<<dim3(C_ / 128, M / 128), 128, G4_SMEM>>>(
        p_Yhi, p_Ylo, p_Wot_hi, p_Wot_lo, b_out, out, M, C_, C_);
}

// round 17
// speedup vs baseline: 1.3308x; 1.0838x over previous
#include <cuda_runtime.h>
#include <cuda_bf16.h>
#include <math.h>
#include <stdint.h>

#define B_ 4
#define T_ 1024
#define C_ 1024
#define H_ 16
#define D_ 64

// ---------------- scratch (device globals; no allocations allowed) ----------
__device__ float g_spike[B_ * T_];
__device__ int   g_idx[B_][T_];     // compacted spiking token indices per batch
__device__ int   g_cnt[B_];
__device__ int   g_gidx[B_ * T_];   // global compacted spiking rows (b*T+t)
__device__ int   g_total;

// transformed Q',K',V as bf16 hi/lo  [BH][T][64]
__device__ __nv_bfloat16 g_Qhi[(size_t)B_ * H_ * T_ * D_];
__device__ __nv_bfloat16 g_Qlo[(size_t)B_ * H_ * T_ * D_];
__device__ __nv_bfloat16 g_Khi[(size_t)B_ * H_ * T_ * D_];
__device__ __nv_bfloat16 g_Klo[(size_t)B_ * H_ * T_ * D_];
__device__ __nv_bfloat16 g_Vhi[(size_t)B_ * H_ * T_ * D_];
__device__ __nv_bfloat16 g_Vlo[(size_t)B_ * H_ * T_ * D_];

// bf16 hi/lo split operands for tensor-core GEMMs
__device__ __nv_bfloat16 g_xhi[(size_t)B_ * T_ * C_];
__device__ __nv_bfloat16 g_xlo[(size_t)B_ * T_ * C_];
__device__ __nv_bfloat16 g_Wqt_hi[(size_t)3 * C_ * C_];    // W_qkv^T [N,K]
__device__ __nv_bfloat16 g_Wqt_lo[(size_t)3 * C_ * C_];
__device__ __nv_bfloat16 g_Yhi[(size_t)B_ * T_ * C_];      // attn out, bf16 hi/lo
__device__ __nv_bfloat16 g_Ylo[(size_t)B_ * T_ * C_];
__device__ __nv_bfloat16 g_Wot_hi[(size_t)C_ * C_];        // W_out^T [N,K]
__device__ __nv_bfloat16 g_Wot_lo[(size_t)C_ * C_];

// ======================= generic-PTX helpers (no 'a' features) ==============
__device__ __forceinline__ uint32_t smem_u32(const void* p) {
    uint32_t a;
    asm("{ .reg .u64 t; cvta.to.shared.u64 t, %1; cvt.u32.u64 %0, t; }"
        : "=r"(a) : "l"(p));
    return a;
}
__device__ __forceinline__ float sqrt_approx(float x) {
    float r;
    asm("sqrt.approx.f32 %0, %1;" : "=f"(r) : "f"(x));
    return r;
}
#define CP16(saddr, gaddr) \
    asm volatile("cp.async.cg.shared.global [%0], [%1], 16;" \
                 :: "r"(saddr), "l"(gaddr))
#define CP_COMMIT() asm volatile("cp.async.commit_group;" ::: "memory")
#define CP_WAIT1()  asm volatile("cp.async.wait_group 1;" ::: "memory")
#define CP_WAIT0()  asm volatile("cp.async.wait_group 0;" ::: "memory")

#define LDSM_X4(r0, r1, r2, r3, addr) \
    asm volatile("ldmatrix.sync.aligned.m8n8.x4.shared.b16 {%0,%1,%2,%3}, [%4];" \
                 : "=r"(r0), "=r"(r1), "=r"(r2), "=r"(r3) : "r"(addr))

#define LDSM_X4_T(r0, r1, r2, r3, addr) \
    asm volatile("ldmatrix.sync.aligned.m8n8.x4.trans.shared.b16 {%0,%1,%2,%3}, [%4];" \
                 : "=r"(r0), "=r"(r1), "=r"(r2), "=r"(r3) : "r"(addr))

#define MMA_BF16(d, a, b0, b1) \
    asm volatile("mma.sync.aligned.m16n8k16.row.col.f32.bf16.bf16.f32 " \
                 "{%0,%1,%2,%3}, {%4,%5,%6,%7}, {%8,%9}, {%0,%1,%2,%3};" \
                 : "+f"((d)[0]), "+f"((d)[1]), "+f"((d)[2]), "+f"((d)[3]) \
                 : "r"((a)[0]), "r"((a)[1]), "r"((a)[2]), "r"((a)[3]), \
                   "r"(b0), "r"(b1))

__device__ __forceinline__ uint32_t pack_bf16(float a, float b) {
    __nv_bfloat162 h = __floats2bfloat162_rn(a, b);
    return *(uint32_t*)&h;
}

// ---------------- fused prep: x | W_qkv^T | W_out^T | out bias-fill ---------
__device__ __forceinline__ void transpose_tile(
    const float* __restrict__ W, __nv_bfloat16* __restrict__ Thi,
    __nv_bfloat16* __restrict__ Tlo, int K, int N, int k0, int n0,
    int tx, int ty, float (*tile)[33])
{
    #pragma unroll
    for (int j = 0; j < 32; j += 8)
        tile[ty + j][tx] = W[(size_t)(k0 + ty + j) * N + n0 + tx];
    __syncthreads();
    #pragma unroll
    for (int j = 0; j < 32; j += 8) {
        float v = tile[tx][ty + j];
        __nv_bfloat16 h = __float2bfloat16(v);
        __nv_bfloat16 l = __float2bfloat16(v - __bfloat162float(h));
        Thi[(size_t)(n0 + ty + j) * K + k0 + tx] = h;
        Tlo[(size_t)(n0 + ty + j) * K + k0 + tx] = l;
    }
}

// grid: [0,512) x-prep | [512,3584) W_qkv | [3584,4608) W_out | [4608,5120) out=b
__global__ void prep_all_kernel(const float* __restrict__ x,
                                const float* __restrict__ W_qkv,
                                const float* __restrict__ W_out,
                                const float* __restrict__ w_sur,
                                const float* __restrict__ b_sur,
                                const float* __restrict__ threshold,
                                const float* __restrict__ b_out,
                                float* __restrict__ out,
                                __nv_bfloat16* __restrict__ xhi,
                                __nv_bfloat16* __restrict__ xlo,
                                __nv_bfloat16* __restrict__ Wqt_hi,
                                __nv_bfloat16* __restrict__ Wqt_lo,
                                __nv_bfloat16* __restrict__ Wot_hi,
                                __nv_bfloat16* __restrict__ Wot_lo) {
    __shared__ float tile[32][33];
    const int bid = blockIdx.x;
    const int tid = threadIdx.x;

    if (bid < 512) {
        // ---- x prep: one warp per row; spike dot + bf16 hi/lo split ----
        const int row = bid * 8 + (tid >> 5);
        const int lane = tid & 31;
        const float* xr = x + (size_t)row * C_;
        float s = 0.f;
        #pragma unroll
        for (int i = 0; i < 8; i++) {
            const int e = lane * 4 + i * 128;
            float4 v = *(const float4*)(xr + e);
            float4 w = *(const float4*)(w_sur + e);
            s += v.x * w.x + v.y * w.y + v.z * w.z + v.w * w.w;

            __nv_bfloat16 h0 = __float2bfloat16(v.x);
            __nv_bfloat16 h1 = __float2bfloat16(v.y);
            __nv_bfloat16 h2 = __float2bfloat16(v.z);
            __nv_bfloat16 h3 = __float2bfloat16(v.w);
            __nv_bfloat162* hp = (__nv_bfloat162*)(xhi + (size_t)row * C_ + e);
            __nv_bfloat162* lp = (__nv_bfloat162*)(xlo + (size_t)row * C_ + e);
            hp[0] = __nv_bfloat162(h0, h1);
            hp[1] = __nv_bfloat162(h2, h3);
            lp[0] = __nv_bfloat162(__float2bfloat16(v.x - __bfloat162float(h0)),
                                   __float2bfloat16(v.y - __bfloat162float(h1)));
            lp[1] = __nv_bfloat162(__float2bfloat16(v.z - __bfloat162float(h2)),
                                   __float2bfloat16(v.w - __bfloat162float(h3)));
        }
        #pragma unroll
        for (int m = 16; m; m >>= 1) s += __shfl_xor_sync(0xffffffffu, s, m);
        if (lane == 0) {
            float z = s + b_sur[0];
            float imp = 1.f / (1.f + expf(-z));
            g_spike[row] = (imp > threshold[0]) ? 1.f : 0.f;
        }
    } else if (bid < 3584) {
        const int t = bid - 512;                 // W_qkv: N=3072 (96 tiles), K=1024
        transpose_tile(W_qkv, Wqt_hi, Wqt_lo, C_, 3 * C_,
                       (t / 96) * 32, (t % 96) * 32, tid & 31, tid >> 5, tile);
    } else if (bid < 4608) {
        const int t = bid - 3584;                // W_out: N=1024 (32), K=1024
        transpose_tile(W_out, Wot_hi, Wot_lo, C_, C_,
                       (t / 32) * 32, (t % 32) * 32, tid & 31, tid >> 5, tile);
    } else {
        // ---- out bias-fill: every row = b_out (spiking rows overwritten) ----
        const int row = (bid - 4608) * 8 + (tid >> 5);
        const int lane = tid & 31;
        float* orow = out + (size_t)row * C_;
        #pragma unroll
        for (int i = 0; i < 8; i++) {
            const int e = lane * 4 + i * 128;
            *(float4*)(orow + e) = *(const float4*)(b_out + e);
        }
    }
}

// ---------------- spike compaction: per-batch lists + global list -----------
__global__ void compact_kernel() {
    __shared__ int cnts[B_];
    const int b = threadIdx.x >> 5;
    const int lane = threadIdx.x & 31;
    int base = 0;
    for (int c = 0; c < 32; c++) {
        const int t = c * 32 + lane;
        const bool sp = g_spike[b * T_ + t] > 0.5f;
        const unsigned m = __ballot_sync(0xffffffffu, sp);
        const int pos = base + __popc(m & ((1u << lane) - 1u));
        if (sp) g_idx[b][pos] = t;
        base += __popc(m);
    }
    if (lane == 0) { g_cnt[b] = base; cnts[b] = base; }
    __syncthreads();
    int off = 0;
    #pragma unroll
    for (int i = 0; i < B_; i++) if (i < b) off += cnts[i];
    for (int i = lane; i < cnts[b]; i += 32)
        g_gidx[off + i] = b * T_ + g_idx[b][i];
    if (b == B_ - 1 && lane == 0) g_total = off + cnts[b];
}

// ---------------- mma.sync bf16x3 GEMM, 4 warps x (64x64) warp tiles --------
// FUSE=true  : QKV GEMM + Lorentz epilogue. Q columns (n0<1024) are M-gathered
//              over g_gidx (spiking rows only, early-exit past g_total);
//              K/V columns are dense.
// GATHER=true: out-proj on spiking rows only (A gathered via g_gidx).
#define G4_STAGE 32768
#define G4_SMEM (3 * G4_STAGE)
#define G4_TILE 8192

template<bool FUSE, bool GATHER>
__global__ __launch_bounds__(128) void gemm4_kernel(
    const __nv_bfloat16* __restrict__ Ahi, const __nv_bfloat16* __restrict__ Alo,
    const __nv_bfloat16* __restrict__ Bhi, const __nv_bfloat16* __restrict__ Blo,
    const float* __restrict__ bias, float* __restrict__ Cmat,
    int M, int N, int K)
{
    const int m0 = blockIdx.y * 128;
    const int n0 = blockIdx.x * 128;
    const bool rowgather = GATHER || (FUSE && n0 < 1024);   // Q third gathered
    int total = 0, tm1 = 0;
    if (rowgather) {
        total = g_total;
        if (m0 >= total) return;
        tm1 = total - 1;
    }

    extern __shared__ char sm[];
    const uint32_t sbase = smem_u32(sm);

    const int tid  = threadIdx.x;
    const int wid  = tid >> 5;
    const int lane = tid & 31;
    const int wm = wid & 1;          // 64-row slab
    const int wn = wid >> 1;         // 64-col slab

    uint32_t so[4];
    const __nv_bfloat16 *pA0[4], *pA1[4], *pB0[4], *pB1[4];
    #pragma unroll
    for (int it = 0; it < 4; it++) {
        const int sub = tid + it * 128;
        const int row = sub >> 2, col = sub & 3;
        so[it] = (uint32_t)row * 64 + (uint32_t)((col ^ ((row >> 1) & 3)) * 16);
        const int ar = rowgather ? g_gidx[min(m0 + row, tm1)] : (m0 + row);
        pA0[it] = Ahi + (size_t)ar * K + col * 8;
        pA1[it] = Alo + (size_t)ar * K + col * 8;
        pB0[it] = Bhi + (size_t)(n0 + row) * K + col * 8;
        pB1[it] = Blo + (size_t)(n0 + row) * K + col * 8;
    }

    float acc[4][8][4];
    #pragma unroll
    for (int i = 0; i < 4; i++)
        #pragma unroll
        for (int j = 0; j < 8; j++)
            #pragma unroll
            for (int c = 0; c < 4; c++) acc[i][j][c] = 0.f;

    const int nch = K >> 5;
    const int lrow = lane & 15;
    const int kc   = lane >> 4;

    #pragma unroll
    for (int s = 0; s < 2; s++) {
        const uint32_t sb = sbase + (uint32_t)s * G4_STAGE;
        const int kb = s << 5;
        #pragma unroll
        for (int it = 0; it < 4; it++) {
            CP16(sb + 0 * G4_TILE + so[it], pA0[it] + kb);
            CP16(sb + 1 * G4_TILE + so[it], pA1[it] + kb);
            CP16(sb + 2 * G4_TILE + so[it], pB0[it] + kb);
            CP16(sb + 3 * G4_TILE + so[it], pB1[it] + kb);
        }
        CP_COMMIT();
    }

    for (int ch = 0; ch < nch; ch++) {
        CP_WAIT1();
        __syncthreads();

        if (ch + 2 < nch) {
            const uint32_t sb = sbase + (uint32_t)((ch + 2) % 3) * G4_STAGE;
            const int kb = (ch + 2) << 5;
            #pragma unroll
            for (int it = 0; it < 4; it++) {
                CP16(sb + 0 * G4_TILE + so[it], pA0[it] + kb);
                CP16(sb + 1 * G4_TILE + so[it], pA1[it] + kb);
                CP16(sb + 2 * G4_TILE + so[it], pB0[it] + kb);
                CP16(sb + 3 * G4_TILE + so[it], pB1[it] + kb);
            }
        }
        CP_COMMIT();

        const uint32_t st = sbase + (uint32_t)(ch % 3) * G4_STAGE;

        #pragma unroll
        for (int kk = 0; kk < 2; kk++) {
            const int chunk = kk * 2 + kc;
            uint32_t ahi[4][4], alo[4][4];
            #pragma unroll
            for (int mi = 0; mi < 4; mi++) {
                const int r = wm * 64 + mi * 16 + lrow;
                const uint32_t off = (uint32_t)r * 64 +
                    (uint32_t)((chunk ^ ((r >> 1) & 3)) * 16);
                LDSM_X4(ahi[mi][0], ahi[mi][1], ahi[mi][2], ahi[mi][3],
                        st + 0 * G4_TILE + off);
                LDSM_X4(alo[mi][0], alo[mi][1], alo[mi][2], alo[mi][3],
                        st + 1 * G4_TILE + off);
            }
            #pragma unroll
            for (int g = 0; g < 4; g++) {
                const int r = wn * 64 + g * 16 + lrow;
                const uint32_t off = (uint32_t)r * 64 +
                    (uint32_t)((chunk ^ ((r >> 1) & 3)) * 16);
                uint32_t bh[4], bl[4];
                LDSM_X4(bh[0], bh[1], bh[2], bh[3], st + 2 * G4_TILE + off);
                LDSM_X4(bl[0], bl[1], bl[2], bl[3], st + 3 * G4_TILE + off);
                #pragma unroll
                for (int mi = 0; mi < 4; mi++) {
                    MMA_BF16(acc[mi][g * 2 + 0], ahi[mi], bh[0], bh[2]);
                    MMA_BF16(acc[mi][g * 2 + 0], ahi[mi], bl[0], bl[2]);
                    MMA_BF16(acc[mi][g * 2 + 0], alo[mi], bh[0], bh[2]);
                    MMA_BF16(acc[mi][g * 2 + 1], ahi[mi], bh[1], bh[3]);
                    MMA_BF16(acc[mi][g * 2 + 1], ahi[mi], bl[1], bl[3]);
                    MMA_BF16(acc[mi][g * 2 + 1], alo[mi], bh[1], bh[3]);
                }
            }
        }
    }

    const int orow = lane >> 2;          // row-in-16 (0..7)
    const int ocol = (lane & 3) * 2;     // col pair base within 8

    if constexpr (GATHER) {
        #pragma unroll
        for (int mi = 0; mi < 4; mi++) {
            #pragma unroll
            for (int hh = 0; hh < 2; hh++) {
                const int rl = m0 + wm * 64 + mi * 16 + orow + hh * 8;
                if (rl >= total) continue;
                const int r0 = g_gidx[rl];
                #pragma unroll
                for (int ni = 0; ni < 8; ni++) {
                    const int c = n0 + wn * 64 + ni * 8 + ocol;
                    float2 v = make_float2(acc[mi][ni][hh * 2 + 0] + bias[c],
                                           acc[mi][ni][hh * 2 + 1] + bias[c + 1]);
                    *(float2*)(Cmat + (size_t)r0 * N + c) = v;
                }
            }
        }
    } else if constexpr (!FUSE) {
        #pragma unroll
        for (int mi = 0; mi < 4; mi++) {
            const int r0 = m0 + wm * 64 + mi * 16 + orow;
            #pragma unroll
            for (int ni = 0; ni < 8; ni++) {
                const int c = n0 + wn * 64 + ni * 8 + ocol;
                const float b0 = bias[c], b1 = bias[c + 1];
                float2 v0 = make_float2(acc[mi][ni][0] + b0, acc[mi][ni][1] + b1);
                float2 v1 = make_float2(acc[mi][ni][2] + b0, acc[mi][ni][3] + b1);
                *(float2*)(Cmat + (size_t)r0 * N + c)       = v0;
                *(float2*)(Cmat + (size_t)(r0 + 8) * N + c) = v1;
            }
        }
    } else {
        const int colbase = n0 + wn * 64;          // 64-aligned -> one head
        const int type = colbase >> 10;            // 0=Q, 1=K, 2=V
        const int head = (colbase & 1023) >> 6;
        __nv_bfloat16* ghi = (type == 0) ? g_Qhi : (type == 1) ? g_Khi : g_Vhi;
        __nv_bfloat16* glo = (type == 0) ? g_Qlo : (type == 1) ? g_Klo : g_Vlo;
        const float sgn = (type == 1) ? -1.f : 1.f;

        float bs[8][2];
        #pragma unroll
        for (int ni = 0; ni < 8; ni++) {
            bs[ni][0] = bias[colbase + ni * 8 + ocol];
            bs[ni][1] = bias[colbase + ni * 8 + ocol + 1];
        }

        #pragma unroll
        for (int mi = 0; mi < 4; mi++) {
            #pragma unroll
            for (int hh = 0; hh < 2; hh++) {
                const int rl = m0 + wm * 64 + mi * 16 + orow + hh * 8;
                int grow;
                if (rowgather) {                    // Q third: gathered rows
                    if (rl >= total) continue;
                    grow = g_gidx[rl];
                } else {
                    grow = rl;
                }
                const int batch = grow >> 10, t = grow & 1023;
                const size_t ob = ((size_t)(batch * H_ + head) * T_ + t) * D_;

                float v[8][2];
                float ss = 0.f;
                #pragma unroll
                for (int ni = 0; ni < 8; ni++) {
                    v[ni][0] = acc[mi][ni][hh * 2 + 0] + bs[ni][0];
                    v[ni][1] = acc[mi][ni][hh * 2 + 1] + bs[ni][1];
                    ss += v[ni][0] * v[ni][0] + v[ni][1] * v[ni][1];
                }

                if (type != 2) {
                    ss += __shfl_xor_sync(0xffffffffu, ss, 1);
                    ss += __shfl_xor_sync(0xffffffffu, ss, 2);
                    float u0 = __shfl_sync(0xffffffffu, v[0][0], lane & ~3u, 32);
                    float mink = ss - 2.f * u0 * u0;
                    float nn = sqrtf(fmaxf(mink, 1e-8f));
                    float e = __expf(nn), ei = 1.f / e;
                    float tme = 0.5f * (e + ei);
                    float coef = sgn * (e - ei) / (2.f * nn);
                    #pragma unroll
                    for (int ni = 0; ni < 8; ni++) {
                        v[ni][0] *= coef;
                        v[ni][1] *= coef;
                    }
                    if ((lane & 3) == 0) v[0][0] = tme;   // d==0 -> time comp
                }

                #pragma unroll
                for (int ni = 0; ni < 8; ni++) {
                    const int d = ni * 8 + ocol;
                    uint32_t hp = pack_bf16(v[ni][0], v[ni][1]);
                    __nv_bfloat162 hv = *(__nv_bfloat162*)&hp;
                    uint32_t lp = pack_bf16(v[ni][0] - __low2float(hv),
                                            v[ni][1] - __high2float(hv));
                    *(uint32_t*)(ghi + ob + d) = hp;
                    *(uint32_t*)(glo + ob + d) = lp;
                }
            }
        }
    }
}

// ---------------- tensor-core flash attention (bf16x3, spike-compacted) -----
#define AT_SMEM 65536
#define SWO(row, ch) ((uint32_t)(row) * 128u + (uint32_t)(((ch) ^ (((row) >> 1) & 3)) * 16))

__global__ __launch_bounds__(128) void attn_kernel() {
    const int b  = blockIdx.z;
    const int cnt = g_cnt[b];
    const int ntiles = (cnt + 63) >> 6;
    if ((int)blockIdx.x >= ntiles) return;
    const int ti = ntiles - 1 - (int)blockIdx.x;   // heavy CTAs first
    const int i0 = ti * 64;

    extern __shared__ char sm[];
    const uint32_t sb = smem_u32(sm);
    const int tid = threadIdx.x;
    const int wid = tid >> 5;
    const int lane = tid & 31;
    const int h  = blockIdx.y;
    const int bh = b * H_ + h;
    const size_t gb = (size_t)bh * T_ * D_;
    const int* idx = g_idx[b];
    const int cm1 = cnt - 1;

    const int lrow  = lane & 15;
    const int khalf = lane >> 4;

    // ---- prologue: gathered Q -> [32K,48K), K/V tile 0 -> buf0 [0,32K) ----
    #pragma unroll
    for (int i = 0; i < 8; i++) {
        const int arr = i >> 2;
        const int sub = tid + (i & 3) * 128;
        const int row = sub >> 3, ch = sub & 7;
        const int tq = idx[min(i0 + row, cm1)];
        const __nv_bfloat16* g = arr ? g_Qlo : g_Qhi;
        CP16(sb + 32768u + (uint32_t)arr * 8192u + SWO(row, ch),
             g + gb + (size_t)tq * D_ + ch * 8);
    }
    #pragma unroll
    for (int i = 0; i < 16; i++) {
        const int arr = i >> 2;
        const int sub = tid + (i & 3) * 128;
        const int row = sub >> 3, ch = sub & 7;
        const __nv_bfloat16* g = (arr == 0) ? g_Khi : (arr == 1) ? g_Klo
                               : (arr == 2) ? g_Vhi : g_Vlo;
        CP16(sb + (uint32_t)arr * 8192u + SWO(row, ch),
             g + gb + (size_t)row * D_ + ch * 8);
    }
    CP_COMMIT();

    float O[8][4];
    #pragma unroll
    for (int i = 0; i < 8; i++)
        #pragma unroll
        for (int c = 0; c < 4; c++) O[i][c] = 0.f;
    float m0 = -1e30f, m1 = -1e30f, l0 = 0.f, l1 = 0.f;
    uint32_t ahi[4][4], alo[4][4];

    const int rq = lane >> 2;
    const int cq = (lane & 3) * 2;
    const int lr0 = i0 + wid * 16 + rq;
    const int lr1 = lr0 + 8;
    const int grow0 = idx[min(lr0, cm1)];
    const int grow1 = idx[min(lr1, cm1)];
    const bool v0 = (lr0 <= cm1);
    const bool v1 = (lr1 <= cm1);

    const int tjmax = idx[min(i0 + 63, cm1)] >> 6;

    for (int tj = 0; tj <= tjmax; tj++) {
        CP_WAIT0();
        __syncthreads();

        if (tj == 0) {
            #pragma unroll
            for (int kc = 0; kc < 4; kc++) {
                const int r = wid * 16 + lrow;
                const uint32_t off = SWO(r, kc * 2 + khalf);
                LDSM_X4(ahi[kc][0], ahi[kc][1], ahi[kc][2], ahi[kc][3],
                        sb + 32768u + off);
                LDSM_X4(alo[kc][0], alo[kc][1], alo[kc][2], alo[kc][3],
                        sb + 40960u + off);
            }
            __syncthreads();
        }

        if (tj < tjmax) {
            const uint32_t dst = sb + (uint32_t)((tj + 1) & 1) * 32768u;
            const size_t src = gb + (size_t)(tj + 1) * 64 * D_;
            #pragma unroll
            for (int i = 0; i < 16; i++) {
                const int arr = i >> 2;
                const int sub = tid + (i & 3) * 128;
                const int row = sub >> 3, ch = sub & 7;
                const __nv_bfloat16* g = (arr == 0) ? g_Khi : (arr == 1) ? g_Klo
                                       : (arr == 2) ? g_Vhi : g_Vlo;
                CP16(dst + (uint32_t)arr * 8192u + SWO(row, ch),
                     g + src + (size_t)row * D_ + ch * 8);
            }
            CP_COMMIT();
        }

        const uint32_t kbuf = sb + (uint32_t)(tj & 1) * 32768u;

        float acc[8][4];
        #pragma unroll
        for (int i = 0; i < 8; i++)
            #pragma unroll
            for (int c = 0; c < 4; c++) acc[i][c] = 0.f;

        #pragma unroll
        for (int kc = 0; kc < 4; kc++) {
            uint32_t bh4[4][4], bl4[4][4];
            #pragma unroll
            for (int g = 0; g < 4; g++) {
                const int r = g * 16 + lrow;
                const uint32_t off = SWO(r, kc * 2 + khalf);
                LDSM_X4(bh4[g][0], bh4[g][1], bh4[g][2], bh4[g][3], kbuf + off);
                LDSM_X4(bl4[g][0], bl4[g][1], bl4[g][2], bl4[g][3],
                        kbuf + 8192u + off);
            }
            #pragma unroll
            for (int ni = 0; ni < 8; ni++) {
                const int g = ni >> 1, o = ni & 1;
                MMA_BF16(acc[ni], ahi[kc], bh4[g][o], bh4[g][2 + o]);
                MMA_BF16(acc[ni], ahi[kc], bl4[g][o], bl4[g][2 + o]);
                MMA_BF16(acc[ni], alo[kc], bh4[g][o], bh4[g][2 + o]);
            }
        }

        const int j0 = tj * 64;
        #pragma unroll
        for (int ni = 0; ni < 8; ni++) {
            #pragma unroll
            for (int c = 0; c < 4; c++) {
                const int col = j0 + ni * 8 + cq + (c & 1);
                const int grow = (c < 2) ? grow0 : grow1;
                float x = fmaxf(acc[ni][c], 1.0f + 1e-7f);
                float dd = __logf(x + sqrt_approx(fmaxf(x * x - 1.f, 0.f)));
                float s = -dd * dd * 0.125f;
                acc[ni][c] = (col > grow) ? -1e30f : s;
            }
        }

        {
            float mx = -1e30f;
            #pragma unroll
            for (int ni = 0; ni < 8; ni++)
                mx = fmaxf(mx, fmaxf(acc[ni][0], acc[ni][1]));
            mx = fmaxf(mx, __shfl_xor_sync(0xffffffffu, mx, 1));
            mx = fmaxf(mx, __shfl_xor_sync(0xffffffffu, mx, 2));
            float mnew = fmaxf(m0, mx);
            float es = __expf(m0 - mnew);
            l0 *= es;
            #pragma unroll
            for (int ni = 0; ni < 8; ni++) { O[ni][0] *= es; O[ni][1] *= es; }
            float rs = 0.f;
            #pragma unroll
            for (int ni = 0; ni < 8; ni++) {
                float p0 = __expf(acc[ni][0] - mnew);
                float p1 = __expf(acc[ni][1] - mnew);
                acc[ni][0] = p0; acc[ni][1] = p1; rs += p0 + p1;
            }
            rs += __shfl_xor_sync(0xffffffffu, rs, 1);
            rs += __shfl_xor_sync(0xffffffffu, rs, 2);
            l0 += rs; m0 = mnew;
        }
        {
            float mx = -1e30f;
            #pragma unroll
            for (int ni = 0; ni < 8; ni++)
                mx = fmaxf(mx, fmaxf(acc[ni][2], acc[ni][3]));
            mx = fmaxf(mx, __shfl_xor_sync(0xffffffffu, mx, 1));
            mx = fmaxf(mx, __shfl_xor_sync(0xffffffffu, mx, 2));
            float mnew = fmaxf(m1, mx);
            float es = __expf(m1 - mnew);
            l1 *= es;
            #pragma unroll
            for (int ni = 0; ni < 8; ni++) { O[ni][2] *= es; O[ni][3] *= es; }
            float rs = 0.f;
            #pragma unroll
            for (int ni = 0; ni < 8; ni++) {
                float p0 = __expf(acc[ni][2] - mnew);
                float p1 = __expf(acc[ni][3] - mnew);
                acc[ni][2] = p0; acc[ni][3] = p1; rs += p0 + p1;
            }
            rs += __shfl_xor_sync(0xffffffffu, rs, 1);
            rs += __shfl_xor_sync(0xffffffffu, rs, 2);
            l1 += rs; m1 = mnew;
        }

        const uint32_t vbuf = kbuf + 16384u;
        #pragma unroll
        for (int kc = 0; kc < 4; kc++) {
            uint32_t ph[4], pl[4];
            #pragma unroll
            for (int q = 0; q < 4; q++) {
                const int ni = 2 * kc + (q >> 1);
                const int c0 = (q & 1) * 2;
                float a = acc[ni][c0], bb = acc[ni][c0 + 1];
                uint32_t hp = pack_bf16(a, bb);
                __nv_bfloat162 hv = *(__nv_bfloat162*)&hp;
                const int idx2 = (q & 1) + (q >> 1) * 2;
                ph[idx2] = hp;
                pl[idx2] = pack_bf16(a - __low2float(hv), bb - __high2float(hv));
            }
            #pragma unroll
            for (int g = 0; g < 4; g++) {
                const int r = kc * 16 + ((lane >> 3) & 1) * 8 + (lane & 7);
                const uint32_t off = SWO(r, g * 2 + khalf);
                uint32_t vh[4], vl[4];
                LDSM_X4_T(vh[0], vh[1], vh[2], vh[3], vbuf + off);
                LDSM_X4_T(vl[0], vl[1], vl[2], vl[3], vbuf + 8192u + off);
                MMA_BF16(O[g * 2],     ph, vh[0], vh[1]);
                MMA_BF16(O[g * 2],     ph, vl[0], vl[1]);
                MMA_BF16(O[g * 2],     pl, vh[0], vh[1]);
                MMA_BF16(O[g * 2 + 1], ph, vh[2], vh[3]);
                MMA_BF16(O[g * 2 + 1], ph, vl[2], vl[3]);
                MMA_BF16(O[g * 2 + 1], pl, vh[2], vh[3]);
            }
        }
    }

    // ---- epilogue: write Yhi/Ylo bf16 (spiking rows only; spike==1) ----
    const float inv0 = 1.f / l0;
    const float inv1 = 1.f / l1;
    const size_t y0 = ((size_t)(b * T_ + grow0)) * C_ + h * D_;
    const size_t y1 = ((size_t)(b * T_ + grow1)) * C_ + h * D_;
    #pragma unroll
    for (int ni = 0; ni < 8; ni++) {
        const int d = ni * 8 + cq;
        if (v0) {
            float a0 = O[ni][0] * inv0, a1 = O[ni][1] * inv0;
            uint32_t h0 = pack_bf16(a0, a1);
            __nv_bfloat162 hv0 = *(__nv_bfloat162*)&h0;
            uint32_t l0p = pack_bf16(a0 - __low2float(hv0), a1 - __high2float(hv0));
            *(uint32_t*)(g_Yhi + y0 + d) = h0;
            *(uint32_t*)(g_Ylo + y0 + d) = l0p;
        }
        if (v1) {
            float b0 = O[ni][2] * inv1, b1 = O[ni][3] * inv1;
            uint32_t h1 = pack_bf16(b0, b1);
            __nv_bfloat162 hv1 = *(__nv_bfloat162*)&h1;
            uint32_t l1p = pack_bf16(b0 - __low2float(hv1), b1 - __high2float(hv1));
            *(uint32_t*)(g_Yhi + y1 + d) = h1;
            *(uint32_t*)(g_Ylo + y1 + d) = l1p;
        }
    }
}

// ---------------- launch -----------------------------------------------------
extern "C" void kernel_launch(void* const* d_in, const int* in_sizes, int n_in,
                              void* d_out, int out_size) {
    const float* x      = (const float*)d_in[0];
    const float* W_qkv  = (const float*)d_in[1];
    const float* b_qkv  = (const float*)d_in[2];
    const float* W_out  = (const float*)d_in[3];
    const float* b_out  = (const float*)d_in[4];
    const float* w_sur  = (const float*)d_in[5];
    const float* b_sur  = (const float*)d_in[6];
    const float* thresh = (const float*)d_in[7];
    float* out = (float*)d_out;

    __nv_bfloat16 *p_xhi, *p_xlo, *p_Wqt_hi, *p_Wqt_lo;
    __nv_bfloat16 *p_Yhi, *p_Ylo, *p_Wot_hi, *p_Wot_lo;
    cudaGetSymbolAddress((void**)&p_xhi, g_xhi);
    cudaGetSymbolAddress((void**)&p_xlo, g_xlo);
    cudaGetSymbolAddress((void**)&p_Wqt_hi, g_Wqt_hi);
    cudaGetSymbolAddress((void**)&p_Wqt_lo, g_Wqt_lo);
    cudaGetSymbolAddress((void**)&p_Yhi, g_Yhi);
    cudaGetSymbolAddress((void**)&p_Ylo, g_Ylo);
    cudaGetSymbolAddress((void**)&p_Wot_hi, g_Wot_hi);
    cudaGetSymbolAddress((void**)&p_Wot_lo, g_Wot_lo);

    cudaFuncSetAttribute(attn_kernel,
                         cudaFuncAttributeMaxDynamicSharedMemorySize, AT_SMEM);
    cudaFuncSetAttribute(gemm4_kernel<true, false>,
                         cudaFuncAttributeMaxDynamicSharedMemorySize, G4_SMEM);
    cudaFuncSetAttribute(gemm4_kernel<false, true>,
                         cudaFuncAttributeMaxDynamicSharedMemorySize, G4_SMEM);

    const int M = B_ * T_;   // 4096

    // 1. fused prep: x spike+split | W^T splits | out = bias (one launch)
    prep_all_kernel<<<5120, 256>>>(x, W_qkv, W_out, w_sur, b_sur, thresh,
                                   b_out, out,
                                   p_xhi, p_xlo, p_Wqt_hi, p_Wqt_lo,
                                   p_Wot_hi, p_Wot_lo);

    // 2. spike compaction (needed by the Q-gathered QKV GEMM)
    compact_kernel<<<1, 128>>>();

    // 3. QKV GEMM, Q third M-gathered over spiking rows; fused Lorentz epilogue
    gemm4_kernel<true, false><<<dim3(3 * C_ / 128, M / 128), 128, G4_SMEM>>>(
        p_xhi, p_xlo, p_Wqt_hi, p_Wqt_lo, b_qkv, nullptr, M, 3 * C_, C_);

    // 4. spike-compacted tensor-core flash attention
    attn_kernel<<<dim3(T_ / 64, H_, B_), 128, AT_SMEM>>>();

    // 5. out projection on spiking rows only (others = bias from prep)
    gemm4_kernel<false, true><<<dim3(C_ / 128, M / 128), 128, G4_SMEM>>>(
        p_Yhi, p_Ylo, p_Wot_hi, p_Wot_lo, b_out, out, M, C_, C_);
}